// round 11
// baseline (speedup 1.0000x reference)
#include <cuda_runtime.h>
#include <cuda_bf16.h>
#include <cstdint>

#define MAXB 131072

// ---------------- persistent device scratch (no runtime allocation) ----------------
__device__ __align__(16) float          g_x0[(size_t)MAXB * 2 * 64];
__device__ __align__(16) unsigned char  g_wbuf[24 * 17408 + 3 * 33792];
#define WOFF_H1  (24 * 17408)
#define WOFF_UPW (WOFF_H1 + 33792)
#define WOFF_IPW (WOFF_UPW + 33792)

// ---------------- common helpers ----------------
static __device__ __forceinline__ uint32_t smem_u32(const void* p) {
    uint32_t a;
    asm("{ .reg .u64 t; cvta.to.shared.u64 t, %1; cvt.u32.u64 %0, t; }" : "=r"(a) : "l"(p));
    return a;
}
static __device__ __forceinline__ void ldmA(uint32_t a[4], uint32_t addr) {
    asm volatile("ldmatrix.sync.aligned.m8n8.x4.shared.b16 {%0,%1,%2,%3}, [%4];"
                 : "=r"(a[0]), "=r"(a[1]), "=r"(a[2]), "=r"(a[3]) : "r"(addr));
}
static __device__ __forceinline__ void ldmB4(uint32_t b[4], uint32_t addr) {
    asm volatile("ldmatrix.sync.aligned.m8n8.x4.shared.b16 {%0,%1,%2,%3}, [%4];"
                 : "=r"(b[0]), "=r"(b[1]), "=r"(b[2]), "=r"(b[3]) : "r"(addr));
}
static __device__ __forceinline__ void mma16816(float d[4], const uint32_t a[4], const uint32_t b[2]) {
    asm volatile("mma.sync.aligned.m16n8k16.row.col.f32.bf16.bf16.f32 "
                 "{%0,%1,%2,%3}, {%4,%5,%6,%7}, {%8,%9}, {%0,%1,%2,%3};"
                 : "+f"(d[0]), "+f"(d[1]), "+f"(d[2]), "+f"(d[3])
                 : "r"(a[0]), "r"(a[1]), "r"(a[2]), "r"(a[3]), "r"(b[0]), "r"(b[1]));
}

// register-A 3-term gemm with x4 B loads. B tile [64 rows][BSTR bytes], lo block at +KLO.
template<int NKC, int BSTR, int KLO>
static __device__ __forceinline__ void gemm3r4(float (*acc)[4],
        const uint32_t (*fh)[4], const uint32_t (*fl)[4], uint32_t bBase) {
    const int lane = threadIdx.x & 31;
    uint32_t bAddr = bBase + (lane & 7) * BSTR + (((lane >> 3) & 1) << 4)
                   + ((lane >> 4) & 1) * 8 * BSTR;
    #pragma unroll
    for (int kc = 0; kc < NKC; ++kc) {
        uint32_t bh[4][4];
        #pragma unroll
        for (int jp = 0; jp < 4; ++jp)
            ldmB4(bh[jp], bAddr + jp * 16 * BSTR + kc * 32);
        #pragma unroll
        for (int jp = 0; jp < 4; ++jp) {
            mma16816(acc[2 * jp],     fh[kc], &bh[jp][0]);
            mma16816(acc[2 * jp + 1], fh[kc], &bh[jp][2]);
        }
        #pragma unroll
        for (int jp = 0; jp < 4; ++jp) {
            mma16816(acc[2 * jp],     fl[kc], &bh[jp][0]);
            mma16816(acc[2 * jp + 1], fl[kc], &bh[jp][2]);
        }
        #pragma unroll
        for (int jp = 0; jp < 4; ++jp) {
            uint32_t bl[4];
            ldmB4(bl, bAddr + jp * 16 * BSTR + kc * 32 + KLO);
            mma16816(acc[2 * jp],     fh[kc], &bl[0]);
            mma16816(acc[2 * jp + 1], fh[kc], &bl[2]);
        }
    }
}

// tile-A 3-term gemm with x4 B loads (embed + head). A tile lo block at +NKC*32 bytes.
template<int NKC, int BSTR, int KLO>
static __device__ void gemm3t(float (*acc)[4], uint32_t aBase, int aStrB, uint32_t bBase) {
    const int lane = threadIdx.x & 31;
    const int KB = NKC * 32;
    uint32_t aAddr = aBase + (lane & 15) * aStrB + ((lane >> 4) << 4);
    uint32_t bAddr = bBase + (lane & 7) * BSTR + (((lane >> 3) & 1) << 4)
                   + ((lane >> 4) & 1) * 8 * BSTR;
    #pragma unroll
    for (int kc = 0; kc < NKC; ++kc) {
        uint32_t ah[4], al[4];
        ldmA(ah, aAddr + kc * 32);
        ldmA(al, aAddr + kc * 32 + KB);
        uint32_t bh[4][4];
        #pragma unroll
        for (int jp = 0; jp < 4; ++jp)
            ldmB4(bh[jp], bAddr + jp * 16 * BSTR + kc * 32);
        #pragma unroll
        for (int jp = 0; jp < 4; ++jp) {
            mma16816(acc[2 * jp],     ah, &bh[jp][0]);
            mma16816(acc[2 * jp + 1], ah, &bh[jp][2]);
        }
        #pragma unroll
        for (int jp = 0; jp < 4; ++jp) {
            mma16816(acc[2 * jp],     al, &bh[jp][0]);
            mma16816(acc[2 * jp + 1], al, &bh[jp][2]);
        }
        #pragma unroll
        for (int jp = 0; jp < 4; ++jp) {
            uint32_t bl[4];
            ldmB4(bl, bAddr + jp * 16 * BSTR + kc * 32 + KLO);
            mma16816(acc[2 * jp],     ah, &bl[0]);
            mma16816(acc[2 * jp + 1], ah, &bl[2]);
        }
    }
}

// convert fp32 pair -> packed bf16 hi + packed bf16 lo
static __device__ __forceinline__ void cvt_pair(float v0, float v1, uint32_t& h, uint32_t& l) {
    __nv_bfloat162 hb = __floats2bfloat162_rn(v0, v1);
    h = *reinterpret_cast<uint32_t*>(&hb);
    float r0 = v0 - __bfloat162float(hb.x);
    float r1 = v1 - __bfloat162float(hb.y);
    __nv_bfloat162 lb = __floats2bfloat162_rn(r0, r1);
    l = *reinterpret_cast<uint32_t*>(&lb);
}

// build m16n8k16 A fragments (hi+lo) from register values v[rowhalf][j][2]
static __device__ __forceinline__ void build_fr(const float v[2][8][2],
                                                uint32_t fh[4][4], uint32_t fl[4][4]) {
    #pragma unroll
    for (int kc = 0; kc < 4; ++kc)
        #pragma unroll
        for (int m = 0; m < 4; ++m) {
            int h = m & 1, j = 2 * kc + (m >> 1);
            cvt_pair(v[h][j][0], v[h][j][1], fh[kc][m], fl[kc][m]);
        }
}

// hi/lo bf16 pair store into padded tile [r][strideElems], hi cols 0:K, lo K:2K
static __device__ __forceinline__ void st_hilo(char* sm, uint32_t off, int strideElems,
                                               int r, int c, int K, float f0, float f1) {
    uint32_t hh, ll;
    cvt_pair(f0, f1, hh, ll);
    __nv_bfloat16* row = (__nv_bfloat16*)(sm + off) + (size_t)r * strideElems;
    *reinterpret_cast<uint32_t*>(row + c)     = hh;
    *reinterpret_cast<uint32_t*>(row + K + c) = ll;
}

// ---------------- cp.async + mbarrier ----------------
#define CP16(dst, src) asm volatile("cp.async.cg.shared.global [%0], [%1], 16;" \
                                    :: "r"(dst), "l"(src) : "memory")
#define CP_COMMIT() asm volatile("cp.async.commit_group;" ::: "memory")
#define CP_WAIT0()  asm volatile("cp.async.wait_group 0;" ::: "memory")

#define MBARRIER_INIT(mbar, count) \
    asm volatile("mbarrier.init.shared.b64 [%0], %1;" :: "r"((uint32_t)(mbar)), "r"((uint32_t)(count)) : "memory")
#define MBARRIER_ARRIVE(mbar) \
    asm volatile("mbarrier.arrive.shared.b64 _, [%0];" :: "r"((uint32_t)(mbar)) : "memory")
// .noinc is load-bearing: default form increments expected count (net-zero) -> deadlock (R10).
#define CP_MBAR_ARRIVE(mbar) \
    asm volatile("cp.async.mbarrier.arrive.noinc.shared.b64 [%0];" :: "r"((uint32_t)(mbar)) : "memory")
#define MBARRIER_WAIT_PARITY(mbar, parity) do { \
    uint32_t _mbar = (uint32_t)(mbar); uint32_t _par = (uint32_t)(parity); uint32_t _done; \
    asm volatile("{\n\t.reg .pred p;\n\t" \
        "mbarrier.try_wait.parity.acquire.cta.shared::cta.b64 p, [%1], %2;\n\t" \
        "selp.b32 %0, 1, 0, p;\n\t}" : "=r"(_done) : "r"(_mbar), "r"(_par) : "memory"); \
    if (!_done) { \
        asm volatile("{\n\t.reg .pred P1;\n\t" \
            "WAIT_LOOP_%=:\n\t" \
            "mbarrier.try_wait.parity.acquire.cta.shared::cta.b64 P1, [%0], %1, 0x989680;\n\t" \
            "@P1 bra.uni WAIT_DONE_%=;\n\tbra.uni WAIT_LOOP_%=;\n\tWAIT_DONE_%=:\n\t}" \
            :: "r"(_mbar), "r"(_par) : "memory"); \
    } } while(0)

// =====================================================================================
// Kernel 1: convert all weights to hi/lo tile images (27 blocks)
// =====================================================================================
__global__ void conv_w_kernel(const float* __restrict__ in_w, const float* __restrict__ out_w,
                              const float* __restrict__ ff1_w, const float* __restrict__ ff2_w,
                              const float* __restrict__ h1_w, const float* __restrict__ upw,
                              const float* __restrict__ ipw)
{
    int b = blockIdx.x;
    if (b < 24) {
        int l = b / 12, c = b % 12;
        const float* src; int rs;
        if (c < 3)       { src = in_w  + ((size_t)l * 192 + 64 * c) * 64; rs = 64; }
        else if (c == 3) { src = out_w + (size_t)l * 4096;                rs = 64; }
        else {
            int cc = (c - 4) >> 1;
            if (((c - 4) & 1) == 0) { src = ff1_w + ((size_t)l * 256 + 64 * cc) * 64; rs = 64;  }
            else                    { src = ff2_w + (size_t)l * 16384 + 64 * cc;      rs = 256; }
        }
        unsigned char* dst = g_wbuf + (size_t)b * 17408;
        for (int idx = threadIdx.x; idx < 64 * 32; idx += 256) {
            int n = idx >> 5, k2 = (idx & 31) << 1;
            float2 f = *reinterpret_cast<const float2*>(src + (size_t)n * rs + k2);
            uint32_t hh, ll;
            cvt_pair(f.x, f.y, hh, ll);
            *reinterpret_cast<uint32_t*>(dst + n * 272 + k2 * 2)       = hh;
            *reinterpret_cast<uint32_t*>(dst + n * 272 + 128 + k2 * 2) = ll;
        }
    } else {
        const float* src = (b == 24) ? h1_w : (b == 25 ? upw : ipw);
        unsigned char* dst = g_wbuf + WOFF_H1 + (size_t)(b - 24) * 33792;
        for (int idx = threadIdx.x; idx < 64 * 64; idx += 256) {
            int n = idx >> 6, k2 = (idx & 63) << 1;
            float2 f = *reinterpret_cast<const float2*>(src + (size_t)n * 128 + k2);
            uint32_t hh, ll;
            cvt_pair(f.x, f.y, hh, ll);
            *reinterpret_cast<uint32_t*>(dst + n * 528 + k2 * 2)       = hh;
            *reinterpret_cast<uint32_t*>(dst + n * 528 + 256 + k2 * 2) = ll;
        }
    }
}

// =====================================================================================
// Kernel 2: embedding (unchanged from R8/R9)
// =====================================================================================
#define EB_SMEM 67584u

static __device__ __forceinline__ void stage_cp256(uint32_t dst, const unsigned char* src,
                                                   int bytes, int tid) {
    for (int o = tid * 16; o < bytes; o += 256 * 16)
        CP16(dst + o, src + o);
}

__global__ void __launch_bounds__(256, 2)
embed_kernel(const int* __restrict__ user_idx, const int* __restrict__ item_idx,
             const float* __restrict__ user_features, const float* __restrict__ item_features,
             const float* __restrict__ user_table, const float* __restrict__ item_table,
             const float* __restrict__ upb, const float* __restrict__ ipb,
             const float* __restrict__ pe)
{
    extern __shared__ char sm[];
    const int tid = threadIdx.x, lane = tid & 31, w = tid >> 5;
    const int qr = lane >> 2, qc = lane & 3;
    const int s0 = blockIdx.x << 6;

    stage_cp256(smem_u32(sm), g_wbuf + WOFF_UPW, 67584, tid);
    CP_COMMIT();

    const int side = w >> 2;
    const int r0 = 16 * w + qr;
    const int sA = side ? r0 - 64 : r0;
    const int sB = sA + 8;
    const float* featp = side ? item_features : user_features;
    const float* fpA = featp + (size_t)(s0 + sA) * 128;
    const float* fpB = featp + (size_t)(s0 + sB) * 128;

    uint32_t fh[8][4], fl[8][4];
    #pragma unroll
    for (int kc = 0; kc < 8; ++kc)
        #pragma unroll
        for (int m = 0; m < 4; ++m) {
            const float* p = (m & 1) ? fpB : fpA;
            int col = 16 * kc + 8 * (m >> 1) + 2 * qc;
            float2 f = __ldg(reinterpret_cast<const float2*>(p + col));
            cvt_pair(f.x, f.y, fh[kc][m], fl[kc][m]);
        }

    int myIdxA = side ? __ldg(item_idx + s0 + sA) : __ldg(user_idx + s0 + sA);
    int myIdxB = side ? __ldg(item_idx + s0 + sB) : __ldg(user_idx + s0 + sB);

    CP_WAIT0();
    __syncthreads();

    float acc[8][4];
    #pragma unroll
    for (int j = 0; j < 8; ++j) { acc[j][0] = acc[j][1] = acc[j][2] = acc[j][3] = 0.f; }
    gemm3r4<8, 528, 256>(acc, fh, fl, smem_u32(sm) + (side ? 33792u : 0u));

    const float* bb  = side ? ipb : upb;
    const float* tbl = side ? item_table : user_table;
    const float* pep = pe + side * 64;
    size_t tA = (size_t)myIdxA * 64;
    size_t tB = (size_t)myIdxB * 64;
    float* dA = g_x0 + ((size_t)(s0 + sA) * 2 + side) * 64;
    float* dB = g_x0 + ((size_t)(s0 + sB) * 2 + side) * 64;
    #pragma unroll
    for (int j = 0; j < 8; ++j) {
        int c = 8 * j + 2 * qc;
        dA[c]     = acc[j][0] + __ldg(bb + c)     + __ldg(tbl + tA + c)     + __ldg(pep + c);
        dA[c + 1] = acc[j][1] + __ldg(bb + c + 1) + __ldg(tbl + tA + c + 1) + __ldg(pep + c + 1);
        dB[c]     = acc[j][2] + __ldg(bb + c)     + __ldg(tbl + tB + c)     + __ldg(pep + c);
        dB[c + 1] = acc[j][3] + __ldg(bb + c + 1) + __ldg(tbl + tB + c + 1) + __ldg(pep + c + 1);
    }
}

// =====================================================================================
// Kernel 3: main transformer. 288 threads = 8 compute warps + 1 producer warp.
// smem: XT head tile [64][528B] @0 | mbarriers @33792 | WB ring 3x52224 @33920
// mbarrier pipeline: full[s] (count 32, cp.async.noinc-arrived), empty[s] (count 8).
// NO block-wide barriers in the phase loop; compute warps drift -> tensor overlap.
// =====================================================================================
#define XT_OFF 0u
#define MB_OFF 33792u
#define WB_OFF 33920u
#define SLOT_SZ 52224u
#define MAIN_SMEM (33920u + 3u * SLOT_SZ)
#define NCOMP 256
#define NTHR 288

static __device__ __forceinline__ void phase_src(int p, int& off, int& bytes) {
    if (p == 12) { off = WOFF_H1; bytes = 33792; return; }
    int l = p / 6, k = p % 6;
    int ch = l * 12 + (k == 0 ? 0 : (k == 1 ? 3 : 4 + 2 * (k - 2)));
    off = ch * 17408;
    bytes = (k == 0 ? 52224 : (k == 1 ? 17408 : 34816));
}

// register-only LayerNorm over one 64-wide row spread across 4 qc lanes
static __device__ __forceinline__ void ln_reg(float v[8][2], const float* g, const float* b, int qc) {
    float s = 0.f;
    #pragma unroll
    for (int j = 0; j < 8; ++j) s += v[j][0] + v[j][1];
    s += __shfl_xor_sync(0xffffffffu, s, 1);
    s += __shfl_xor_sync(0xffffffffu, s, 2);
    float m = s * (1.f / 64.f);
    float var = 0.f;
    #pragma unroll
    for (int j = 0; j < 8; ++j) {
        float d0 = v[j][0] - m, d1 = v[j][1] - m;
        var += d0 * d0 + d1 * d1;
    }
    var += __shfl_xor_sync(0xffffffffu, var, 1);
    var += __shfl_xor_sync(0xffffffffu, var, 2);
    float inv = rsqrtf(var * (1.f / 64.f) + 1e-5f);
    #pragma unroll
    for (int j = 0; j < 8; ++j) {
        int cc = 8 * j + 2 * qc;
        v[j][0] = (v[j][0] - m) * inv * __ldg(g + cc)     + __ldg(b + cc);
        v[j][1] = (v[j][1] - m) * inv * __ldg(g + cc + 1) + __ldg(b + cc + 1);
    }
}

__global__ void __launch_bounds__(NTHR, 1)
main_kernel(const float* __restrict__ in_b, const float* __restrict__ out_b,
            const float* __restrict__ ln1_g, const float* __restrict__ ln1_b,
            const float* __restrict__ ff1_b, const float* __restrict__ ff2_b,
            const float* __restrict__ ln2_g, const float* __restrict__ ln2_b,
            const float* __restrict__ h1_b, const float* __restrict__ h2_w,
            const float* __restrict__ h2_b, float* __restrict__ out)
{
    extern __shared__ char sm[];
    const int tid = threadIdx.x, lane = tid & 31, w = tid >> 5;
    const uint32_t xt_u = smem_u32(sm + XT_OFF);
    const uint32_t mb_u = smem_u32(sm + MB_OFF);
    const uint32_t wb_u = smem_u32(sm + WB_OFF);
    const uint32_t slot[3] = { wb_u, wb_u + SLOT_SZ, wb_u + 2u * SLOT_SZ };

    if (tid == 0) {
        #pragma unroll
        for (int s = 0; s < 3; ++s) {
            MBARRIER_INIT(mb_u + s * 16, 32);      // full[s]: 32 producer-lane cp arrives
            MBARRIER_INIT(mb_u + s * 16 + 8, 8);   // empty[s]: 8 compute-warp arrives
        }
    }
    __syncthreads();   // one-time: mbarriers visible to all 288 threads

    if (w == 8) {
        // ================= producer warp =================
        int phE[3] = { 0, 0, 0 };
        for (int p = 0; p <= 12; ++p) {
            int s = p % 3;
            if (p >= 3) {
                MBARRIER_WAIT_PARITY(mb_u + s * 16 + 8, phE[s]);
                phE[s] ^= 1;
            }
            int off, by; phase_src(p, off, by);
            const unsigned char* src = g_wbuf + off;
            for (int o = lane * 16; o < by; o += 32 * 16)
                CP16(slot[s] + o, src + o);
            CP_MBAR_ARRIVE(mb_u + s * 16);
        }
        return;
    }

    // ================= compute warps (0..7) =================
    const int qr = lane >> 2, qc = lane & 3;
    const int rA = 16 * w + qr;
    const int s0m = blockIdx.x << 6;

    float x_[2][8][2];
    {
        const float* x0p = g_x0 + (size_t)(blockIdx.x * 128) * 64;
        #pragma unroll
        for (int h = 0; h < 2; ++h) {
            const float* xp = x0p + (size_t)(rA + 8 * h) * 64;
            #pragma unroll
            for (int j = 0; j < 8; ++j) {
                float2 f = __ldg(reinterpret_cast<const float2*>(xp + 8 * j + 2 * qc));
                x_[h][j][0] = f.x; x_[h][j][1] = f.y;
            }
        }
    }

    uint32_t fxh[4][4], fxl[4][4];
    build_fr(x_, fxh, fxl);

    float accF[8][4];
    uint32_t fch[4][4], fcl[4][4];
    int phF[3] = { 0, 0, 0 };
    int pid = 0;

    for (int l = 0; l < 2; ++l) {
        for (int k = 0; k < 6; ++k) {
            const int s = pid % 3;
            MBARRIER_WAIT_PARITY(mb_u + s * 16, phF[s]);
            phF[s] ^= 1;
            const uint32_t bb = slot[s];
            const uint32_t emptyb = mb_u + s * 16 + 8;

            if (k == 0) {
                // ======== qkv + attention (2 live accumulators) ========
                float q_[8][4];
                #pragma unroll
                for (int j = 0; j < 8; ++j) { q_[j][0] = q_[j][1] = q_[j][2] = q_[j][3] = 0.f; }
                gemm3r4<4, 272, 128>(q_, fxh, fxl, bb);
                const float* bq = in_b + l * 192;
                #pragma unroll
                for (int j = 0; j < 8; ++j) {
                    int c = 8 * j + 2 * qc;
                    float b0 = __ldg(bq + c), b1 = __ldg(bq + c + 1);
                    q_[j][0] += b0; q_[j][1] += b1; q_[j][2] += b0; q_[j][3] += b1;
                }

                float t_[8][4];
                #pragma unroll
                for (int j = 0; j < 8; ++j) { t_[j][0] = t_[j][1] = t_[j][2] = t_[j][3] = 0.f; }
                gemm3r4<4, 272, 128>(t_, fxh, fxl, bb + 17408u);
                const float* bk = in_b + l * 192 + 64;
                #pragma unroll
                for (int j = 0; j < 8; ++j) {
                    int c = 8 * j + 2 * qc;
                    float b0 = __ldg(bk + c), b1 = __ldg(bk + c + 1);
                    t_[j][0] += b0; t_[j][1] += b1; t_[j][2] += b0; t_[j][3] += b1;
                }
                float wS[2][4], wO[2][4];
                {
                    float sS[2][4], sO[2][4];
                    #pragma unroll
                    for (int h = 0; h < 4; ++h) {
                        int j0 = 2 * h, j1 = 2 * h + 1;
                        sS[0][h] = q_[j0][0] * t_[j0][0] + q_[j0][1] * t_[j0][1]
                                 + q_[j1][0] * t_[j1][0] + q_[j1][1] * t_[j1][1];
                        sS[1][h] = q_[j0][2] * t_[j0][2] + q_[j0][3] * t_[j0][3]
                                 + q_[j1][2] * t_[j1][2] + q_[j1][3] * t_[j1][3];
                        float k00 = __shfl_xor_sync(0xffffffffu, t_[j0][0], 4);
                        float k01 = __shfl_xor_sync(0xffffffffu, t_[j0][1], 4);
                        float k10 = __shfl_xor_sync(0xffffffffu, t_[j1][0], 4);
                        float k11 = __shfl_xor_sync(0xffffffffu, t_[j1][1], 4);
                        float k02 = __shfl_xor_sync(0xffffffffu, t_[j0][2], 4);
                        float k03 = __shfl_xor_sync(0xffffffffu, t_[j0][3], 4);
                        float k12 = __shfl_xor_sync(0xffffffffu, t_[j1][2], 4);
                        float k13 = __shfl_xor_sync(0xffffffffu, t_[j1][3], 4);
                        sO[0][h] = q_[j0][0] * k00 + q_[j0][1] * k01 + q_[j1][0] * k10 + q_[j1][1] * k11;
                        sO[1][h] = q_[j0][2] * k02 + q_[j0][3] * k03 + q_[j1][2] * k12 + q_[j1][3] * k13;
                    }
                    #pragma unroll
                    for (int r = 0; r < 2; ++r)
                        #pragma unroll
                        for (int h = 0; h < 4; ++h) {
                            sS[r][h] += __shfl_xor_sync(0xffffffffu, sS[r][h], 1);
                            sS[r][h] += __shfl_xor_sync(0xffffffffu, sS[r][h], 2);
                            sO[r][h] += __shfl_xor_sync(0xffffffffu, sO[r][h], 1);
                            sO[r][h] += __shfl_xor_sync(0xffffffffu, sO[r][h], 2);
                            float a = sS[r][h] * 0.25f, o = sO[r][h] * 0.25f;
                            float m = fmaxf(a, o);
                            float ea = __expf(a - m), eo = __expf(o - m);
                            float inv = __fdividef(1.f, ea + eo);
                            wS[r][h] = ea * inv; wO[r][h] = eo * inv;
                        }
                }
                // v (reuse t_)
                #pragma unroll
                for (int j = 0; j < 8; ++j) { t_[j][0] = t_[j][1] = t_[j][2] = t_[j][3] = 0.f; }
                gemm3r4<4, 272, 128>(t_, fxh, fxl, bb + 34816u);
                if (lane == 0) MBARRIER_ARRIVE(emptyb);   // slot reads done
                const float* bv = in_b + l * 192 + 128;
                #pragma unroll
                for (int j = 0; j < 8; ++j) {
                    int c = 8 * j + 2 * qc;
                    float b0 = __ldg(bv + c), b1 = __ldg(bv + c + 1);
                    t_[j][0] += b0; t_[j][1] += b1; t_[j][2] += b0; t_[j][3] += b1;
                }
                #pragma unroll
                for (int j = 0; j < 8; ++j) {
                    int h = j >> 1;
                    float p0 = __shfl_xor_sync(0xffffffffu, t_[j][0], 4);
                    float p1 = __shfl_xor_sync(0xffffffffu, t_[j][1], 4);
                    float p2 = __shfl_xor_sync(0xffffffffu, t_[j][2], 4);
                    float p3 = __shfl_xor_sync(0xffffffffu, t_[j][3], 4);
                    float c00 = wS[0][h] * t_[j][0] + wO[0][h] * p0;
                    float c01 = wS[0][h] * t_[j][1] + wO[0][h] * p1;
                    float c10 = wS[1][h] * t_[j][2] + wO[1][h] * p2;
                    float c11 = wS[1][h] * t_[j][3] + wO[1][h] * p3;
                    int kc = j >> 1, jh = j & 1;
                    cvt_pair(c00, c01, fch[kc][(jh << 1) | 0], fcl[kc][(jh << 1) | 0]);
                    cvt_pair(c10, c11, fch[kc][(jh << 1) | 1], fcl[kc][(jh << 1) | 1]);
                }
            } else if (k == 1) {
                // ======== out-proj + residual + LN1 ========
                float acc[8][4];
                #pragma unroll
                for (int j = 0; j < 8; ++j) { acc[j][0] = acc[j][1] = acc[j][2] = acc[j][3] = 0.f; }
                gemm3r4<4, 272, 128>(acc, fch, fcl, bb);
                if (lane == 0) MBARRIER_ARRIVE(emptyb);
                const float* bo = out_b + l * 64;
                #pragma unroll
                for (int j = 0; j < 8; ++j) {
                    int c = 8 * j + 2 * qc;
                    float b0 = __ldg(bo + c), b1 = __ldg(bo + c + 1);
                    x_[0][j][0] += acc[j][0] + b0; x_[0][j][1] += acc[j][1] + b1;
                    x_[1][j][0] += acc[j][2] + b0; x_[1][j][1] += acc[j][3] + b1;
                }
                ln_reg(x_[0], ln1_g + l * 64, ln1_b + l * 64, qc);
                ln_reg(x_[1], ln1_g + l * 64, ln1_b + l * 64, qc);
                build_fr(x_, fxh, fxl);
            } else {
                // ======== ff pair ========
                int c4 = k - 2;
                float acc[8][4];
                #pragma unroll
                for (int j = 0; j < 8; ++j) { acc[j][0] = acc[j][1] = acc[j][2] = acc[j][3] = 0.f; }
                gemm3r4<4, 272, 128>(acc, fxh, fxl, bb);
                const float* b1p = ff1_b + l * 256 + 64 * c4;
                #pragma unroll
                for (int j = 0; j < 8; ++j) {
                    int c = 8 * j + 2 * qc;
                    float b0 = __ldg(b1p + c), b1 = __ldg(b1p + c + 1);
                    float h00 = fmaxf(acc[j][0] + b0, 0.f), h01 = fmaxf(acc[j][1] + b1, 0.f);
                    float h10 = fmaxf(acc[j][2] + b0, 0.f), h11 = fmaxf(acc[j][3] + b1, 0.f);
                    int kc = j >> 1, jh = j & 1;
                    cvt_pair(h00, h01, fch[kc][(jh << 1) | 0], fcl[kc][(jh << 1) | 0]);
                    cvt_pair(h10, h11, fch[kc][(jh << 1) | 1], fcl[kc][(jh << 1) | 1]);
                }
                if (c4 == 0) {
                    #pragma unroll
                    for (int j = 0; j < 8; ++j) { accF[j][0] = accF[j][1] = accF[j][2] = accF[j][3] = 0.f; }
                }
                gemm3r4<4, 272, 128>(accF, fch, fcl, bb + 17408u);
                if (lane == 0) MBARRIER_ARRIVE(emptyb);
                if (c4 == 3) {
                    const float* b2 = ff2_b + l * 64;
                    #pragma unroll
                    for (int j = 0; j < 8; ++j) {
                        int c = 8 * j + 2 * qc;
                        float b0 = __ldg(b2 + c), b1 = __ldg(b2 + c + 1);
                        x_[0][j][0] += accF[j][0] + b0; x_[0][j][1] += accF[j][1] + b1;
                        x_[1][j][0] += accF[j][2] + b0; x_[1][j][1] += accF[j][3] + b1;
                    }
                    ln_reg(x_[0], ln2_g + l * 64, ln2_b + l * 64, qc);
                    ln_reg(x_[1], ln2_g + l * 64, ln2_b + l * 64, qc);
                    if (l == 0) {
                        build_fr(x_, fxh, fxl);
                    } else {
                        #pragma unroll
                        for (int h = 0; h < 2; ++h) {
                            int row = (rA + 8 * h) >> 1;
                            int cb  = 64 * ((rA + 8 * h) & 1);
                            #pragma unroll
                            for (int j = 0; j < 8; ++j) {
                                int c = 8 * j + 2 * qc;
                                st_hilo(sm, XT_OFF, 264, row, cb + c, 128,
                                        x_[h][j][0], x_[h][j][1]);
                            }
                        }
                    }
                }
            }
            ++pid;
        }
    }

    // ================= head (phase 12, slot[0]) =================
    asm volatile("bar.sync 1, %0;" :: "n"(NCOMP) : "memory");   // XT complete across warps
    MBARRIER_WAIT_PARITY(mb_u + 0 * 16, phF[0]);

    if (w < 4) {
        float acc[8][4];
        #pragma unroll
        for (int j = 0; j < 8; ++j) { acc[j][0] = acc[j][1] = acc[j][2] = acc[j][3] = 0.f; }
        gemm3t<8, 528, 256>(acc, xt_u + (uint32_t)(16 * w) * 528u, 528, slot[0]);
        float pA = 0.f, pB = 0.f;
        #pragma unroll
        for (int j = 0; j < 8; ++j) {
            int c = 8 * j + 2 * qc;
            float b0 = __ldg(h1_b + c), b1 = __ldg(h1_b + c + 1);
            float w0 = __ldg(h2_w + c), w1 = __ldg(h2_w + c + 1);
            pA += fmaxf(acc[j][0] + b0, 0.f) * w0 + fmaxf(acc[j][1] + b1, 0.f) * w1;
            pB += fmaxf(acc[j][2] + b0, 0.f) * w0 + fmaxf(acc[j][3] + b1, 0.f) * w1;
        }
        pA += __shfl_xor_sync(0xffffffffu, pA, 1);
        pA += __shfl_xor_sync(0xffffffffu, pA, 2);
        pB += __shfl_xor_sync(0xffffffffu, pB, 1);
        pB += __shfl_xor_sync(0xffffffffu, pB, 2);
        if (qc == 0) {
            float hb = __ldg(h2_b);
            out[s0m + 16 * w + qr]     = pA + hb;
            out[s0m + 16 * w + qr + 8] = pB + hb;
        }
    }
}

// =====================================================================================
extern "C" void kernel_launch(void* const* d_in, const int* in_sizes, int n_in,
                              void* d_out, int out_size)
{
    const int*   user_idx      = (const int*)  d_in[0];
    const int*   item_idx      = (const int*)  d_in[1];
    const float* user_features = (const float*)d_in[2];
    const float* item_features = (const float*)d_in[3];
    const float* user_table    = (const float*)d_in[4];
    const float* item_table    = (const float*)d_in[5];
    const float* upw           = (const float*)d_in[6];
    const float* upb           = (const float*)d_in[7];
    const float* ipw           = (const float*)d_in[8];
    const float* ipb           = (const float*)d_in[9];
    const float* pe            = (const float*)d_in[10];
    const float* in_w          = (const float*)d_in[11];
    const float* in_b          = (const float*)d_in[12];
    const float* out_w         = (const float*)d_in[13];
    const float* out_b         = (const float*)d_in[14];
    const float* ln1_g         = (const float*)d_in[15];
    const float* ln1_b         = (const float*)d_in[16];
    const float* ff1_w         = (const float*)d_in[17];
    const float* ff1_b         = (const float*)d_in[18];
    const float* ff2_w         = (const float*)d_in[19];
    const float* ff2_b         = (const float*)d_in[20];
    const float* ln2_g         = (const float*)d_in[21];
    const float* ln2_b         = (const float*)d_in[22];
    const float* h1_w          = (const float*)d_in[23];
    const float* h1_b          = (const float*)d_in[24];
    const float* h2_w          = (const float*)d_in[25];
    const float* h2_b          = (const float*)d_in[26];
    float* out = (float*)d_out;

    const int B = in_sizes[0];

    static bool attr_set = false;
    if (!attr_set) {
        cudaFuncSetAttribute(embed_kernel, cudaFuncAttributeMaxDynamicSharedMemorySize, EB_SMEM);
        cudaFuncSetAttribute(main_kernel,  cudaFuncAttributeMaxDynamicSharedMemorySize, MAIN_SMEM);
        attr_set = true;
    }

    conv_w_kernel<<<27, 256>>>(in_w, out_w, ff1_w, ff2_w, h1_w, upw, ipw);
    embed_kernel<<<B / 64, 256, EB_SMEM>>>(user_idx, item_idx, user_features, item_features,
                                           user_table, item_table, upb, ipb, pe);
    main_kernel<<<B / 64, NTHR, MAIN_SMEM>>>(in_b, out_b, ln1_g, ln1_b, ff1_b, ff2_b,
                                             ln2_g, ln2_b, h1_b, h2_w, h2_b, out);
}

// round 12
// speedup vs baseline: 1.0791x; 1.0791x over previous
#include <cuda_runtime.h>
#include <cuda_bf16.h>
#include <cstdint>

// ---------------- persistent device scratch (no runtime allocation) ----------------
// 24 x 17408 K-chunk images | h1 image 33792 | embed B image [upw|ipw] 66560
__device__ __align__(16) unsigned char  g_wbuf[24 * 17408 + 33792 + 66560];
#define WOFF_H1  (24 * 17408)
#define WOFF_EMB (WOFF_H1 + 33792)

// ---------------- common helpers ----------------
static __device__ __forceinline__ uint32_t smem_u32(const void* p) {
    uint32_t a;
    asm("{ .reg .u64 t; cvta.to.shared.u64 t, %1; cvt.u32.u64 %0, t; }" : "=r"(a) : "l"(p));
    return a;
}
static __device__ __forceinline__ void ldmA(uint32_t a[4], uint32_t addr) {
    asm volatile("ldmatrix.sync.aligned.m8n8.x4.shared.b16 {%0,%1,%2,%3}, [%4];"
                 : "=r"(a[0]), "=r"(a[1]), "=r"(a[2]), "=r"(a[3]) : "r"(addr));
}
static __device__ __forceinline__ void ldmB4(uint32_t b[4], uint32_t addr) {
    asm volatile("ldmatrix.sync.aligned.m8n8.x4.shared.b16 {%0,%1,%2,%3}, [%4];"
                 : "=r"(b[0]), "=r"(b[1]), "=r"(b[2]), "=r"(b[3]) : "r"(addr));
}
static __device__ __forceinline__ void mma16816(float d[4], const uint32_t a[4], const uint32_t b[2]) {
    asm volatile("mma.sync.aligned.m16n8k16.row.col.f32.bf16.bf16.f32 "
                 "{%0,%1,%2,%3}, {%4,%5,%6,%7}, {%8,%9}, {%0,%1,%2,%3};"
                 : "+f"(d[0]), "+f"(d[1]), "+f"(d[2]), "+f"(d[3])
                 : "r"(a[0]), "r"(a[1]), "r"(a[2]), "r"(a[3]), "r"(b[0]), "r"(b[1]));
}

// register-A 3-term gemm with x4 B loads. B tile [64 rows][BSTR bytes], lo block at +KLO.
template<int NKC, int BSTR, int KLO>
static __device__ __forceinline__ void gemm3r4(float (*acc)[4],
        const uint32_t (*fh)[4], const uint32_t (*fl)[4], uint32_t bBase) {
    const int lane = threadIdx.x & 31;
    uint32_t bAddr = bBase + (lane & 7) * BSTR + (((lane >> 3) & 1) << 4)
                   + ((lane >> 4) & 1) * 8 * BSTR;
    #pragma unroll
    for (int kc = 0; kc < NKC; ++kc) {
        uint32_t bh[4][4];
        #pragma unroll
        for (int jp = 0; jp < 4; ++jp)
            ldmB4(bh[jp], bAddr + jp * 16 * BSTR + kc * 32);
        #pragma unroll
        for (int jp = 0; jp < 4; ++jp) {
            mma16816(acc[2 * jp],     fh[kc], &bh[jp][0]);
            mma16816(acc[2 * jp + 1], fh[kc], &bh[jp][2]);
        }
        #pragma unroll
        for (int jp = 0; jp < 4; ++jp) {
            mma16816(acc[2 * jp],     fl[kc], &bh[jp][0]);
            mma16816(acc[2 * jp + 1], fl[kc], &bh[jp][2]);
        }
        #pragma unroll
        for (int jp = 0; jp < 4; ++jp) {
            uint32_t bl[4];
            ldmB4(bl, bAddr + jp * 16 * BSTR + kc * 32 + KLO);
            mma16816(acc[2 * jp],     fh[kc], &bl[0]);
            mma16816(acc[2 * jp + 1], fh[kc], &bl[2]);
        }
    }
}

// tile-A 3-term gemm (head). A tile lo block at +NKC*32 bytes.
template<int NKC, int BSTR, int KLO>
static __device__ void gemm3t(float (*acc)[4], uint32_t aBase, int aStrB, uint32_t bBase) {
    const int lane = threadIdx.x & 31;
    const int KB = NKC * 32;
    uint32_t aAddr = aBase + (lane & 15) * aStrB + ((lane >> 4) << 4);
    uint32_t bAddr = bBase + (lane & 7) * BSTR + (((lane >> 3) & 1) << 4)
                   + ((lane >> 4) & 1) * 8 * BSTR;
    #pragma unroll
    for (int kc = 0; kc < NKC; ++kc) {
        uint32_t ah[4], al[4];
        ldmA(ah, aAddr + kc * 32);
        ldmA(al, aAddr + kc * 32 + KB);
        uint32_t bh[4][4];
        #pragma unroll
        for (int jp = 0; jp < 4; ++jp)
            ldmB4(bh[jp], bAddr + jp * 16 * BSTR + kc * 32);
        #pragma unroll
        for (int jp = 0; jp < 4; ++jp) {
            mma16816(acc[2 * jp],     ah, &bh[jp][0]);
            mma16816(acc[2 * jp + 1], ah, &bh[jp][2]);
        }
        #pragma unroll
        for (int jp = 0; jp < 4; ++jp) {
            mma16816(acc[2 * jp],     al, &bh[jp][0]);
            mma16816(acc[2 * jp + 1], al, &bh[jp][2]);
        }
        #pragma unroll
        for (int jp = 0; jp < 4; ++jp) {
            uint32_t bl[4];
            ldmB4(bl, bAddr + jp * 16 * BSTR + kc * 32 + KLO);
            mma16816(acc[2 * jp],     ah, &bl[0]);
            mma16816(acc[2 * jp + 1], ah, &bl[2]);
        }
    }
}

// convert fp32 pair -> packed bf16 hi + packed bf16 lo
static __device__ __forceinline__ void cvt_pair(float v0, float v1, uint32_t& h, uint32_t& l) {
    __nv_bfloat162 hb = __floats2bfloat162_rn(v0, v1);
    h = *reinterpret_cast<uint32_t*>(&hb);
    float r0 = v0 - __bfloat162float(hb.x);
    float r1 = v1 - __bfloat162float(hb.y);
    __nv_bfloat162 lb = __floats2bfloat162_rn(r0, r1);
    l = *reinterpret_cast<uint32_t*>(&lb);
}

// build m16n8k16 A fragments (hi+lo) from register values v[rowhalf][j][2]
static __device__ __forceinline__ void build_fr(const float v[2][8][2],
                                                uint32_t fh[4][4], uint32_t fl[4][4]) {
    #pragma unroll
    for (int kc = 0; kc < 4; ++kc)
        #pragma unroll
        for (int m = 0; m < 4; ++m) {
            int h = m & 1, j = 2 * kc + (m >> 1);
            cvt_pair(v[h][j][0], v[h][j][1], fh[kc][m], fl[kc][m]);
        }
}

// hi/lo bf16 pair store into padded tile [r][strideElems], hi cols 0:K, lo K:2K
static __device__ __forceinline__ void st_hilo(char* sm, uint32_t off, int strideElems,
                                               int r, int c, int K, float f0, float f1) {
    uint32_t hh, ll;
    cvt_pair(f0, f1, hh, ll);
    __nv_bfloat16* row = (__nv_bfloat16*)(sm + off) + (size_t)r * strideElems;
    *reinterpret_cast<uint32_t*>(row + c)     = hh;
    *reinterpret_cast<uint32_t*>(row + K + c) = ll;
}

// embed gemm: A rows 0-7 = user feats (K cols 0:128), rows 8-15 = item feats (cols 128:256).
// B image [64][1040B] (hi 512B | lo 512B | pad). 3-term. Fragments built on the fly.
static __device__ void gemm3_emb(float (*acc)[4], const float* __restrict__ fpU,
                                 const float* __restrict__ fpI, uint32_t bBase, int qc) {
    const int lane = threadIdx.x & 31;
    uint32_t bAddr = bBase + (lane & 7) * 1040 + (((lane >> 3) & 1) << 4)
                   + ((lane >> 4) & 1) * 8 * 1040;
    #pragma unroll
    for (int kc = 0; kc < 16; ++kc) {
        uint32_t ah[4] = {0u, 0u, 0u, 0u}, al[4] = {0u, 0u, 0u, 0u};
        if (kc < 8) {
            int col = 16 * kc + 2 * qc;
            float2 f0 = __ldg(reinterpret_cast<const float2*>(fpU + col));
            float2 f1 = __ldg(reinterpret_cast<const float2*>(fpU + col + 8));
            cvt_pair(f0.x, f0.y, ah[0], al[0]);
            cvt_pair(f1.x, f1.y, ah[2], al[2]);
        } else {
            int col = 16 * (kc - 8) + 2 * qc;
            float2 f0 = __ldg(reinterpret_cast<const float2*>(fpI + col));
            float2 f1 = __ldg(reinterpret_cast<const float2*>(fpI + col + 8));
            cvt_pair(f0.x, f0.y, ah[1], al[1]);
            cvt_pair(f1.x, f1.y, ah[3], al[3]);
        }
        uint32_t bh[4][4];
        #pragma unroll
        for (int jp = 0; jp < 4; ++jp)
            ldmB4(bh[jp], bAddr + jp * 16 * 1040 + kc * 32);
        #pragma unroll
        for (int jp = 0; jp < 4; ++jp) {
            mma16816(acc[2 * jp],     ah, &bh[jp][0]);
            mma16816(acc[2 * jp + 1], ah, &bh[jp][2]);
        }
        #pragma unroll
        for (int jp = 0; jp < 4; ++jp) {
            mma16816(acc[2 * jp],     al, &bh[jp][0]);
            mma16816(acc[2 * jp + 1], al, &bh[jp][2]);
        }
        #pragma unroll
        for (int jp = 0; jp < 4; ++jp) {
            uint32_t bl[4];
            ldmB4(bl, bAddr + jp * 16 * 1040 + kc * 32 + 512);
            mma16816(acc[2 * jp],     ah, &bl[0]);
            mma16816(acc[2 * jp + 1], ah, &bl[2]);
        }
    }
}

// ---------------- cp.async ----------------
#define CP16(dst, src) asm volatile("cp.async.cg.shared.global [%0], [%1], 16;" \
                                    :: "r"(dst), "l"(src) : "memory")
#define CP_COMMIT() asm volatile("cp.async.commit_group;" ::: "memory")
#define CP_WAIT0()  asm volatile("cp.async.wait_group 0;" ::: "memory")

static __device__ __forceinline__ void stage_cp256(uint32_t dst, const unsigned char* src,
                                                   int bytes, int tid) {
    for (int o = tid * 16; o < bytes; o += 256 * 16)
        CP16(dst + o, src + o);
}

// =====================================================================================
// Kernel 1: convert all weights to hi/lo tile images (26 blocks)
// =====================================================================================
__global__ void conv_w_kernel(const float* __restrict__ in_w, const float* __restrict__ out_w,
                              const float* __restrict__ ff1_w, const float* __restrict__ ff2_w,
                              const float* __restrict__ h1_w, const float* __restrict__ upw,
                              const float* __restrict__ ipw)
{
    int b = blockIdx.x;
    if (b < 24) {
        int l = b / 12, c = b % 12;
        const float* src; int rs;
        if (c < 3)       { src = in_w  + ((size_t)l * 192 + 64 * c) * 64; rs = 64; }
        else if (c == 3) { src = out_w + (size_t)l * 4096;                rs = 64; }
        else {
            int cc = (c - 4) >> 1;
            if (((c - 4) & 1) == 0) { src = ff1_w + ((size_t)l * 256 + 64 * cc) * 64; rs = 64;  }
            else                    { src = ff2_w + (size_t)l * 16384 + 64 * cc;      rs = 256; }
        }
        unsigned char* dst = g_wbuf + (size_t)b * 17408;
        for (int idx = threadIdx.x; idx < 64 * 32; idx += 256) {
            int n = idx >> 5, k2 = (idx & 31) << 1;
            float2 f = *reinterpret_cast<const float2*>(src + (size_t)n * rs + k2);
            uint32_t hh, ll;
            cvt_pair(f.x, f.y, hh, ll);
            *reinterpret_cast<uint32_t*>(dst + n * 272 + k2 * 2)       = hh;
            *reinterpret_cast<uint32_t*>(dst + n * 272 + 128 + k2 * 2) = ll;
        }
    } else if (b == 24) {
        unsigned char* dst = g_wbuf + WOFF_H1;
        for (int idx = threadIdx.x; idx < 64 * 64; idx += 256) {
            int n = idx >> 6, k2 = (idx & 63) << 1;
            float2 f = *reinterpret_cast<const float2*>(h1_w + (size_t)n * 128 + k2);
            uint32_t hh, ll;
            cvt_pair(f.x, f.y, hh, ll);
            *reinterpret_cast<uint32_t*>(dst + n * 528 + k2 * 2)       = hh;
            *reinterpret_cast<uint32_t*>(dst + n * 528 + 256 + k2 * 2) = ll;
        }
    } else {
        // embed B image: [64 rows][256 cols] = [upw | ipw] K-concat, stride 1040B
        unsigned char* dst = g_wbuf + WOFF_EMB;
        for (int idx = threadIdx.x; idx < 64 * 128; idx += 256) {
            int n = idx >> 7, k2 = (idx & 127) << 1;
            float2 f = (k2 < 128)
                     ? *reinterpret_cast<const float2*>(upw + (size_t)n * 128 + k2)
                     : *reinterpret_cast<const float2*>(ipw + (size_t)n * 128 + (k2 - 128));
            uint32_t hh, ll;
            cvt_pair(f.x, f.y, hh, ll);
            *reinterpret_cast<uint32_t*>(dst + n * 1040 + k2 * 2)       = hh;
            *reinterpret_cast<uint32_t*>(dst + n * 1040 + 512 + k2 * 2) = ll;
        }
    }
}

// =====================================================================================
// Kernel 2 (main): fully fused. 256 threads, 64 samples.
// warp w, thread qr owns SAMPLE sl=8w+qr: row qr = user token, row qr+8 = item token.
// smem: XT head tile [64][528B] @0 | WB ring 2x66560 @33792  total 166912
// phases: p0 embed, p1..p12 transformer, p13 head.
// =====================================================================================
#define XT_OFF 0u
#define WB_OFF 33792u
#define SLOT_SZ 66560u
#define MAIN_SMEM (33792u + 2u * SLOT_SZ)
#define MT 256

static __device__ __forceinline__ void phase_src(int p, int& off, int& bytes) {
    if (p == 0)  { off = WOFF_EMB; bytes = 66560; return; }
    if (p == 13) { off = WOFF_H1;  bytes = 33792; return; }
    int l = (p - 1) / 6, k = (p - 1) % 6;
    int ch = l * 12 + (k == 0 ? 0 : (k == 1 ? 3 : 4 + 2 * (k - 2)));
    off = ch * 17408;
    bytes = (k == 0 ? 52224 : (k == 1 ? 17408 : 34816));
}

// register-only LayerNorm over one 64-wide row spread across 4 qc lanes
static __device__ __forceinline__ void ln_reg(float v[8][2], const float* g, const float* b, int qc) {
    float s = 0.f;
    #pragma unroll
    for (int j = 0; j < 8; ++j) s += v[j][0] + v[j][1];
    s += __shfl_xor_sync(0xffffffffu, s, 1);
    s += __shfl_xor_sync(0xffffffffu, s, 2);
    float m = s * (1.f / 64.f);
    float var = 0.f;
    #pragma unroll
    for (int j = 0; j < 8; ++j) {
        float d0 = v[j][0] - m, d1 = v[j][1] - m;
        var += d0 * d0 + d1 * d1;
    }
    var += __shfl_xor_sync(0xffffffffu, var, 1);
    var += __shfl_xor_sync(0xffffffffu, var, 2);
    float inv = rsqrtf(var * (1.f / 64.f) + 1e-5f);
    #pragma unroll
    for (int j = 0; j < 8; ++j) {
        int cc = 8 * j + 2 * qc;
        v[j][0] = (v[j][0] - m) * inv * __ldg(g + cc)     + __ldg(b + cc);
        v[j][1] = (v[j][1] - m) * inv * __ldg(g + cc + 1) + __ldg(b + cc + 1);
    }
}

__global__ void __launch_bounds__(MT, 1)
main_kernel(const int* __restrict__ user_idx, const int* __restrict__ item_idx,
            const float* __restrict__ user_features, const float* __restrict__ item_features,
            const float* __restrict__ user_table, const float* __restrict__ item_table,
            const float* __restrict__ upb, const float* __restrict__ ipb,
            const float* __restrict__ pe,
            const float* __restrict__ in_b, const float* __restrict__ out_b,
            const float* __restrict__ ln1_g, const float* __restrict__ ln1_b,
            const float* __restrict__ ff1_b, const float* __restrict__ ff2_b,
            const float* __restrict__ ln2_g, const float* __restrict__ ln2_b,
            const float* __restrict__ h1_b, const float* __restrict__ h2_w,
            const float* __restrict__ h2_b, float* __restrict__ out)
{
    extern __shared__ char sm[];
    const int tid = threadIdx.x, lane = tid & 31, w = tid >> 5;
    const int qr = lane >> 2, qc = lane & 3;
    const int sl = 8 * w + qr;                 // sample owned by this thread
    const int s0m = blockIdx.x << 6;
    const uint32_t xt_u = smem_u32(sm + XT_OFF);
    const uint32_t wb_u = smem_u32(sm + WB_OFF);
    const uint32_t slot[2] = { wb_u, wb_u + SLOT_SZ };

    // prefetch phase 0 (embed B image)
    stage_cp256(slot[0], g_wbuf + WOFF_EMB, 66560, tid);
    CP_COMMIT();

    float x_[2][8][2];                 // [0]=user token, [1]=item token
    uint32_t fxh[4][4], fxl[4][4];
    float accF[8][4];
    uint32_t fch[4][4], fcl[4][4];

    for (int p = 0; p <= 13; ++p) {
        CP_WAIT0();
        __syncthreads();
        if (p < 13) {
            int off, by; phase_src(p + 1, off, by);
            stage_cp256(slot[(p + 1) & 1], g_wbuf + off, by, tid);
            CP_COMMIT();
        }
        const uint32_t bb = slot[p & 1];

        if (p == 0) {
            // ======== embed: x = feat@[upw|ipw]^T + bias + table + pe ========
            float acc[8][4];
            #pragma unroll
            for (int j = 0; j < 8; ++j) { acc[j][0] = acc[j][1] = acc[j][2] = acc[j][3] = 0.f; }
            gemm3_emb(acc, user_features + (size_t)(s0m + sl) * 128,
                           item_features + (size_t)(s0m + sl) * 128, bb, qc);
            int uidx = __ldg(user_idx + s0m + sl);
            int iidx = __ldg(item_idx + s0m + sl);
            const float* ut = user_table + (size_t)uidx * 64;
            const float* it = item_table + (size_t)iidx * 64;
            #pragma unroll
            for (int j = 0; j < 8; ++j) {
                int c = 8 * j + 2 * qc;
                x_[0][j][0] = acc[j][0] + __ldg(upb + c)     + __ldg(ut + c)     + __ldg(pe + c);
                x_[0][j][1] = acc[j][1] + __ldg(upb + c + 1) + __ldg(ut + c + 1) + __ldg(pe + c + 1);
                x_[1][j][0] = acc[j][2] + __ldg(ipb + c)     + __ldg(it + c)     + __ldg(pe + 64 + c);
                x_[1][j][1] = acc[j][3] + __ldg(ipb + c + 1) + __ldg(it + c + 1) + __ldg(pe + 64 + c + 1);
            }
            build_fr(x_, fxh, fxl);
        } else if (p == 13) {
            // ======== head ========
            if (w < 4) {
                float acc[8][4];
                #pragma unroll
                for (int j = 0; j < 8; ++j) { acc[j][0] = acc[j][1] = acc[j][2] = acc[j][3] = 0.f; }
                gemm3t<8, 528, 256>(acc, xt_u + (uint32_t)(16 * w) * 528u, 528, bb);
                float pA = 0.f, pB = 0.f;
                #pragma unroll
                for (int j = 0; j < 8; ++j) {
                    int c = 8 * j + 2 * qc;
                    float b0 = __ldg(h1_b + c), b1 = __ldg(h1_b + c + 1);
                    float w0 = __ldg(h2_w + c), w1 = __ldg(h2_w + c + 1);
                    pA += fmaxf(acc[j][0] + b0, 0.f) * w0 + fmaxf(acc[j][1] + b1, 0.f) * w1;
                    pB += fmaxf(acc[j][2] + b0, 0.f) * w0 + fmaxf(acc[j][3] + b1, 0.f) * w1;
                }
                pA += __shfl_xor_sync(0xffffffffu, pA, 1);
                pA += __shfl_xor_sync(0xffffffffu, pA, 2);
                pB += __shfl_xor_sync(0xffffffffu, pB, 1);
                pB += __shfl_xor_sync(0xffffffffu, pB, 2);
                if (qc == 0) {
                    float hb = __ldg(h2_b);
                    out[s0m + 16 * w + qr]     = pA + hb;
                    out[s0m + 16 * w + qr + 8] = pB + hb;
                }
            }
        } else {
            const int l = (p - 1) / 6, k = (p - 1) % 6;
            if (k == 0) {
                // ======== qkv + attention (partner token in-thread, no shfl exchange) ====
                float q_[8][4];
                #pragma unroll
                for (int j = 0; j < 8; ++j) { q_[j][0] = q_[j][1] = q_[j][2] = q_[j][3] = 0.f; }
                gemm3r4<4, 272, 128>(q_, fxh, fxl, bb);
                const float* bq = in_b + l * 192;
                #pragma unroll
                for (int j = 0; j < 8; ++j) {
                    int c = 8 * j + 2 * qc;
                    float b0 = __ldg(bq + c), b1 = __ldg(bq + c + 1);
                    q_[j][0] += b0; q_[j][1] += b1; q_[j][2] += b0; q_[j][3] += b1;
                }
                float t_[8][4];
                #pragma unroll
                for (int j = 0; j < 8; ++j) { t_[j][0] = t_[j][1] = t_[j][2] = t_[j][3] = 0.f; }
                gemm3r4<4, 272, 128>(t_, fxh, fxl, bb + 17408u);
                const float* bk = in_b + l * 192 + 64;
                #pragma unroll
                for (int j = 0; j < 8; ++j) {
                    int c = 8 * j + 2 * qc;
                    float b0 = __ldg(bk + c), b1 = __ldg(bk + c + 1);
                    t_[j][0] += b0; t_[j][1] += b1; t_[j][2] += b0; t_[j][3] += b1;
                }
                float wUU[4], wUI[4], wIU[4], wII[4];
                {
                    float sUU[4], sUI[4], sIU[4], sII[4];
                    #pragma unroll
                    for (int h = 0; h < 4; ++h) {
                        int j0 = 2 * h, j1 = 2 * h + 1;
                        sUU[h] = q_[j0][0] * t_[j0][0] + q_[j0][1] * t_[j0][1]
                               + q_[j1][0] * t_[j1][0] + q_[j1][1] * t_[j1][1];
                        sUI[h] = q_[j0][0] * t_[j0][2] + q_[j0][1] * t_[j0][3]
                               + q_[j1][0] * t_[j1][2] + q_[j1][1] * t_[j1][3];
                        sIU[h] = q_[j0][2] * t_[j0][0] + q_[j0][3] * t_[j0][1]
                               + q_[j1][2] * t_[j1][0] + q_[j1][3] * t_[j1][1];
                        sII[h] = q_[j0][2] * t_[j0][2] + q_[j0][3] * t_[j0][3]
                               + q_[j1][2] * t_[j1][2] + q_[j1][3] * t_[j1][3];
                    }
                    #pragma unroll
                    for (int h = 0; h < 4; ++h) {
                        sUU[h] += __shfl_xor_sync(0xffffffffu, sUU[h], 1);
                        sUU[h] += __shfl_xor_sync(0xffffffffu, sUU[h], 2);
                        sUI[h] += __shfl_xor_sync(0xffffffffu, sUI[h], 1);
                        sUI[h] += __shfl_xor_sync(0xffffffffu, sUI[h], 2);
                        sIU[h] += __shfl_xor_sync(0xffffffffu, sIU[h], 1);
                        sIU[h] += __shfl_xor_sync(0xffffffffu, sIU[h], 2);
                        sII[h] += __shfl_xor_sync(0xffffffffu, sII[h], 1);
                        sII[h] += __shfl_xor_sync(0xffffffffu, sII[h], 2);
                        float a = sUU[h] * 0.25f, o = sUI[h] * 0.25f;
                        float m = fmaxf(a, o);
                        float ea = __expf(a - m), eo = __expf(o - m);
                        float inv = __fdividef(1.f, ea + eo);
                        wUU[h] = ea * inv; wUI[h] = eo * inv;
                        a = sIU[h] * 0.25f; o = sII[h] * 0.25f;
                        m = fmaxf(a, o);
                        ea = __expf(a - m); eo = __expf(o - m);
                        inv = __fdividef(1.f, ea + eo);
                        wIU[h] = ea * inv; wII[h] = eo * inv;
                    }
                }
                // v (reuse t_)
                #pragma unroll
                for (int j = 0; j < 8; ++j) { t_[j][0] = t_[j][1] = t_[j][2] = t_[j][3] = 0.f; }
                gemm3r4<4, 272, 128>(t_, fxh, fxl, bb + 34816u);
                const float* bv = in_b + l * 192 + 128;
                #pragma unroll
                for (int j = 0; j < 8; ++j) {
                    int c = 8 * j + 2 * qc;
                    float b0 = __ldg(bv + c), b1 = __ldg(bv + c + 1);
                    t_[j][0] += b0; t_[j][1] += b1; t_[j][2] += b0; t_[j][3] += b1;
                }
                #pragma unroll
                for (int j = 0; j < 8; ++j) {
                    int h = j >> 1;
                    float c00 = wUU[h] * t_[j][0] + wUI[h] * t_[j][2];
                    float c01 = wUU[h] * t_[j][1] + wUI[h] * t_[j][3];
                    float c10 = wIU[h] * t_[j][0] + wII[h] * t_[j][2];
                    float c11 = wIU[h] * t_[j][1] + wII[h] * t_[j][3];
                    int kc = j >> 1, jh = j & 1;
                    cvt_pair(c00, c01, fch[kc][(jh << 1) | 0], fcl[kc][(jh << 1) | 0]);
                    cvt_pair(c10, c11, fch[kc][(jh << 1) | 1], fcl[kc][(jh << 1) | 1]);
                }
            } else if (k == 1) {
                // ======== out-proj + residual + LN1 ========
                float acc[8][4];
                #pragma unroll
                for (int j = 0; j < 8; ++j) { acc[j][0] = acc[j][1] = acc[j][2] = acc[j][3] = 0.f; }
                gemm3r4<4, 272, 128>(acc, fch, fcl, bb);
                const float* bo = out_b + l * 64;
                #pragma unroll
                for (int j = 0; j < 8; ++j) {
                    int c = 8 * j + 2 * qc;
                    float b0 = __ldg(bo + c), b1 = __ldg(bo + c + 1);
                    x_[0][j][0] += acc[j][0] + b0; x_[0][j][1] += acc[j][1] + b1;
                    x_[1][j][0] += acc[j][2] + b0; x_[1][j][1] += acc[j][3] + b1;
                }
                ln_reg(x_[0], ln1_g + l * 64, ln1_b + l * 64, qc);
                ln_reg(x_[1], ln1_g + l * 64, ln1_b + l * 64, qc);
                build_fr(x_, fxh, fxl);
            } else {
                // ======== ff pair ========
                int c4 = k - 2;
                float acc[8][4];
                #pragma unroll
                for (int j = 0; j < 8; ++j) { acc[j][0] = acc[j][1] = acc[j][2] = acc[j][3] = 0.f; }
                gemm3r4<4, 272, 128>(acc, fxh, fxl, bb);
                const float* b1p = ff1_b + l * 256 + 64 * c4;
                #pragma unroll
                for (int j = 0; j < 8; ++j) {
                    int c = 8 * j + 2 * qc;
                    float b0 = __ldg(b1p + c), b1 = __ldg(b1p + c + 1);
                    float h00 = fmaxf(acc[j][0] + b0, 0.f), h01 = fmaxf(acc[j][1] + b1, 0.f);
                    float h10 = fmaxf(acc[j][2] + b0, 0.f), h11 = fmaxf(acc[j][3] + b1, 0.f);
                    int kc = j >> 1, jh = j & 1;
                    cvt_pair(h00, h01, fch[kc][(jh << 1) | 0], fcl[kc][(jh << 1) | 0]);
                    cvt_pair(h10, h11, fch[kc][(jh << 1) | 1], fcl[kc][(jh << 1) | 1]);
                }
                if (c4 == 0) {
                    #pragma unroll
                    for (int j = 0; j < 8; ++j) { accF[j][0] = accF[j][1] = accF[j][2] = accF[j][3] = 0.f; }
                }
                gemm3r4<4, 272, 128>(accF, fch, fcl, bb + 17408u);
                if (c4 == 3) {
                    const float* b2 = ff2_b + l * 64;
                    #pragma unroll
                    for (int j = 0; j < 8; ++j) {
                        int c = 8 * j + 2 * qc;
                        float b0 = __ldg(b2 + c), b1 = __ldg(b2 + c + 1);
                        x_[0][j][0] += accF[j][0] + b0; x_[0][j][1] += accF[j][1] + b1;
                        x_[1][j][0] += accF[j][2] + b0; x_[1][j][1] += accF[j][3] + b1;
                    }
                    ln_reg(x_[0], ln2_g + l * 64, ln2_b + l * 64, qc);
                    ln_reg(x_[1], ln2_g + l * 64, ln2_b + l * 64, qc);
                    if (l == 0) {
                        build_fr(x_, fxh, fxl);
                    } else {
                        // head A tile: row = sample sl; user cols 0:64, item cols 64:128
                        #pragma unroll
                        for (int j = 0; j < 8; ++j) {
                            int c = 8 * j + 2 * qc;
                            st_hilo(sm, XT_OFF, 264, sl, c,      128, x_[0][j][0], x_[0][j][1]);
                            st_hilo(sm, XT_OFF, 264, sl, 64 + c, 128, x_[1][j][0], x_[1][j][1]);
                        }
                    }
                }
            }
        }
    }
}

// =====================================================================================
extern "C" void kernel_launch(void* const* d_in, const int* in_sizes, int n_in,
                              void* d_out, int out_size)
{
    const int*   user_idx      = (const int*)  d_in[0];
    const int*   item_idx      = (const int*)  d_in[1];
    const float* user_features = (const float*)d_in[2];
    const float* item_features = (const float*)d_in[3];
    const float* user_table    = (const float*)d_in[4];
    const float* item_table    = (const float*)d_in[5];
    const float* upw           = (const float*)d_in[6];
    const float* upb           = (const float*)d_in[7];
    const float* ipw           = (const float*)d_in[8];
    const float* ipb           = (const float*)d_in[9];
    const float* pe            = (const float*)d_in[10];
    const float* in_w          = (const float*)d_in[11];
    const float* in_b          = (const float*)d_in[12];
    const float* out_w         = (const float*)d_in[13];
    const float* out_b         = (const float*)d_in[14];
    const float* ln1_g         = (const float*)d_in[15];
    const float* ln1_b         = (const float*)d_in[16];
    const float* ff1_w         = (const float*)d_in[17];
    const float* ff1_b         = (const float*)d_in[18];
    const float* ff2_w         = (const float*)d_in[19];
    const float* ff2_b         = (const float*)d_in[20];
    const float* ln2_g         = (const float*)d_in[21];
    const float* ln2_b         = (const float*)d_in[22];
    const float* h1_w          = (const float*)d_in[23];
    const float* h1_b          = (const float*)d_in[24];
    const float* h2_w          = (const float*)d_in[25];
    const float* h2_b          = (const float*)d_in[26];
    float* out = (float*)d_out;

    const int B = in_sizes[0];

    static bool attr_set = false;
    if (!attr_set) {
        cudaFuncSetAttribute(main_kernel, cudaFuncAttributeMaxDynamicSharedMemorySize, MAIN_SMEM);
        attr_set = true;
    }

    conv_w_kernel<<<26, 256>>>(in_w, out_w, ff1_w, ff2_w, h1_w, upw, ipw);
    main_kernel<<<B / 64, MT, MAIN_SMEM>>>(user_idx, item_idx, user_features, item_features,
                                           user_table, item_table, upb, ipb, pe,
                                           in_b, out_b, ln1_g, ln1_b, ff1_b, ff2_b,
                                           ln2_g, ln2_b, h1_b, h2_w, h2_b, out);
}

// round 13
// speedup vs baseline: 1.3491x; 1.2501x over previous
#include <cuda_runtime.h>
#include <cuda_fp16.h>
#include <cstdint>

// ---------------- persistent device scratch (no runtime allocation) ----------------
// 24 x 9216 K-chunk hi-images | h1 image 17408 | embed B image [upw|ipw] 33792
#define CH_SZ    9216
#define WOFF_H1  (24 * CH_SZ)
#define WOFF_EMB (WOFF_H1 + 17408)
__device__ __align__(16) unsigned char  g_wbuf[WOFF_EMB + 33792];

// ---------------- common helpers ----------------
static __device__ __forceinline__ uint32_t smem_u32(const void* p) {
    uint32_t a;
    asm("{ .reg .u64 t; cvta.to.shared.u64 t, %1; cvt.u32.u64 %0, t; }" : "=r"(a) : "l"(p));
    return a;
}
static __device__ __forceinline__ void ldmA(uint32_t a[4], uint32_t addr) {
    asm volatile("ldmatrix.sync.aligned.m8n8.x4.shared.b16 {%0,%1,%2,%3}, [%4];"
                 : "=r"(a[0]), "=r"(a[1]), "=r"(a[2]), "=r"(a[3]) : "r"(addr));
}
static __device__ __forceinline__ void ldmB4(uint32_t b[4], uint32_t addr) {
    asm volatile("ldmatrix.sync.aligned.m8n8.x4.shared.b16 {%0,%1,%2,%3}, [%4];"
                 : "=r"(b[0]), "=r"(b[1]), "=r"(b[2]), "=r"(b[3]) : "r"(addr));
}
static __device__ __forceinline__ void mma16816(float d[4], const uint32_t a[4], const uint32_t b[2]) {
    asm volatile("mma.sync.aligned.m16n8k16.row.col.f32.f16.f16.f32 "
                 "{%0,%1,%2,%3}, {%4,%5,%6,%7}, {%8,%9}, {%0,%1,%2,%3};"
                 : "+f"(d[0]), "+f"(d[1]), "+f"(d[2]), "+f"(d[3])
                 : "r"(a[0]), "r"(a[1]), "r"(a[2]), "r"(a[3]), "r"(b[0]), "r"(b[1]));
}

// convert fp32 pair -> packed fp16 hi + packed fp16 lo (residual)
static __device__ __forceinline__ void cvt_pair(float v0, float v1, uint32_t& h, uint32_t& l) {
    __half2 hb = __floats2half2_rn(v0, v1);
    h = *reinterpret_cast<uint32_t*>(&hb);
    float r0 = v0 - __low2float(hb);
    float r1 = v1 - __high2float(hb);
    __half2 lb = __floats2half2_rn(r0, r1);
    l = *reinterpret_cast<uint32_t*>(&lb);
}
// hi-only convert (weights)
static __device__ __forceinline__ uint32_t cvt_hi(float v0, float v1) {
    __half2 hb = __floats2half2_rn(v0, v1);
    return *reinterpret_cast<uint32_t*>(&hb);
}

// 2-term gemm, register A (hi+lo), B hi-only tile [64 rows][BSTR bytes]
template<int NKC, int BSTR>
static __device__ __forceinline__ void gemm2r4(float (*acc)[4],
        const uint32_t (*fh)[4], const uint32_t (*fl)[4], uint32_t bBase) {
    const int lane = threadIdx.x & 31;
    uint32_t bAddr = bBase + (lane & 7) * BSTR + (((lane >> 3) & 1) << 4)
                   + ((lane >> 4) & 1) * 8 * BSTR;
    #pragma unroll
    for (int kc = 0; kc < NKC; ++kc) {
        uint32_t bh[4][4];
        #pragma unroll
        for (int jp = 0; jp < 4; ++jp)
            ldmB4(bh[jp], bAddr + jp * 16 * BSTR + kc * 32);
        #pragma unroll
        for (int jp = 0; jp < 4; ++jp) {
            mma16816(acc[2 * jp],     fh[kc], &bh[jp][0]);
            mma16816(acc[2 * jp + 1], fh[kc], &bh[jp][2]);
        }
        #pragma unroll
        for (int jp = 0; jp < 4; ++jp) {
            mma16816(acc[2 * jp],     fl[kc], &bh[jp][0]);
            mma16816(acc[2 * jp + 1], fl[kc], &bh[jp][2]);
        }
    }
}

// 2-term gemm, tile A (hi at kc*32, lo at +NKC*32), B hi-only (head)
template<int NKC, int ASTR, int BSTR>
static __device__ void gemm2t(float (*acc)[4], uint32_t aBase, uint32_t bBase) {
    const int lane = threadIdx.x & 31;
    const int KB = NKC * 32;
    uint32_t aAddr = aBase + (lane & 15) * ASTR + ((lane >> 4) << 4);
    uint32_t bAddr = bBase + (lane & 7) * BSTR + (((lane >> 3) & 1) << 4)
                   + ((lane >> 4) & 1) * 8 * BSTR;
    #pragma unroll
    for (int kc = 0; kc < NKC; ++kc) {
        uint32_t ah[4], al[4];
        ldmA(ah, aAddr + kc * 32);
        ldmA(al, aAddr + kc * 32 + KB);
        uint32_t bh[4][4];
        #pragma unroll
        for (int jp = 0; jp < 4; ++jp)
            ldmB4(bh[jp], bAddr + jp * 16 * BSTR + kc * 32);
        #pragma unroll
        for (int jp = 0; jp < 4; ++jp) {
            mma16816(acc[2 * jp],     ah, &bh[jp][0]);
            mma16816(acc[2 * jp + 1], ah, &bh[jp][2]);
        }
        #pragma unroll
        for (int jp = 0; jp < 4; ++jp) {
            mma16816(acc[2 * jp],     al, &bh[jp][0]);
            mma16816(acc[2 * jp + 1], al, &bh[jp][2]);
        }
    }
}

// build m16n8k16 A fragments (hi+lo) from register values v[rowhalf][j][2]
static __device__ __forceinline__ void build_fr(const float v[2][8][2],
                                                uint32_t fh[4][4], uint32_t fl[4][4]) {
    #pragma unroll
    for (int kc = 0; kc < 4; ++kc)
        #pragma unroll
        for (int m = 0; m < 4; ++m) {
            int h = m & 1, j = 2 * kc + (m >> 1);
            cvt_pair(v[h][j][0], v[h][j][1], fh[kc][m], fl[kc][m]);
        }
}

// hi/lo fp16 pair store into padded tile [r][strideElems], hi cols 0:K, lo K:2K
static __device__ __forceinline__ void st_hilo(char* sm, uint32_t off, int strideElems,
                                               int r, int c, int K, float f0, float f1) {
    uint32_t hh, ll;
    cvt_pair(f0, f1, hh, ll);
    __half* row = (__half*)(sm + off) + (size_t)r * strideElems;
    *reinterpret_cast<uint32_t*>(row + c)     = hh;
    *reinterpret_cast<uint32_t*>(row + K + c) = ll;
}

// embed gemm: A rows 0-7 = user feats (K cols 0:128), rows 8-15 = item feats (128:256).
// B hi-only image [64][528B]. 2-term; fragments built on the fly.
static __device__ void gemm2_emb(float (*acc)[4], const float* __restrict__ fpU,
                                 const float* __restrict__ fpI, uint32_t bBase, int qc) {
    const int lane = threadIdx.x & 31;
    uint32_t bAddr = bBase + (lane & 7) * 528 + (((lane >> 3) & 1) << 4)
                   + ((lane >> 4) & 1) * 8 * 528;
    #pragma unroll
    for (int kc = 0; kc < 16; ++kc) {
        uint32_t ah[4] = {0u, 0u, 0u, 0u}, al[4] = {0u, 0u, 0u, 0u};
        if (kc < 8) {
            int col = 16 * kc + 2 * qc;
            float2 f0 = __ldg(reinterpret_cast<const float2*>(fpU + col));
            float2 f1 = __ldg(reinterpret_cast<const float2*>(fpU + col + 8));
            cvt_pair(f0.x, f0.y, ah[0], al[0]);
            cvt_pair(f1.x, f1.y, ah[2], al[2]);
        } else {
            int col = 16 * (kc - 8) + 2 * qc;
            float2 f0 = __ldg(reinterpret_cast<const float2*>(fpI + col));
            float2 f1 = __ldg(reinterpret_cast<const float2*>(fpI + col + 8));
            cvt_pair(f0.x, f0.y, ah[1], al[1]);
            cvt_pair(f1.x, f1.y, ah[3], al[3]);
        }
        uint32_t bh[4][4];
        #pragma unroll
        for (int jp = 0; jp < 4; ++jp)
            ldmB4(bh[jp], bAddr + jp * 16 * 528 + kc * 32);
        #pragma unroll
        for (int jp = 0; jp < 4; ++jp) {
            mma16816(acc[2 * jp],     ah, &bh[jp][0]);
            mma16816(acc[2 * jp + 1], ah, &bh[jp][2]);
        }
        #pragma unroll
        for (int jp = 0; jp < 4; ++jp) {
            mma16816(acc[2 * jp],     al, &bh[jp][0]);
            mma16816(acc[2 * jp + 1], al, &bh[jp][2]);
        }
    }
}

// ---------------- cp.async ----------------
#define CP16(dst, src) asm volatile("cp.async.cg.shared.global [%0], [%1], 16;" \
                                    :: "r"(dst), "l"(src) : "memory")
#define CP_COMMIT() asm volatile("cp.async.commit_group;" ::: "memory")
#define CP_WAIT0()  asm volatile("cp.async.wait_group 0;" ::: "memory")

static __device__ __forceinline__ void stage_cp256(uint32_t dst, const unsigned char* src,
                                                   int bytes, int tid) {
    for (int o = tid * 16; o < bytes; o += 256 * 16)
        CP16(dst + o, src + o);
}

// =====================================================================================
// Kernel 1: convert all weights to fp16 HI-ONLY tile images (26 blocks)
//   chunks 0..23: [64][144B]  (128B hi | 16 pad)
//   h1:           [64][272B]  (256B hi | 16 pad)
//   embed [upw|ipw]: [64][528B] (512B hi | 16 pad)
// =====================================================================================
__global__ void conv_w_kernel(const float* __restrict__ in_w, const float* __restrict__ out_w,
                              const float* __restrict__ ff1_w, const float* __restrict__ ff2_w,
                              const float* __restrict__ h1_w, const float* __restrict__ upw,
                              const float* __restrict__ ipw)
{
    int b = blockIdx.x;
    if (b < 24) {
        int l = b / 12, c = b % 12;
        const float* src; int rs;
        if (c < 3)       { src = in_w  + ((size_t)l * 192 + 64 * c) * 64; rs = 64; }
        else if (c == 3) { src = out_w + (size_t)l * 4096;                rs = 64; }
        else {
            int cc = (c - 4) >> 1;
            if (((c - 4) & 1) == 0) { src = ff1_w + ((size_t)l * 256 + 64 * cc) * 64; rs = 64;  }
            else                    { src = ff2_w + (size_t)l * 16384 + 64 * cc;      rs = 256; }
        }
        unsigned char* dst = g_wbuf + (size_t)b * CH_SZ;
        for (int idx = threadIdx.x; idx < 64 * 32; idx += 256) {
            int n = idx >> 5, k2 = (idx & 31) << 1;
            float2 f = *reinterpret_cast<const float2*>(src + (size_t)n * rs + k2);
            *reinterpret_cast<uint32_t*>(dst + n * 144 + k2 * 2) = cvt_hi(f.x, f.y);
        }
    } else if (b == 24) {
        unsigned char* dst = g_wbuf + WOFF_H1;
        for (int idx = threadIdx.x; idx < 64 * 64; idx += 256) {
            int n = idx >> 6, k2 = (idx & 63) << 1;
            float2 f = *reinterpret_cast<const float2*>(h1_w + (size_t)n * 128 + k2);
            *reinterpret_cast<uint32_t*>(dst + n * 272 + k2 * 2) = cvt_hi(f.x, f.y);
        }
    } else {
        unsigned char* dst = g_wbuf + WOFF_EMB;
        for (int idx = threadIdx.x; idx < 64 * 128; idx += 256) {
            int n = idx >> 7, k2 = (idx & 127) << 1;
            float2 f = (k2 < 128)
                     ? *reinterpret_cast<const float2*>(upw + (size_t)n * 128 + k2)
                     : *reinterpret_cast<const float2*>(ipw + (size_t)n * 128 + (k2 - 128));
            *reinterpret_cast<uint32_t*>(dst + n * 528 + k2 * 2) = cvt_hi(f.x, f.y);
        }
    }
}

// =====================================================================================
// Kernel 2 (main): fully fused. 256 threads, 64 samples.
// warp w, thread qr owns SAMPLE sl=8w+qr: token rows in-thread (user=regs[0], item=regs[1]).
// smem: XT head tile [64][528B] @0 | WB ring 2x33792 @33792  total 101376
// phases: p0 embed, p1..p12 transformer, p13 head.
// =====================================================================================
#define XT_OFF 0u
#define WB_OFF 33792u
#define SLOT_SZ 33792u
#define MAIN_SMEM (33792u + 2u * SLOT_SZ)
#define MT 256

static __device__ __forceinline__ void phase_src(int p, int& off, int& bytes) {
    if (p == 0)  { off = WOFF_EMB; bytes = 33792; return; }
    if (p == 13) { off = WOFF_H1;  bytes = 17408; return; }
    int l = (p - 1) / 6, k = (p - 1) % 6;
    int ch = l * 12 + (k == 0 ? 0 : (k == 1 ? 3 : 4 + 2 * (k - 2)));
    off = ch * CH_SZ;
    bytes = (k == 0 ? 3 * CH_SZ : (k == 1 ? CH_SZ : 2 * CH_SZ));
}

// register-only LayerNorm over one 64-wide row spread across 4 qc lanes
static __device__ __forceinline__ void ln_reg(float v[8][2], const float* g, const float* b, int qc) {
    float s = 0.f;
    #pragma unroll
    for (int j = 0; j < 8; ++j) s += v[j][0] + v[j][1];
    s += __shfl_xor_sync(0xffffffffu, s, 1);
    s += __shfl_xor_sync(0xffffffffu, s, 2);
    float m = s * (1.f / 64.f);
    float var = 0.f;
    #pragma unroll
    for (int j = 0; j < 8; ++j) {
        float d0 = v[j][0] - m, d1 = v[j][1] - m;
        var += d0 * d0 + d1 * d1;
    }
    var += __shfl_xor_sync(0xffffffffu, var, 1);
    var += __shfl_xor_sync(0xffffffffu, var, 2);
    float inv = rsqrtf(var * (1.f / 64.f) + 1e-5f);
    #pragma unroll
    for (int j = 0; j < 8; ++j) {
        int cc = 8 * j + 2 * qc;
        v[j][0] = (v[j][0] - m) * inv * __ldg(g + cc)     + __ldg(b + cc);
        v[j][1] = (v[j][1] - m) * inv * __ldg(g + cc + 1) + __ldg(b + cc + 1);
    }
}

__global__ void __launch_bounds__(MT, 1)
main_kernel(const int* __restrict__ user_idx, const int* __restrict__ item_idx,
            const float* __restrict__ user_features, const float* __restrict__ item_features,
            const float* __restrict__ user_table, const float* __restrict__ item_table,
            const float* __restrict__ upb, const float* __restrict__ ipb,
            const float* __restrict__ pe,
            const float* __restrict__ in_b, const float* __restrict__ out_b,
            const float* __restrict__ ln1_g, const float* __restrict__ ln1_b,
            const float* __restrict__ ff1_b, const float* __restrict__ ff2_b,
            const float* __restrict__ ln2_g, const float* __restrict__ ln2_b,
            const float* __restrict__ h1_b, const float* __restrict__ h2_w,
            const float* __restrict__ h2_b, float* __restrict__ out)
{
    extern __shared__ char sm[];
    const int tid = threadIdx.x, lane = tid & 31, w = tid >> 5;
    const int qr = lane >> 2, qc = lane & 3;
    const int sl = 8 * w + qr;                 // sample owned by this thread
    const int s0m = blockIdx.x << 6;
    const uint32_t xt_u = smem_u32(sm + XT_OFF);
    const uint32_t wb_u = smem_u32(sm + WB_OFF);
    const uint32_t slot[2] = { wb_u, wb_u + SLOT_SZ };

    // prefetch phase 0 (embed B image)
    stage_cp256(slot[0], g_wbuf + WOFF_EMB, 33792, tid);
    CP_COMMIT();

    float x_[2][8][2];                 // [0]=user token, [1]=item token
    uint32_t fxh[4][4], fxl[4][4];
    float accF[8][4];
    uint32_t fch[4][4], fcl[4][4];

    for (int p = 0; p <= 13; ++p) {
        CP_WAIT0();
        __syncthreads();
        if (p < 13) {
            int off, by; phase_src(p + 1, off, by);
            stage_cp256(slot[(p + 1) & 1], g_wbuf + off, by, tid);
            CP_COMMIT();
        }
        const uint32_t bb = slot[p & 1];

        if (p == 0) {
            // ======== embed ========
            float acc[8][4];
            #pragma unroll
            for (int j = 0; j < 8; ++j) { acc[j][0] = acc[j][1] = acc[j][2] = acc[j][3] = 0.f; }
            gemm2_emb(acc, user_features + (size_t)(s0m + sl) * 128,
                           item_features + (size_t)(s0m + sl) * 128, bb, qc);
            int uidx = __ldg(user_idx + s0m + sl);
            int iidx = __ldg(item_idx + s0m + sl);
            const float* ut = user_table + (size_t)uidx * 64;
            const float* it = item_table + (size_t)iidx * 64;
            #pragma unroll
            for (int j = 0; j < 8; ++j) {
                int c = 8 * j + 2 * qc;
                x_[0][j][0] = acc[j][0] + __ldg(upb + c)     + __ldg(ut + c)     + __ldg(pe + c);
                x_[0][j][1] = acc[j][1] + __ldg(upb + c + 1) + __ldg(ut + c + 1) + __ldg(pe + c + 1);
                x_[1][j][0] = acc[j][2] + __ldg(ipb + c)     + __ldg(it + c)     + __ldg(pe + 64 + c);
                x_[1][j][1] = acc[j][3] + __ldg(ipb + c + 1) + __ldg(it + c + 1) + __ldg(pe + 64 + c + 1);
            }
            build_fr(x_, fxh, fxl);
        } else if (p == 13) {
            // ======== head ========
            if (w < 4) {
                float acc[8][4];
                #pragma unroll
                for (int j = 0; j < 8; ++j) { acc[j][0] = acc[j][1] = acc[j][2] = acc[j][3] = 0.f; }
                gemm2t<8, 528, 272>(acc, xt_u + (uint32_t)(16 * w) * 528u, bb);
                float pA = 0.f, pB = 0.f;
                #pragma unroll
                for (int j = 0; j < 8; ++j) {
                    int c = 8 * j + 2 * qc;
                    float b0 = __ldg(h1_b + c), b1 = __ldg(h1_b + c + 1);
                    float w0 = __ldg(h2_w + c), w1 = __ldg(h2_w + c + 1);
                    pA += fmaxf(acc[j][0] + b0, 0.f) * w0 + fmaxf(acc[j][1] + b1, 0.f) * w1;
                    pB += fmaxf(acc[j][2] + b0, 0.f) * w0 + fmaxf(acc[j][3] + b1, 0.f) * w1;
                }
                pA += __shfl_xor_sync(0xffffffffu, pA, 1);
                pA += __shfl_xor_sync(0xffffffffu, pA, 2);
                pB += __shfl_xor_sync(0xffffffffu, pB, 1);
                pB += __shfl_xor_sync(0xffffffffu, pB, 2);
                if (qc == 0) {
                    float hb = __ldg(h2_b);
                    out[s0m + 16 * w + qr]     = pA + hb;
                    out[s0m + 16 * w + qr + 8] = pB + hb;
                }
            }
        } else {
            const int l = (p - 1) / 6, k = (p - 1) % 6;
            if (k == 0) {
                // ======== qkv + attention (partner token in-thread) ========
                float q_[8][4];
                #pragma unroll
                for (int j = 0; j < 8; ++j) { q_[j][0] = q_[j][1] = q_[j][2] = q_[j][3] = 0.f; }
                gemm2r4<4, 144>(q_, fxh, fxl, bb);
                const float* bq = in_b + l * 192;
                #pragma unroll
                for (int j = 0; j < 8; ++j) {
                    int c = 8 * j + 2 * qc;
                    float b0 = __ldg(bq + c), b1 = __ldg(bq + c + 1);
                    q_[j][0] += b0; q_[j][1] += b1; q_[j][2] += b0; q_[j][3] += b1;
                }
                float t_[8][4];
                #pragma unroll
                for (int j = 0; j < 8; ++j) { t_[j][0] = t_[j][1] = t_[j][2] = t_[j][3] = 0.f; }
                gemm2r4<4, 144>(t_, fxh, fxl, bb + (uint32_t)CH_SZ);
                const float* bk = in_b + l * 192 + 64;
                #pragma unroll
                for (int j = 0; j < 8; ++j) {
                    int c = 8 * j + 2 * qc;
                    float b0 = __ldg(bk + c), b1 = __ldg(bk + c + 1);
                    t_[j][0] += b0; t_[j][1] += b1; t_[j][2] += b0; t_[j][3] += b1;
                }
                float wUU[4], wUI[4], wIU[4], wII[4];
                {
                    float sUU[4], sUI[4], sIU[4], sII[4];
                    #pragma unroll
                    for (int h = 0; h < 4; ++h) {
                        int j0 = 2 * h, j1 = 2 * h + 1;
                        sUU[h] = q_[j0][0] * t_[j0][0] + q_[j0][1] * t_[j0][1]
                               + q_[j1][0] * t_[j1][0] + q_[j1][1] * t_[j1][1];
                        sUI[h] = q_[j0][0] * t_[j0][2] + q_[j0][1] * t_[j0][3]
                               + q_[j1][0] * t_[j1][2] + q_[j1][1] * t_[j1][3];
                        sIU[h] = q_[j0][2] * t_[j0][0] + q_[j0][3] * t_[j0][1]
                               + q_[j1][2] * t_[j1][0] + q_[j1][3] * t_[j1][1];
                        sII[h] = q_[j0][2] * t_[j0][2] + q_[j0][3] * t_[j0][3]
                               + q_[j1][2] * t_[j1][2] + q_[j1][3] * t_[j1][3];
                    }
                    #pragma unroll
                    for (int h = 0; h < 4; ++h) {
                        sUU[h] += __shfl_xor_sync(0xffffffffu, sUU[h], 1);
                        sUU[h] += __shfl_xor_sync(0xffffffffu, sUU[h], 2);
                        sUI[h] += __shfl_xor_sync(0xffffffffu, sUI[h], 1);
                        sUI[h] += __shfl_xor_sync(0xffffffffu, sUI[h], 2);
                        sIU[h] += __shfl_xor_sync(0xffffffffu, sIU[h], 1);
                        sIU[h] += __shfl_xor_sync(0xffffffffu, sIU[h], 2);
                        sII[h] += __shfl_xor_sync(0xffffffffu, sII[h], 1);
                        sII[h] += __shfl_xor_sync(0xffffffffu, sII[h], 2);
                        float a = sUU[h] * 0.25f, o = sUI[h] * 0.25f;
                        float m = fmaxf(a, o);
                        float ea = __expf(a - m), eo = __expf(o - m);
                        float inv = __fdividef(1.f, ea + eo);
                        wUU[h] = ea * inv; wUI[h] = eo * inv;
                        a = sIU[h] * 0.25f; o = sII[h] * 0.25f;
                        m = fmaxf(a, o);
                        ea = __expf(a - m); eo = __expf(o - m);
                        inv = __fdividef(1.f, ea + eo);
                        wIU[h] = ea * inv; wII[h] = eo * inv;
                    }
                }
                // v (reuse t_)
                #pragma unroll
                for (int j = 0; j < 8; ++j) { t_[j][0] = t_[j][1] = t_[j][2] = t_[j][3] = 0.f; }
                gemm2r4<4, 144>(t_, fxh, fxl, bb + 2u * CH_SZ);
                const float* bv = in_b + l * 192 + 128;
                #pragma unroll
                for (int j = 0; j < 8; ++j) {
                    int c = 8 * j + 2 * qc;
                    float b0 = __ldg(bv + c), b1 = __ldg(bv + c + 1);
                    t_[j][0] += b0; t_[j][1] += b1; t_[j][2] += b0; t_[j][3] += b1;
                }
                #pragma unroll
                for (int j = 0; j < 8; ++j) {
                    int h = j >> 1;
                    float c00 = wUU[h] * t_[j][0] + wUI[h] * t_[j][2];
                    float c01 = wUU[h] * t_[j][1] + wUI[h] * t_[j][3];
                    float c10 = wIU[h] * t_[j][0] + wII[h] * t_[j][2];
                    float c11 = wIU[h] * t_[j][1] + wII[h] * t_[j][3];
                    int kc = j >> 1, jh = j & 1;
                    cvt_pair(c00, c01, fch[kc][(jh << 1) | 0], fcl[kc][(jh << 1) | 0]);
                    cvt_pair(c10, c11, fch[kc][(jh << 1) | 1], fcl[kc][(jh << 1) | 1]);
                }
            } else if (k == 1) {
                // ======== out-proj + residual + LN1 ========
                float acc[8][4];
                #pragma unroll
                for (int j = 0; j < 8; ++j) { acc[j][0] = acc[j][1] = acc[j][2] = acc[j][3] = 0.f; }
                gemm2r4<4, 144>(acc, fch, fcl, bb);
                const float* bo = out_b + l * 64;
                #pragma unroll
                for (int j = 0; j < 8; ++j) {
                    int c = 8 * j + 2 * qc;
                    float b0 = __ldg(bo + c), b1 = __ldg(bo + c + 1);
                    x_[0][j][0] += acc[j][0] + b0; x_[0][j][1] += acc[j][1] + b1;
                    x_[1][j][0] += acc[j][2] + b0; x_[1][j][1] += acc[j][3] + b1;
                }
                ln_reg(x_[0], ln1_g + l * 64, ln1_b + l * 64, qc);
                ln_reg(x_[1], ln1_g + l * 64, ln1_b + l * 64, qc);
                build_fr(x_, fxh, fxl);
            } else {
                // ======== ff pair ========
                int c4 = k - 2;
                float acc[8][4];
                #pragma unroll
                for (int j = 0; j < 8; ++j) { acc[j][0] = acc[j][1] = acc[j][2] = acc[j][3] = 0.f; }
                gemm2r4<4, 144>(acc, fxh, fxl, bb);
                const float* b1p = ff1_b + l * 256 + 64 * c4;
                #pragma unroll
                for (int j = 0; j < 8; ++j) {
                    int c = 8 * j + 2 * qc;
                    float b0 = __ldg(b1p + c), b1 = __ldg(b1p + c + 1);
                    float h00 = fmaxf(acc[j][0] + b0, 0.f), h01 = fmaxf(acc[j][1] + b1, 0.f);
                    float h10 = fmaxf(acc[j][2] + b0, 0.f), h11 = fmaxf(acc[j][3] + b1, 0.f);
                    int kc = j >> 1, jh = j & 1;
                    cvt_pair(h00, h01, fch[kc][(jh << 1) | 0], fcl[kc][(jh << 1) | 0]);
                    cvt_pair(h10, h11, fch[kc][(jh << 1) | 1], fcl[kc][(jh << 1) | 1]);
                }
                if (c4 == 0) {
                    #pragma unroll
                    for (int j = 0; j < 8; ++j) { accF[j][0] = accF[j][1] = accF[j][2] = accF[j][3] = 0.f; }
                }
                gemm2r4<4, 144>(accF, fch, fcl, bb + (uint32_t)CH_SZ);
                if (c4 == 3) {
                    const float* b2 = ff2_b + l * 64;
                    #pragma unroll
                    for (int j = 0; j < 8; ++j) {
                        int c = 8 * j + 2 * qc;
                        float b0 = __ldg(b2 + c), b1 = __ldg(b2 + c + 1);
                        x_[0][j][0] += accF[j][0] + b0; x_[0][j][1] += accF[j][1] + b1;
                        x_[1][j][0] += accF[j][2] + b0; x_[1][j][1] += accF[j][3] + b1;
                    }
                    ln_reg(x_[0], ln2_g + l * 64, ln2_b + l * 64, qc);
                    ln_reg(x_[1], ln2_g + l * 64, ln2_b + l * 64, qc);
                    if (l == 0) {
                        build_fr(x_, fxh, fxl);
                    } else {
                        // head A tile: row = sample; user cols 0:64, item cols 64:128 (hi), lo at +128
                        #pragma unroll
                        for (int j = 0; j < 8; ++j) {
                            int c = 8 * j + 2 * qc;
                            st_hilo(sm, XT_OFF, 264, sl, c,      128, x_[0][j][0], x_[0][j][1]);
                            st_hilo(sm, XT_OFF, 264, sl, 64 + c, 128, x_[1][j][0], x_[1][j][1]);
                        }
                    }
                }
            }
        }
    }
}

// =====================================================================================
extern "C" void kernel_launch(void* const* d_in, const int* in_sizes, int n_in,
                              void* d_out, int out_size)
{
    const int*   user_idx      = (const int*)  d_in[0];
    const int*   item_idx      = (const int*)  d_in[1];
    const float* user_features = (const float*)d_in[2];
    const float* item_features = (const float*)d_in[3];
    const float* user_table    = (const float*)d_in[4];
    const float* item_table    = (const float*)d_in[5];
    const float* upw           = (const float*)d_in[6];
    const float* upb           = (const float*)d_in[7];
    const float* ipw           = (const float*)d_in[8];
    const float* ipb           = (const float*)d_in[9];
    const float* pe            = (const float*)d_in[10];
    const float* in_w          = (const float*)d_in[11];
    const float* in_b          = (const float*)d_in[12];
    const float* out_w         = (const float*)d_in[13];
    const float* out_b         = (const float*)d_in[14];
    const float* ln1_g         = (const float*)d_in[15];
    const float* ln1_b         = (const float*)d_in[16];
    const float* ff1_w         = (const float*)d_in[17];
    const float* ff1_b         = (const float*)d_in[18];
    const float* ff2_w         = (const float*)d_in[19];
    const float* ff2_b         = (const float*)d_in[20];
    const float* ln2_g         = (const float*)d_in[21];
    const float* ln2_b         = (const float*)d_in[22];
    const float* h1_w          = (const float*)d_in[23];
    const float* h1_b          = (const float*)d_in[24];
    const float* h2_w          = (const float*)d_in[25];
    const float* h2_b          = (const float*)d_in[26];
    float* out = (float*)d_out;

    const int B = in_sizes[0];

    static bool attr_set = false;
    if (!attr_set) {
        cudaFuncSetAttribute(main_kernel, cudaFuncAttributeMaxDynamicSharedMemorySize, MAIN_SMEM);
        attr_set = true;
    }

    conv_w_kernel<<<26, 256>>>(in_w, out_w, ff1_w, ff2_w, h1_w, upw, ipw);
    main_kernel<<<B / 64, MT, MAIN_SMEM>>>(user_idx, item_idx, user_features, item_features,
                                           user_table, item_table, upb, ipb, pe,
                                           in_b, out_b, ln1_g, ln1_b, ff1_b, ff2_b,
                                           ln2_g, ln2_b, h1_b, h2_w, h2_b, out);
}

// round 14
// speedup vs baseline: 1.8530x; 1.3736x over previous
#include <cuda_runtime.h>
#include <cuda_fp16.h>
#include <cstdint>

// ---------------- persistent device scratch (no runtime allocation) ----------------
// 24 x 9216 K-chunk hi-images | h1 image 17408 | embed B image [upw|ipw] 33792
#define CH_SZ    9216
#define WOFF_H1  (24 * CH_SZ)
#define WOFF_EMB (WOFF_H1 + 17408)
__device__ __align__(16) unsigned char  g_wbuf[WOFF_EMB + 33792];

// ---------------- common helpers ----------------
static __device__ __forceinline__ uint32_t smem_u32(const void* p) {
    uint32_t a;
    asm("{ .reg .u64 t; cvta.to.shared.u64 t, %1; cvt.u32.u64 %0, t; }" : "=r"(a) : "l"(p));
    return a;
}
static __device__ __forceinline__ void ldmA(uint32_t a[4], uint32_t addr) {
    asm volatile("ldmatrix.sync.aligned.m8n8.x4.shared.b16 {%0,%1,%2,%3}, [%4];"
                 : "=r"(a[0]), "=r"(a[1]), "=r"(a[2]), "=r"(a[3]) : "r"(addr));
}
static __device__ __forceinline__ void ldmB4(uint32_t b[4], uint32_t addr) {
    asm volatile("ldmatrix.sync.aligned.m8n8.x4.shared.b16 {%0,%1,%2,%3}, [%4];"
                 : "=r"(b[0]), "=r"(b[1]), "=r"(b[2]), "=r"(b[3]) : "r"(addr));
}
static __device__ __forceinline__ void mma16816(float d[4], const uint32_t a[4], const uint32_t b[2]) {
    asm volatile("mma.sync.aligned.m16n8k16.row.col.f32.f16.f16.f32 "
                 "{%0,%1,%2,%3}, {%4,%5,%6,%7}, {%8,%9}, {%0,%1,%2,%3};"
                 : "+f"(d[0]), "+f"(d[1]), "+f"(d[2]), "+f"(d[3])
                 : "r"(a[0]), "r"(a[1]), "r"(a[2]), "r"(a[3]), "r"(b[0]), "r"(b[1]));
}

// fp32 pair -> packed fp16
static __device__ __forceinline__ uint32_t cvt_hi(float v0, float v1) {
    __half2 hb = __floats2half2_rn(v0, v1);
    return *reinterpret_cast<uint32_t*>(&hb);
}

// 1-term fp16 gemm, register A (hi only), B hi tile [64 rows][BSTR bytes]
template<int NKC, int BSTR>
static __device__ __forceinline__ void gemm1r4(float (*acc)[4],
        const uint32_t (*fh)[4], uint32_t bBase) {
    const int lane = threadIdx.x & 31;
    uint32_t bAddr = bBase + (lane & 7) * BSTR + (((lane >> 3) & 1) << 4)
                   + ((lane >> 4) & 1) * 8 * BSTR;
    #pragma unroll
    for (int kc = 0; kc < NKC; ++kc) {
        uint32_t bh[4][4];
        #pragma unroll
        for (int jp = 0; jp < 4; ++jp)
            ldmB4(bh[jp], bAddr + jp * 16 * BSTR + kc * 32);
        #pragma unroll
        for (int jp = 0; jp < 4; ++jp) {
            mma16816(acc[2 * jp],     fh[kc], &bh[jp][0]);
            mma16816(acc[2 * jp + 1], fh[kc], &bh[jp][2]);
        }
    }
}

// 1-term gemm, tile A (hi only, [64 rows][ASTR bytes]) x B hi ([64][BSTR]) — head
template<int NKC, int ASTR, int BSTR>
static __device__ void gemm1t(float (*acc)[4], uint32_t aBase, uint32_t bBase) {
    const int lane = threadIdx.x & 31;
    uint32_t aAddr = aBase + (lane & 15) * ASTR + ((lane >> 4) << 4);
    uint32_t bAddr = bBase + (lane & 7) * BSTR + (((lane >> 3) & 1) << 4)
                   + ((lane >> 4) & 1) * 8 * BSTR;
    #pragma unroll
    for (int kc = 0; kc < NKC; ++kc) {
        uint32_t ah[4];
        ldmA(ah, aAddr + kc * 32);
        uint32_t bh[4][4];
        #pragma unroll
        for (int jp = 0; jp < 4; ++jp)
            ldmB4(bh[jp], bAddr + jp * 16 * BSTR + kc * 32);
        #pragma unroll
        for (int jp = 0; jp < 4; ++jp) {
            mma16816(acc[2 * jp],     ah, &bh[jp][0]);
            mma16816(acc[2 * jp + 1], ah, &bh[jp][2]);
        }
    }
}

// build m16n8k16 A fragments (hi only) from register values v[rowhalf][j][2]
static __device__ __forceinline__ void build_fr(const float v[2][8][2], uint32_t fh[4][4]) {
    #pragma unroll
    for (int kc = 0; kc < 4; ++kc)
        #pragma unroll
        for (int m = 0; m < 4; ++m) {
            int h = m & 1, j = 2 * kc + (m >> 1);
            fh[kc][m] = cvt_hi(v[h][j][0], v[h][j][1]);
        }
}

// fp16 pair store into tile [r][strideElems]
static __device__ __forceinline__ void st_hi(char* sm, uint32_t off, int strideElems,
                                             int r, int c, float f0, float f1) {
    __half* row = (__half*)(sm + off) + (size_t)r * strideElems;
    *reinterpret_cast<uint32_t*>(row + c) = cvt_hi(f0, f1);
}

// embed gemm: A rows 0-7 = user feats (K cols 0:128), rows 8-15 = item feats (128:256).
// B hi image [64][528B]. 1-term; fragments built on the fly.
static __device__ void gemm1_emb(float (*acc)[4], const float* __restrict__ fpU,
                                 const float* __restrict__ fpI, uint32_t bBase, int qc) {
    const int lane = threadIdx.x & 31;
    uint32_t bAddr = bBase + (lane & 7) * 528 + (((lane >> 3) & 1) << 4)
                   + ((lane >> 4) & 1) * 8 * 528;
    #pragma unroll
    for (int kc = 0; kc < 16; ++kc) {
        uint32_t ah[4] = {0u, 0u, 0u, 0u};
        if (kc < 8) {
            int col = 16 * kc + 2 * qc;
            float2 f0 = __ldg(reinterpret_cast<const float2*>(fpU + col));
            float2 f1 = __ldg(reinterpret_cast<const float2*>(fpU + col + 8));
            ah[0] = cvt_hi(f0.x, f0.y);
            ah[2] = cvt_hi(f1.x, f1.y);
        } else {
            int col = 16 * (kc - 8) + 2 * qc;
            float2 f0 = __ldg(reinterpret_cast<const float2*>(fpI + col));
            float2 f1 = __ldg(reinterpret_cast<const float2*>(fpI + col + 8));
            ah[1] = cvt_hi(f0.x, f0.y);
            ah[3] = cvt_hi(f1.x, f1.y);
        }
        uint32_t bh[4][4];
        #pragma unroll
        for (int jp = 0; jp < 4; ++jp)
            ldmB4(bh[jp], bAddr + jp * 16 * 528 + kc * 32);
        #pragma unroll
        for (int jp = 0; jp < 4; ++jp) {
            mma16816(acc[2 * jp],     ah, &bh[jp][0]);
            mma16816(acc[2 * jp + 1], ah, &bh[jp][2]);
        }
    }
}

// ---------------- cp.async ----------------
#define CP16(dst, src) asm volatile("cp.async.cg.shared.global [%0], [%1], 16;" \
                                    :: "r"(dst), "l"(src) : "memory")
#define CP_COMMIT() asm volatile("cp.async.commit_group;" ::: "memory")
#define CP_WAIT0()  asm volatile("cp.async.wait_group 0;" ::: "memory")

static __device__ __forceinline__ void stage_cp256(uint32_t dst, const unsigned char* src,
                                                   int bytes, int tid) {
    for (int o = tid * 16; o < bytes; o += 256 * 16)
        CP16(dst + o, src + o);
}

// =====================================================================================
// Kernel 1: convert all weights to fp16 HI-ONLY tile images (26 blocks)
// =====================================================================================
__global__ void conv_w_kernel(const float* __restrict__ in_w, const float* __restrict__ out_w,
                              const float* __restrict__ ff1_w, const float* __restrict__ ff2_w,
                              const float* __restrict__ h1_w, const float* __restrict__ upw,
                              const float* __restrict__ ipw)
{
    int b = blockIdx.x;
    if (b < 24) {
        int l = b / 12, c = b % 12;
        const float* src; int rs;
        if (c < 3)       { src = in_w  + ((size_t)l * 192 + 64 * c) * 64; rs = 64; }
        else if (c == 3) { src = out_w + (size_t)l * 4096;                rs = 64; }
        else {
            int cc = (c - 4) >> 1;
            if (((c - 4) & 1) == 0) { src = ff1_w + ((size_t)l * 256 + 64 * cc) * 64; rs = 64;  }
            else                    { src = ff2_w + (size_t)l * 16384 + 64 * cc;      rs = 256; }
        }
        unsigned char* dst = g_wbuf + (size_t)b * CH_SZ;
        for (int idx = threadIdx.x; idx < 64 * 32; idx += 256) {
            int n = idx >> 5, k2 = (idx & 31) << 1;
            float2 f = *reinterpret_cast<const float2*>(src + (size_t)n * rs + k2);
            *reinterpret_cast<uint32_t*>(dst + n * 144 + k2 * 2) = cvt_hi(f.x, f.y);
        }
    } else if (b == 24) {
        unsigned char* dst = g_wbuf + WOFF_H1;
        for (int idx = threadIdx.x; idx < 64 * 64; idx += 256) {
            int n = idx >> 6, k2 = (idx & 63) << 1;
            float2 f = *reinterpret_cast<const float2*>(h1_w + (size_t)n * 128 + k2);
            *reinterpret_cast<uint32_t*>(dst + n * 272 + k2 * 2) = cvt_hi(f.x, f.y);
        }
    } else {
        unsigned char* dst = g_wbuf + WOFF_EMB;
        for (int idx = threadIdx.x; idx < 64 * 128; idx += 256) {
            int n = idx >> 7, k2 = (idx & 127) << 1;
            float2 f = (k2 < 128)
                     ? *reinterpret_cast<const float2*>(upw + (size_t)n * 128 + k2)
                     : *reinterpret_cast<const float2*>(ipw + (size_t)n * 128 + (k2 - 128));
            *reinterpret_cast<uint32_t*>(dst + n * 528 + k2 * 2) = cvt_hi(f.x, f.y);
        }
    }
}

// =====================================================================================
// Kernel 2 (main): fully fused, pure fp16 MMA. 256 threads, 64 samples.
// warp w, thread qr owns SAMPLE sl=8w+qr: token rows in-thread (user=regs[0], item=regs[1]).
// smem: XT head tile [64][272B] @0 | WB ring 2x33792 @17408  total 84992
// phases: p0 embed, p1..p12 transformer, p13 head.
// =====================================================================================
#define XT_OFF 0u
#define WB_OFF 17408u
#define SLOT_SZ 33792u
#define MAIN_SMEM (17408u + 2u * SLOT_SZ)
#define MT 256

static __device__ __forceinline__ void phase_src(int p, int& off, int& bytes) {
    if (p == 0)  { off = WOFF_EMB; bytes = 33792; return; }
    if (p == 13) { off = WOFF_H1;  bytes = 17408; return; }
    int l = (p - 1) / 6, k = (p - 1) % 6;
    int ch = l * 12 + (k == 0 ? 0 : (k == 1 ? 3 : 4 + 2 * (k - 2)));
    off = ch * CH_SZ;
    bytes = (k == 0 ? 3 * CH_SZ : (k == 1 ? CH_SZ : 2 * CH_SZ));
}

// register-only LayerNorm over one 64-wide row spread across 4 qc lanes
static __device__ __forceinline__ void ln_reg(float v[8][2], const float* g, const float* b, int qc) {
    float s = 0.f;
    #pragma unroll
    for (int j = 0; j < 8; ++j) s += v[j][0] + v[j][1];
    s += __shfl_xor_sync(0xffffffffu, s, 1);
    s += __shfl_xor_sync(0xffffffffu, s, 2);
    float m = s * (1.f / 64.f);
    float var = 0.f;
    #pragma unroll
    for (int j = 0; j < 8; ++j) {
        float d0 = v[j][0] - m, d1 = v[j][1] - m;
        var += d0 * d0 + d1 * d1;
    }
    var += __shfl_xor_sync(0xffffffffu, var, 1);
    var += __shfl_xor_sync(0xffffffffu, var, 2);
    float inv = rsqrtf(var * (1.f / 64.f) + 1e-5f);
    #pragma unroll
    for (int j = 0; j < 8; ++j) {
        int cc = 8 * j + 2 * qc;
        v[j][0] = (v[j][0] - m) * inv * __ldg(g + cc)     + __ldg(b + cc);
        v[j][1] = (v[j][1] - m) * inv * __ldg(g + cc + 1) + __ldg(b + cc + 1);
    }
}

__global__ void __launch_bounds__(MT, 1)
main_kernel(const int* __restrict__ user_idx, const int* __restrict__ item_idx,
            const float* __restrict__ user_features, const float* __restrict__ item_features,
            const float* __restrict__ user_table, const float* __restrict__ item_table,
            const float* __restrict__ upb, const float* __restrict__ ipb,
            const float* __restrict__ pe,
            const float* __restrict__ in_b, const float* __restrict__ out_b,
            const float* __restrict__ ln1_g, const float* __restrict__ ln1_b,
            const float* __restrict__ ff1_b, const float* __restrict__ ff2_b,
            const float* __restrict__ ln2_g, const float* __restrict__ ln2_b,
            const float* __restrict__ h1_b, const float* __restrict__ h2_w,
            const float* __restrict__ h2_b, float* __restrict__ out)
{
    extern __shared__ char sm[];
    const int tid = threadIdx.x, lane = tid & 31, w = tid >> 5;
    const int qr = lane >> 2, qc = lane & 3;
    const int sl = 8 * w + qr;                 // sample owned by this thread
    const int s0m = blockIdx.x << 6;
    const uint32_t xt_u = smem_u32(sm + XT_OFF);
    const uint32_t wb_u = smem_u32(sm + WB_OFF);
    const uint32_t slot[2] = { wb_u, wb_u + SLOT_SZ };

    // prefetch phase 0 (embed B image)
    stage_cp256(slot[0], g_wbuf + WOFF_EMB, 33792, tid);
    CP_COMMIT();

    float x_[2][8][2];                 // [0]=user token, [1]=item token
    uint32_t fxh[4][4];
    float accF[8][4];
    uint32_t fch[4][4];

    for (int p = 0; p <= 13; ++p) {
        CP_WAIT0();
        __syncthreads();
        if (p < 13) {
            int off, by; phase_src(p + 1, off, by);
            stage_cp256(slot[(p + 1) & 1], g_wbuf + off, by, tid);
            CP_COMMIT();
        }
        const uint32_t bb = slot[p & 1];

        if (p == 0) {
            // ======== embed ========
            float acc[8][4];
            #pragma unroll
            for (int j = 0; j < 8; ++j) { acc[j][0] = acc[j][1] = acc[j][2] = acc[j][3] = 0.f; }
            gemm1_emb(acc, user_features + (size_t)(s0m + sl) * 128,
                           item_features + (size_t)(s0m + sl) * 128, bb, qc);
            int uidx = __ldg(user_idx + s0m + sl);
            int iidx = __ldg(item_idx + s0m + sl);
            const float* ut = user_table + (size_t)uidx * 64;
            const float* it = item_table + (size_t)iidx * 64;
            #pragma unroll
            for (int j = 0; j < 8; ++j) {
                int c = 8 * j + 2 * qc;
                x_[0][j][0] = acc[j][0] + __ldg(upb + c)     + __ldg(ut + c)     + __ldg(pe + c);
                x_[0][j][1] = acc[j][1] + __ldg(upb + c + 1) + __ldg(ut + c + 1) + __ldg(pe + c + 1);
                x_[1][j][0] = acc[j][2] + __ldg(ipb + c)     + __ldg(it + c)     + __ldg(pe + 64 + c);
                x_[1][j][1] = acc[j][3] + __ldg(ipb + c + 1) + __ldg(it + c + 1) + __ldg(pe + 64 + c + 1);
            }
            build_fr(x_, fxh);
        } else if (p == 13) {
            // ======== head ========
            if (w < 4) {
                float acc[8][4];
                #pragma unroll
                for (int j = 0; j < 8; ++j) { acc[j][0] = acc[j][1] = acc[j][2] = acc[j][3] = 0.f; }
                gemm1t<8, 272, 272>(acc, xt_u + (uint32_t)(16 * w) * 272u, bb);
                float pA = 0.f, pB = 0.f;
                #pragma unroll
                for (int j = 0; j < 8; ++j) {
                    int c = 8 * j + 2 * qc;
                    float b0 = __ldg(h1_b + c), b1 = __ldg(h1_b + c + 1);
                    float w0 = __ldg(h2_w + c), w1 = __ldg(h2_w + c + 1);
                    pA += fmaxf(acc[j][0] + b0, 0.f) * w0 + fmaxf(acc[j][1] + b1, 0.f) * w1;
                    pB += fmaxf(acc[j][2] + b0, 0.f) * w0 + fmaxf(acc[j][3] + b1, 0.f) * w1;
                }
                pA += __shfl_xor_sync(0xffffffffu, pA, 1);
                pA += __shfl_xor_sync(0xffffffffu, pA, 2);
                pB += __shfl_xor_sync(0xffffffffu, pB, 1);
                pB += __shfl_xor_sync(0xffffffffu, pB, 2);
                if (qc == 0) {
                    float hb = __ldg(h2_b);
                    out[s0m + 16 * w + qr]     = pA + hb;
                    out[s0m + 16 * w + qr + 8] = pB + hb;
                }
            }
        } else {
            const int l = (p - 1) / 6, k = (p - 1) % 6;
            if (k == 0) {
                // ======== qkv + attention (partner token in-thread) ========
                float q_[8][4];
                #pragma unroll
                for (int j = 0; j < 8; ++j) { q_[j][0] = q_[j][1] = q_[j][2] = q_[j][3] = 0.f; }
                gemm1r4<4, 144>(q_, fxh, bb);
                const float* bq = in_b + l * 192;
                #pragma unroll
                for (int j = 0; j < 8; ++j) {
                    int c = 8 * j + 2 * qc;
                    float b0 = __ldg(bq + c), b1 = __ldg(bq + c + 1);
                    q_[j][0] += b0; q_[j][1] += b1; q_[j][2] += b0; q_[j][3] += b1;
                }
                float t_[8][4];
                #pragma unroll
                for (int j = 0; j < 8; ++j) { t_[j][0] = t_[j][1] = t_[j][2] = t_[j][3] = 0.f; }
                gemm1r4<4, 144>(t_, fxh, bb + (uint32_t)CH_SZ);
                const float* bk = in_b + l * 192 + 64;
                #pragma unroll
                for (int j = 0; j < 8; ++j) {
                    int c = 8 * j + 2 * qc;
                    float b0 = __ldg(bk + c), b1 = __ldg(bk + c + 1);
                    t_[j][0] += b0; t_[j][1] += b1; t_[j][2] += b0; t_[j][3] += b1;
                }
                float wUU[4], wUI[4], wIU[4], wII[4];
                {
                    float sUU[4], sUI[4], sIU[4], sII[4];
                    #pragma unroll
                    for (int h = 0; h < 4; ++h) {
                        int j0 = 2 * h, j1 = 2 * h + 1;
                        sUU[h] = q_[j0][0] * t_[j0][0] + q_[j0][1] * t_[j0][1]
                               + q_[j1][0] * t_[j1][0] + q_[j1][1] * t_[j1][1];
                        sUI[h] = q_[j0][0] * t_[j0][2] + q_[j0][1] * t_[j0][3]
                               + q_[j1][0] * t_[j1][2] + q_[j1][1] * t_[j1][3];
                        sIU[h] = q_[j0][2] * t_[j0][0] + q_[j0][3] * t_[j0][1]
                               + q_[j1][2] * t_[j1][0] + q_[j1][3] * t_[j1][1];
                        sII[h] = q_[j0][2] * t_[j0][2] + q_[j0][3] * t_[j0][3]
                               + q_[j1][2] * t_[j1][2] + q_[j1][3] * t_[j1][3];
                    }
                    #pragma unroll
                    for (int h = 0; h < 4; ++h) {
                        sUU[h] += __shfl_xor_sync(0xffffffffu, sUU[h], 1);
                        sUU[h] += __shfl_xor_sync(0xffffffffu, sUU[h], 2);
                        sUI[h] += __shfl_xor_sync(0xffffffffu, sUI[h], 1);
                        sUI[h] += __shfl_xor_sync(0xffffffffu, sUI[h], 2);
                        sIU[h] += __shfl_xor_sync(0xffffffffu, sIU[h], 1);
                        sIU[h] += __shfl_xor_sync(0xffffffffu, sIU[h], 2);
                        sII[h] += __shfl_xor_sync(0xffffffffu, sII[h], 1);
                        sII[h] += __shfl_xor_sync(0xffffffffu, sII[h], 2);
                        float a = sUU[h] * 0.25f, o = sUI[h] * 0.25f;
                        float m = fmaxf(a, o);
                        float ea = __expf(a - m), eo = __expf(o - m);
                        float inv = __fdividef(1.f, ea + eo);
                        wUU[h] = ea * inv; wUI[h] = eo * inv;
                        a = sIU[h] * 0.25f; o = sII[h] * 0.25f;
                        m = fmaxf(a, o);
                        ea = __expf(a - m); eo = __expf(o - m);
                        inv = __fdividef(1.f, ea + eo);
                        wIU[h] = ea * inv; wII[h] = eo * inv;
                    }
                }
                // v (reuse t_)
                #pragma unroll
                for (int j = 0; j < 8; ++j) { t_[j][0] = t_[j][1] = t_[j][2] = t_[j][3] = 0.f; }
                gemm1r4<4, 144>(t_, fxh, bb + 2u * CH_SZ);
                const float* bv = in_b + l * 192 + 128;
                #pragma unroll
                for (int j = 0; j < 8; ++j) {
                    int c = 8 * j + 2 * qc;
                    float b0 = __ldg(bv + c), b1 = __ldg(bv + c + 1);
                    t_[j][0] += b0; t_[j][1] += b1; t_[j][2] += b0; t_[j][3] += b1;
                }
                #pragma unroll
                for (int j = 0; j < 8; ++j) {
                    int h = j >> 1;
                    float c00 = wUU[h] * t_[j][0] + wUI[h] * t_[j][2];
                    float c01 = wUU[h] * t_[j][1] + wUI[h] * t_[j][3];
                    float c10 = wIU[h] * t_[j][0] + wII[h] * t_[j][2];
                    float c11 = wIU[h] * t_[j][1] + wII[h] * t_[j][3];
                    int kc = j >> 1, jh = j & 1;
                    fch[kc][(jh << 1) | 0] = cvt_hi(c00, c01);
                    fch[kc][(jh << 1) | 1] = cvt_hi(c10, c11);
                }
            } else if (k == 1) {
                // ======== out-proj + residual + LN1 ========
                float acc[8][4];
                #pragma unroll
                for (int j = 0; j < 8; ++j) { acc[j][0] = acc[j][1] = acc[j][2] = acc[j][3] = 0.f; }
                gemm1r4<4, 144>(acc, fch, bb);
                const float* bo = out_b + l * 64;
                #pragma unroll
                for (int j = 0; j < 8; ++j) {
                    int c = 8 * j + 2 * qc;
                    float b0 = __ldg(bo + c), b1 = __ldg(bo + c + 1);
                    x_[0][j][0] += acc[j][0] + b0; x_[0][j][1] += acc[j][1] + b1;
                    x_[1][j][0] += acc[j][2] + b0; x_[1][j][1] += acc[j][3] + b1;
                }
                ln_reg(x_[0], ln1_g + l * 64, ln1_b + l * 64, qc);
                ln_reg(x_[1], ln1_g + l * 64, ln1_b + l * 64, qc);
                build_fr(x_, fxh);
            } else {
                // ======== ff pair ========
                int c4 = k - 2;
                float acc[8][4];
                #pragma unroll
                for (int j = 0; j < 8; ++j) { acc[j][0] = acc[j][1] = acc[j][2] = acc[j][3] = 0.f; }
                gemm1r4<4, 144>(acc, fxh, bb);
                const float* b1p = ff1_b + l * 256 + 64 * c4;
                #pragma unroll
                for (int j = 0; j < 8; ++j) {
                    int c = 8 * j + 2 * qc;
                    float b0 = __ldg(b1p + c), b1 = __ldg(b1p + c + 1);
                    float h00 = fmaxf(acc[j][0] + b0, 0.f), h01 = fmaxf(acc[j][1] + b1, 0.f);
                    float h10 = fmaxf(acc[j][2] + b0, 0.f), h11 = fmaxf(acc[j][3] + b1, 0.f);
                    int kc = j >> 1, jh = j & 1;
                    fch[kc][(jh << 1) | 0] = cvt_hi(h00, h01);
                    fch[kc][(jh << 1) | 1] = cvt_hi(h10, h11);
                }
                if (c4 == 0) {
                    #pragma unroll
                    for (int j = 0; j < 8; ++j) { accF[j][0] = accF[j][1] = accF[j][2] = accF[j][3] = 0.f; }
                }
                gemm1r4<4, 144>(accF, fch, bb + (uint32_t)CH_SZ);
                if (c4 == 3) {
                    const float* b2 = ff2_b + l * 64;
                    #pragma unroll
                    for (int j = 0; j < 8; ++j) {
                        int c = 8 * j + 2 * qc;
                        float b0 = __ldg(b2 + c), b1 = __ldg(b2 + c + 1);
                        x_[0][j][0] += accF[j][0] + b0; x_[0][j][1] += accF[j][1] + b1;
                        x_[1][j][0] += accF[j][2] + b0; x_[1][j][1] += accF[j][3] + b1;
                    }
                    ln_reg(x_[0], ln2_g + l * 64, ln2_b + l * 64, qc);
                    ln_reg(x_[1], ln2_g + l * 64, ln2_b + l * 64, qc);
                    if (l == 0) {
                        build_fr(x_, fxh);
                    } else {
                        // head A tile: row = sample; user cols 0:64, item cols 64:128
                        #pragma unroll
                        for (int j = 0; j < 8; ++j) {
                            int c = 8 * j + 2 * qc;
                            st_hi(sm, XT_OFF, 136, sl, c,      x_[0][j][0], x_[0][j][1]);
                            st_hi(sm, XT_OFF, 136, sl, 64 + c, x_[1][j][0], x_[1][j][1]);
                        }
                    }
                }
            }
        }
    }
}

// =====================================================================================
extern "C" void kernel_launch(void* const* d_in, const int* in_sizes, int n_in,
                              void* d_out, int out_size)
{
    const int*   user_idx      = (const int*)  d_in[0];
    const int*   item_idx      = (const int*)  d_in[1];
    const float* user_features = (const float*)d_in[2];
    const float* item_features = (const float*)d_in[3];
    const float* user_table    = (const float*)d_in[4];
    const float* item_table    = (const float*)d_in[5];
    const float* upw           = (const float*)d_in[6];
    const float* upb           = (const float*)d_in[7];
    const float* ipw           = (const float*)d_in[8];
    const float* ipb           = (const float*)d_in[9];
    const float* pe            = (const float*)d_in[10];
    const float* in_w          = (const float*)d_in[11];
    const float* in_b          = (const float*)d_in[12];
    const float* out_w         = (const float*)d_in[13];
    const float* out_b         = (const float*)d_in[14];
    const float* ln1_g         = (const float*)d_in[15];
    const float* ln1_b         = (const float*)d_in[16];
    const float* ff1_w         = (const float*)d_in[17];
    const float* ff1_b         = (const float*)d_in[18];
    const float* ff2_w         = (const float*)d_in[19];
    const float* ff2_b         = (const float*)d_in[20];
    const float* ln2_g         = (const float*)d_in[21];
    const float* ln2_b         = (const float*)d_in[22];
    const float* h1_w          = (const float*)d_in[23];
    const float* h1_b          = (const float*)d_in[24];
    const float* h2_w          = (const float*)d_in[25];
    const float* h2_b          = (const float*)d_in[26];
    float* out = (float*)d_out;

    const int B = in_sizes[0];

    static bool attr_set = false;
    if (!attr_set) {
        cudaFuncSetAttribute(main_kernel, cudaFuncAttributeMaxDynamicSharedMemorySize, MAIN_SMEM);
        attr_set = true;
    }

    conv_w_kernel<<<26, 256>>>(in_w, out_w, ff1_w, ff2_w, h1_w, upw, ipw);
    main_kernel<<<B / 64, MT, MAIN_SMEM>>>(user_idx, item_idx, user_features, item_features,
                                           user_table, item_table, upb, ipb, pe,
                                           in_b, out_b, ln1_g, ln1_b, ff1_b, ff2_b,
                                           ln2_g, ln2_b, h1_b, h2_w, h2_b, out);
}

// round 15
// speedup vs baseline: 1.9122x; 1.0319x over previous
#include <cuda_runtime.h>
#include <cuda_fp16.h>
#include <cstdint>

// ---------------- persistent device scratch (no runtime allocation) ----------------
// 24 x 9216 K-chunk hi-images | h1 image 17408 | embed B image [upw|ipw] 33792
#define CH_SZ    9216
#define WOFF_H1  (24 * CH_SZ)
#define WOFF_EMB (WOFF_H1 + 17408)
__device__ __align__(16) unsigned char  g_wbuf[WOFF_EMB + 33792];

// ---------------- common helpers ----------------
static __device__ __forceinline__ uint32_t smem_u32(const void* p) {
    uint32_t a;
    asm("{ .reg .u64 t; cvta.to.shared.u64 t, %1; cvt.u32.u64 %0, t; }" : "=r"(a) : "l"(p));
    return a;
}
static __device__ __forceinline__ void ldmA(uint32_t a[4], uint32_t addr) {
    asm volatile("ldmatrix.sync.aligned.m8n8.x4.shared.b16 {%0,%1,%2,%3}, [%4];"
                 : "=r"(a[0]), "=r"(a[1]), "=r"(a[2]), "=r"(a[3]) : "r"(addr));
}
static __device__ __forceinline__ void ldmB4(uint32_t b[4], uint32_t addr) {
    asm volatile("ldmatrix.sync.aligned.m8n8.x4.shared.b16 {%0,%1,%2,%3}, [%4];"
                 : "=r"(b[0]), "=r"(b[1]), "=r"(b[2]), "=r"(b[3]) : "r"(addr));
}
static __device__ __forceinline__ void mma16816(float d[4], const uint32_t a[4], const uint32_t b[2]) {
    asm volatile("mma.sync.aligned.m16n8k16.row.col.f32.f16.f16.f32 "
                 "{%0,%1,%2,%3}, {%4,%5,%6,%7}, {%8,%9}, {%0,%1,%2,%3};"
                 : "+f"(d[0]), "+f"(d[1]), "+f"(d[2]), "+f"(d[3])
                 : "r"(a[0]), "r"(a[1]), "r"(a[2]), "r"(a[3]), "r"(b[0]), "r"(b[1]));
}

// fp32 pair -> packed fp16
static __device__ __forceinline__ uint32_t cvt_hi(float v0, float v1) {
    __half2 hb = __floats2half2_rn(v0, v1);
    return *reinterpret_cast<uint32_t*>(&hb);
}

// 1-term fp16 gemm, register A (hi only), B hi tile [64 rows][BSTR bytes]
template<int NKC, int BSTR>
static __device__ __forceinline__ void gemm1r4(float (*acc)[4],
        const uint32_t (*fh)[4], uint32_t bBase) {
    const int lane = threadIdx.x & 31;
    uint32_t bAddr = bBase + (lane & 7) * BSTR + (((lane >> 3) & 1) << 4)
                   + ((lane >> 4) & 1) * 8 * BSTR;
    #pragma unroll
    for (int kc = 0; kc < NKC; ++kc) {
        uint32_t bh[4][4];
        #pragma unroll
        for (int jp = 0; jp < 4; ++jp)
            ldmB4(bh[jp], bAddr + jp * 16 * BSTR + kc * 32);
        #pragma unroll
        for (int jp = 0; jp < 4; ++jp) {
            mma16816(acc[2 * jp],     fh[kc], &bh[jp][0]);
            mma16816(acc[2 * jp + 1], fh[kc], &bh[jp][2]);
        }
    }
}

// 1-term gemm, tile A (hi only, [rows][ASTR bytes]) x B hi ([64][BSTR]) — head
template<int NKC, int ASTR, int BSTR>
static __device__ void gemm1t(float (*acc)[4], uint32_t aBase, uint32_t bBase) {
    const int lane = threadIdx.x & 31;
    uint32_t aAddr = aBase + (lane & 15) * ASTR + ((lane >> 4) << 4);
    uint32_t bAddr = bBase + (lane & 7) * BSTR + (((lane >> 3) & 1) << 4)
                   + ((lane >> 4) & 1) * 8 * BSTR;
    #pragma unroll
    for (int kc = 0; kc < NKC; ++kc) {
        uint32_t ah[4];
        ldmA(ah, aAddr + kc * 32);
        uint32_t bh[4][4];
        #pragma unroll
        for (int jp = 0; jp < 4; ++jp)
            ldmB4(bh[jp], bAddr + jp * 16 * BSTR + kc * 32);
        #pragma unroll
        for (int jp = 0; jp < 4; ++jp) {
            mma16816(acc[2 * jp],     ah, &bh[jp][0]);
            mma16816(acc[2 * jp + 1], ah, &bh[jp][2]);
        }
    }
}

// build m16n8k16 A fragments (hi only) from register values v[rowhalf][j][2]
static __device__ __forceinline__ void build_fr(const float v[2][8][2], uint32_t fh[4][4]) {
    #pragma unroll
    for (int kc = 0; kc < 4; ++kc)
        #pragma unroll
        for (int m = 0; m < 4; ++m) {
            int h = m & 1, j = 2 * kc + (m >> 1);
            fh[kc][m] = cvt_hi(v[h][j][0], v[h][j][1]);
        }
}

// fp16 pair store into tile [r][strideElems]
static __device__ __forceinline__ void st_hi(char* sm, uint32_t off, int strideElems,
                                             int r, int c, float f0, float f1) {
    __half* row = (__half*)(sm + off) + (size_t)r * strideElems;
    *reinterpret_cast<uint32_t*>(row + c) = cvt_hi(f0, f1);
}

// embed gemm: A rows 0-7 = user feats (K cols 0:128), rows 8-15 = item feats (128:256).
// B hi image [64][528B]. 1-term; fragments built on the fly.
static __device__ void gemm1_emb(float (*acc)[4], const float* __restrict__ fpU,
                                 const float* __restrict__ fpI, uint32_t bBase, int qc) {
    const int lane = threadIdx.x & 31;
    uint32_t bAddr = bBase + (lane & 7) * 528 + (((lane >> 3) & 1) << 4)
                   + ((lane >> 4) & 1) * 8 * 528;
    #pragma unroll
    for (int kc = 0; kc < 16; ++kc) {
        uint32_t ah[4] = {0u, 0u, 0u, 0u};
        if (kc < 8) {
            int col = 16 * kc + 2 * qc;
            float2 f0 = __ldg(reinterpret_cast<const float2*>(fpU + col));
            float2 f1 = __ldg(reinterpret_cast<const float2*>(fpU + col + 8));
            ah[0] = cvt_hi(f0.x, f0.y);
            ah[2] = cvt_hi(f1.x, f1.y);
        } else {
            int col = 16 * (kc - 8) + 2 * qc;
            float2 f0 = __ldg(reinterpret_cast<const float2*>(fpI + col));
            float2 f1 = __ldg(reinterpret_cast<const float2*>(fpI + col + 8));
            ah[1] = cvt_hi(f0.x, f0.y);
            ah[3] = cvt_hi(f1.x, f1.y);
        }
        uint32_t bh[4][4];
        #pragma unroll
        for (int jp = 0; jp < 4; ++jp)
            ldmB4(bh[jp], bAddr + jp * 16 * 528 + kc * 32);
        #pragma unroll
        for (int jp = 0; jp < 4; ++jp) {
            mma16816(acc[2 * jp],     ah, &bh[jp][0]);
            mma16816(acc[2 * jp + 1], ah, &bh[jp][2]);
        }
    }
}

// ---------------- cp.async ----------------
#define CP16(dst, src) asm volatile("cp.async.cg.shared.global [%0], [%1], 16;" \
                                    :: "r"(dst), "l"(src) : "memory")
#define CP_COMMIT() asm volatile("cp.async.commit_group;" ::: "memory")
#define CP_WAIT0()  asm volatile("cp.async.wait_group 0;" ::: "memory")

// =====================================================================================
// Kernel 1: convert all weights to fp16 HI-ONLY tile images (26 blocks)
// =====================================================================================
__global__ void conv_w_kernel(const float* __restrict__ in_w, const float* __restrict__ out_w,
                              const float* __restrict__ ff1_w, const float* __restrict__ ff2_w,
                              const float* __restrict__ h1_w, const float* __restrict__ upw,
                              const float* __restrict__ ipw)
{
    int b = blockIdx.x;
    if (b < 24) {
        int l = b / 12, c = b % 12;
        const float* src; int rs;
        if (c < 3)       { src = in_w  + ((size_t)l * 192 + 64 * c) * 64; rs = 64; }
        else if (c == 3) { src = out_w + (size_t)l * 4096;                rs = 64; }
        else {
            int cc = (c - 4) >> 1;
            if (((c - 4) & 1) == 0) { src = ff1_w + ((size_t)l * 256 + 64 * cc) * 64; rs = 64;  }
            else                    { src = ff2_w + (size_t)l * 16384 + 64 * cc;      rs = 256; }
        }
        unsigned char* dst = g_wbuf + (size_t)b * CH_SZ;
        for (int idx = threadIdx.x; idx < 64 * 32; idx += 256) {
            int n = idx >> 5, k2 = (idx & 31) << 1;
            float2 f = *reinterpret_cast<const float2*>(src + (size_t)n * rs + k2);
            *reinterpret_cast<uint32_t*>(dst + n * 144 + k2 * 2) = cvt_hi(f.x, f.y);
        }
    } else if (b == 24) {
        unsigned char* dst = g_wbuf + WOFF_H1;
        for (int idx = threadIdx.x; idx < 64 * 64; idx += 256) {
            int n = idx >> 6, k2 = (idx & 63) << 1;
            float2 f = *reinterpret_cast<const float2*>(h1_w + (size_t)n * 128 + k2);
            *reinterpret_cast<uint32_t*>(dst + n * 272 + k2 * 2) = cvt_hi(f.x, f.y);
        }
    } else {
        unsigned char* dst = g_wbuf + WOFF_EMB;
        for (int idx = threadIdx.x; idx < 64 * 128; idx += 256) {
            int n = idx >> 7, k2 = (idx & 127) << 1;
            float2 f = (k2 < 128)
                     ? *reinterpret_cast<const float2*>(upw + (size_t)n * 128 + k2)
                     : *reinterpret_cast<const float2*>(ipw + (size_t)n * 128 + (k2 - 128));
            *reinterpret_cast<uint32_t*>(dst + n * 528 + k2 * 2) = cvt_hi(f.x, f.y);
        }
    }
}

// =====================================================================================
// Kernel 2 (main): 128 threads / 32 samples / 4 warps; 2 CTAs per SM (cross-CTA overlap).
// warp w (0..3), thread qr owns SAMPLE sl=8w+qr; both tokens in-thread.
// smem: XT head tile [32][272B] @0 | WB ring 2x33792 @8704  total 76288 (x2 CTAs = 149KB)
// phases: p0 embed, p1..p12 transformer, p13 head.
// =====================================================================================
#define XT_OFF 0u
#define WB_OFF 8704u
#define SLOT_SZ 33792u
#define MAIN_SMEM (8704u + 2u * SLOT_SZ)
#define MT 128

static __device__ __forceinline__ void stage_cp(uint32_t dst, const unsigned char* src,
                                                int bytes, int tid) {
    for (int o = tid * 16; o < bytes; o += MT * 16)
        CP16(dst + o, src + o);
}

static __device__ __forceinline__ void phase_src(int p, int& off, int& bytes) {
    if (p == 0)  { off = WOFF_EMB; bytes = 33792; return; }
    if (p == 13) { off = WOFF_H1;  bytes = 17408; return; }
    int l = (p - 1) / 6, k = (p - 1) % 6;
    int ch = l * 12 + (k == 0 ? 0 : (k == 1 ? 3 : 4 + 2 * (k - 2)));
    off = ch * CH_SZ;
    bytes = (k == 0 ? 3 * CH_SZ : (k == 1 ? CH_SZ : 2 * CH_SZ));
}

// register-only LayerNorm over one 64-wide row spread across 4 qc lanes
static __device__ __forceinline__ void ln_reg(float v[8][2], const float* g, const float* b, int qc) {
    float s = 0.f;
    #pragma unroll
    for (int j = 0; j < 8; ++j) s += v[j][0] + v[j][1];
    s += __shfl_xor_sync(0xffffffffu, s, 1);
    s += __shfl_xor_sync(0xffffffffu, s, 2);
    float m = s * (1.f / 64.f);
    float var = 0.f;
    #pragma unroll
    for (int j = 0; j < 8; ++j) {
        float d0 = v[j][0] - m, d1 = v[j][1] - m;
        var += d0 * d0 + d1 * d1;
    }
    var += __shfl_xor_sync(0xffffffffu, var, 1);
    var += __shfl_xor_sync(0xffffffffu, var, 2);
    float inv = rsqrtf(var * (1.f / 64.f) + 1e-5f);
    #pragma unroll
    for (int j = 0; j < 8; ++j) {
        int cc = 8 * j + 2 * qc;
        v[j][0] = (v[j][0] - m) * inv * __ldg(g + cc)     + __ldg(b + cc);
        v[j][1] = (v[j][1] - m) * inv * __ldg(g + cc + 1) + __ldg(b + cc + 1);
    }
}

__global__ void __launch_bounds__(MT, 2)
main_kernel(const int* __restrict__ user_idx, const int* __restrict__ item_idx,
            const float* __restrict__ user_features, const float* __restrict__ item_features,
            const float* __restrict__ user_table, const float* __restrict__ item_table,
            const float* __restrict__ upb, const float* __restrict__ ipb,
            const float* __restrict__ pe,
            const float* __restrict__ in_b, const float* __restrict__ out_b,
            const float* __restrict__ ln1_g, const float* __restrict__ ln1_b,
            const float* __restrict__ ff1_b, const float* __restrict__ ff2_b,
            const float* __restrict__ ln2_g, const float* __restrict__ ln2_b,
            const float* __restrict__ h1_b, const float* __restrict__ h2_w,
            const float* __restrict__ h2_b, float* __restrict__ out)
{
    extern __shared__ char sm[];
    const int tid = threadIdx.x, lane = tid & 31, w = tid >> 5;   // w: 0..3
    const int qr = lane >> 2, qc = lane & 3;
    const int sl = 8 * w + qr;                 // sample owned by this thread (0..31)
    const int s0m = blockIdx.x << 5;           // 32 samples per block
    const uint32_t xt_u = smem_u32(sm + XT_OFF);
    const uint32_t wb_u = smem_u32(sm + WB_OFF);
    const uint32_t slot[2] = { wb_u, wb_u + SLOT_SZ };

    // prefetch phase 0 (embed B image)
    stage_cp(slot[0], g_wbuf + WOFF_EMB, 33792, tid);
    CP_COMMIT();

    float x_[2][8][2];                 // [0]=user token, [1]=item token
    uint32_t fxh[4][4];
    float accF[8][4];
    uint32_t fch[4][4];

    for (int p = 0; p <= 13; ++p) {
        CP_WAIT0();
        __syncthreads();
        if (p < 13) {
            int off, by; phase_src(p + 1, off, by);
            stage_cp(slot[(p + 1) & 1], g_wbuf + off, by, tid);
            CP_COMMIT();
        }
        const uint32_t bb = slot[p & 1];

        if (p == 0) {
            // ======== embed ========
            float acc[8][4];
            #pragma unroll
            for (int j = 0; j < 8; ++j) { acc[j][0] = acc[j][1] = acc[j][2] = acc[j][3] = 0.f; }
            gemm1_emb(acc, user_features + (size_t)(s0m + sl) * 128,
                           item_features + (size_t)(s0m + sl) * 128, bb, qc);
            int uidx = __ldg(user_idx + s0m + sl);
            int iidx = __ldg(item_idx + s0m + sl);
            const float* ut = user_table + (size_t)uidx * 64;
            const float* it = item_table + (size_t)iidx * 64;
            #pragma unroll
            for (int j = 0; j < 8; ++j) {
                int c = 8 * j + 2 * qc;
                x_[0][j][0] = acc[j][0] + __ldg(upb + c)     + __ldg(ut + c)     + __ldg(pe + c);
                x_[0][j][1] = acc[j][1] + __ldg(upb + c + 1) + __ldg(ut + c + 1) + __ldg(pe + c + 1);
                x_[1][j][0] = acc[j][2] + __ldg(ipb + c)     + __ldg(it + c)     + __ldg(pe + 64 + c);
                x_[1][j][1] = acc[j][3] + __ldg(ipb + c + 1) + __ldg(it + c + 1) + __ldg(pe + 64 + c + 1);
            }
            build_fr(x_, fxh);
        } else if (p == 13) {
            // ======== head: 32 samples -> warps 0,1 (16 rows each) ========
            if (w < 2) {
                float acc[8][4];
                #pragma unroll
                for (int j = 0; j < 8; ++j) { acc[j][0] = acc[j][1] = acc[j][2] = acc[j][3] = 0.f; }
                gemm1t<8, 272, 272>(acc, xt_u + (uint32_t)(16 * w) * 272u, bb);
                float pA = 0.f, pB = 0.f;
                #pragma unroll
                for (int j = 0; j < 8; ++j) {
                    int c = 8 * j + 2 * qc;
                    float b0 = __ldg(h1_b + c), b1 = __ldg(h1_b + c + 1);
                    float w0 = __ldg(h2_w + c), w1 = __ldg(h2_w + c + 1);
                    pA += fmaxf(acc[j][0] + b0, 0.f) * w0 + fmaxf(acc[j][1] + b1, 0.f) * w1;
                    pB += fmaxf(acc[j][2] + b0, 0.f) * w0 + fmaxf(acc[j][3] + b1, 0.f) * w1;
                }
                pA += __shfl_xor_sync(0xffffffffu, pA, 1);
                pA += __shfl_xor_sync(0xffffffffu, pA, 2);
                pB += __shfl_xor_sync(0xffffffffu, pB, 1);
                pB += __shfl_xor_sync(0xffffffffu, pB, 2);
                if (qc == 0) {
                    float hb = __ldg(h2_b);
                    out[s0m + 16 * w + qr]     = pA + hb;
                    out[s0m + 16 * w + qr + 8] = pB + hb;
                }
            }
        } else {
            const int l = (p - 1) / 6, k = (p - 1) % 6;
            if (k == 0) {
                // ======== qkv + attention (partner token in-thread) ========
                float q_[8][4];
                #pragma unroll
                for (int j = 0; j < 8; ++j) { q_[j][0] = q_[j][1] = q_[j][2] = q_[j][3] = 0.f; }
                gemm1r4<4, 144>(q_, fxh, bb);
                const float* bq = in_b + l * 192;
                #pragma unroll
                for (int j = 0; j < 8; ++j) {
                    int c = 8 * j + 2 * qc;
                    float b0 = __ldg(bq + c), b1 = __ldg(bq + c + 1);
                    q_[j][0] += b0; q_[j][1] += b1; q_[j][2] += b0; q_[j][3] += b1;
                }
                float t_[8][4];
                #pragma unroll
                for (int j = 0; j < 8; ++j) { t_[j][0] = t_[j][1] = t_[j][2] = t_[j][3] = 0.f; }
                gemm1r4<4, 144>(t_, fxh, bb + (uint32_t)CH_SZ);
                const float* bk = in_b + l * 192 + 64;
                #pragma unroll
                for (int j = 0; j < 8; ++j) {
                    int c = 8 * j + 2 * qc;
                    float b0 = __ldg(bk + c), b1 = __ldg(bk + c + 1);
                    t_[j][0] += b0; t_[j][1] += b1; t_[j][2] += b0; t_[j][3] += b1;
                }
                float wUU[4], wUI[4], wIU[4], wII[4];
                {
                    float sUU[4], sUI[4], sIU[4], sII[4];
                    #pragma unroll
                    for (int h = 0; h < 4; ++h) {
                        int j0 = 2 * h, j1 = 2 * h + 1;
                        sUU[h] = q_[j0][0] * t_[j0][0] + q_[j0][1] * t_[j0][1]
                               + q_[j1][0] * t_[j1][0] + q_[j1][1] * t_[j1][1];
                        sUI[h] = q_[j0][0] * t_[j0][2] + q_[j0][1] * t_[j0][3]
                               + q_[j1][0] * t_[j1][2] + q_[j1][1] * t_[j1][3];
                        sIU[h] = q_[j0][2] * t_[j0][0] + q_[j0][3] * t_[j0][1]
                               + q_[j1][2] * t_[j1][0] + q_[j1][3] * t_[j1][1];
                        sII[h] = q_[j0][2] * t_[j0][2] + q_[j0][3] * t_[j0][3]
                               + q_[j1][2] * t_[j1][2] + q_[j1][3] * t_[j1][3];
                    }
                    #pragma unroll
                    for (int h = 0; h < 4; ++h) {
                        sUU[h] += __shfl_xor_sync(0xffffffffu, sUU[h], 1);
                        sUU[h] += __shfl_xor_sync(0xffffffffu, sUU[h], 2);
                        sUI[h] += __shfl_xor_sync(0xffffffffu, sUI[h], 1);
                        sUI[h] += __shfl_xor_sync(0xffffffffu, sUI[h], 2);
                        sIU[h] += __shfl_xor_sync(0xffffffffu, sIU[h], 1);
                        sIU[h] += __shfl_xor_sync(0xffffffffu, sIU[h], 2);
                        sII[h] += __shfl_xor_sync(0xffffffffu, sII[h], 1);
                        sII[h] += __shfl_xor_sync(0xffffffffu, sII[h], 2);
                        float a = sUU[h] * 0.25f, o = sUI[h] * 0.25f;
                        float m = fmaxf(a, o);
                        float ea = __expf(a - m), eo = __expf(o - m);
                        float inv = __fdividef(1.f, ea + eo);
                        wUU[h] = ea * inv; wUI[h] = eo * inv;
                        a = sIU[h] * 0.25f; o = sII[h] * 0.25f;
                        m = fmaxf(a, o);
                        ea = __expf(a - m); eo = __expf(o - m);
                        inv = __fdividef(1.f, ea + eo);
                        wIU[h] = ea * inv; wII[h] = eo * inv;
                    }
                }
                // v (reuse t_)
                #pragma unroll
                for (int j = 0; j < 8; ++j) { t_[j][0] = t_[j][1] = t_[j][2] = t_[j][3] = 0.f; }
                gemm1r4<4, 144>(t_, fxh, bb + 2u * CH_SZ);
                const float* bv = in_b + l * 192 + 128;
                #pragma unroll
                for (int j = 0; j < 8; ++j) {
                    int c = 8 * j + 2 * qc;
                    float b0 = __ldg(bv + c), b1 = __ldg(bv + c + 1);
                    t_[j][0] += b0; t_[j][1] += b1; t_[j][2] += b0; t_[j][3] += b1;
                }
                #pragma unroll
                for (int j = 0; j < 8; ++j) {
                    int h = j >> 1;
                    float c00 = wUU[h] * t_[j][0] + wUI[h] * t_[j][2];
                    float c01 = wUU[h] * t_[j][1] + wUI[h] * t_[j][3];
                    float c10 = wIU[h] * t_[j][0] + wII[h] * t_[j][2];
                    float c11 = wIU[h] * t_[j][1] + wII[h] * t_[j][3];
                    int kc = j >> 1, jh = j & 1;
                    fch[kc][(jh << 1) | 0] = cvt_hi(c00, c01);
                    fch[kc][(jh << 1) | 1] = cvt_hi(c10, c11);
                }
            } else if (k == 1) {
                // ======== out-proj + residual + LN1 ========
                float acc[8][4];
                #pragma unroll
                for (int j = 0; j < 8; ++j) { acc[j][0] = acc[j][1] = acc[j][2] = acc[j][3] = 0.f; }
                gemm1r4<4, 144>(acc, fch, bb);
                const float* bo = out_b + l * 64;
                #pragma unroll
                for (int j = 0; j < 8; ++j) {
                    int c = 8 * j + 2 * qc;
                    float b0 = __ldg(bo + c), b1 = __ldg(bo + c + 1);
                    x_[0][j][0] += acc[j][0] + b0; x_[0][j][1] += acc[j][1] + b1;
                    x_[1][j][0] += acc[j][2] + b0; x_[1][j][1] += acc[j][3] + b1;
                }
                ln_reg(x_[0], ln1_g + l * 64, ln1_b + l * 64, qc);
                ln_reg(x_[1], ln1_g + l * 64, ln1_b + l * 64, qc);
                build_fr(x_, fxh);
            } else {
                // ======== ff pair ========
                int c4 = k - 2;
                float acc[8][4];
                #pragma unroll
                for (int j = 0; j < 8; ++j) { acc[j][0] = acc[j][1] = acc[j][2] = acc[j][3] = 0.f; }
                gemm1r4<4, 144>(acc, fxh, bb);
                const float* b1p = ff1_b + l * 256 + 64 * c4;
                #pragma unroll
                for (int j = 0; j < 8; ++j) {
                    int c = 8 * j + 2 * qc;
                    float b0 = __ldg(b1p + c), b1 = __ldg(b1p + c + 1);
                    float h00 = fmaxf(acc[j][0] + b0, 0.f), h01 = fmaxf(acc[j][1] + b1, 0.f);
                    float h10 = fmaxf(acc[j][2] + b0, 0.f), h11 = fmaxf(acc[j][3] + b1, 0.f);
                    int kc = j >> 1, jh = j & 1;
                    fch[kc][(jh << 1) | 0] = cvt_hi(h00, h01);
                    fch[kc][(jh << 1) | 1] = cvt_hi(h10, h11);
                }
                if (c4 == 0) {
                    #pragma unroll
                    for (int j = 0; j < 8; ++j) { accF[j][0] = accF[j][1] = accF[j][2] = accF[j][3] = 0.f; }
                }
                gemm1r4<4, 144>(accF, fch, bb + (uint32_t)CH_SZ);
                if (c4 == 3) {
                    const float* b2 = ff2_b + l * 64;
                    #pragma unroll
                    for (int j = 0; j < 8; ++j) {
                        int c = 8 * j + 2 * qc;
                        float b0 = __ldg(b2 + c), b1 = __ldg(b2 + c + 1);
                        x_[0][j][0] += accF[j][0] + b0; x_[0][j][1] += accF[j][1] + b1;
                        x_[1][j][0] += accF[j][2] + b0; x_[1][j][1] += accF[j][3] + b1;
                    }
                    ln_reg(x_[0], ln2_g + l * 64, ln2_b + l * 64, qc);
                    ln_reg(x_[1], ln2_g + l * 64, ln2_b + l * 64, qc);
                    if (l == 0) {
                        build_fr(x_, fxh);
                    } else {
                        // head A tile: row = sample; user cols 0:64, item cols 64:128
                        #pragma unroll
                        for (int j = 0; j < 8; ++j) {
                            int c = 8 * j + 2 * qc;
                            st_hi(sm, XT_OFF, 136, sl, c,      x_[0][j][0], x_[0][j][1]);
                            st_hi(sm, XT_OFF, 136, sl, 64 + c, x_[1][j][0], x_[1][j][1]);
                        }
                    }
                }
            }
        }
    }
}

// =====================================================================================
extern "C" void kernel_launch(void* const* d_in, const int* in_sizes, int n_in,
                              void* d_out, int out_size)
{
    const int*   user_idx      = (const int*)  d_in[0];
    const int*   item_idx      = (const int*)  d_in[1];
    const float* user_features = (const float*)d_in[2];
    const float* item_features = (const float*)d_in[3];
    const float* user_table    = (const float*)d_in[4];
    const float* item_table    = (const float*)d_in[5];
    const float* upw           = (const float*)d_in[6];
    const float* upb           = (const float*)d_in[7];
    const float* ipw           = (const float*)d_in[8];
    const float* ipb           = (const float*)d_in[9];
    const float* pe            = (const float*)d_in[10];
    const float* in_w          = (const float*)d_in[11];
    const float* in_b          = (const float*)d_in[12];
    const float* out_w         = (const float*)d_in[13];
    const float* out_b         = (const float*)d_in[14];
    const float* ln1_g         = (const float*)d_in[15];
    const float* ln1_b         = (const float*)d_in[16];
    const float* ff1_w         = (const float*)d_in[17];
    const float* ff1_b         = (const float*)d_in[18];
    const float* ff2_w         = (const float*)d_in[19];
    const float* ff2_b         = (const float*)d_in[20];
    const float* ln2_g         = (const float*)d_in[21];
    const float* ln2_b         = (const float*)d_in[22];
    const float* h1_w          = (const float*)d_in[23];
    const float* h1_b          = (const float*)d_in[24];
    const float* h2_w          = (const float*)d_in[25];
    const float* h2_b          = (const float*)d_in[26];
    float* out = (float*)d_out;

    const int B = in_sizes[0];

    static bool attr_set = false;
    if (!attr_set) {
        cudaFuncSetAttribute(main_kernel, cudaFuncAttributeMaxDynamicSharedMemorySize, MAIN_SMEM);
        attr_set = true;
    }

    conv_w_kernel<<<26, 256>>>(in_w, out_w, ff1_w, ff2_w, h1_w, upw, ipw);
    main_kernel<<<B / 32, MT, MAIN_SMEM>>>(user_idx, item_idx, user_features, item_features,
                                           user_table, item_table, upb, ipb, pe,
                                           in_b, out_b, ln1_g, ln1_b, ff1_b, ff2_b,
                                           ln2_g, ln2_b, h1_b, h2_w, h2_b, out);
}

// round 16
// speedup vs baseline: 1.9243x; 1.0063x over previous
#include <cuda_runtime.h>
#include <cuda_fp16.h>
#include <cstdint>

// ---------------- persistent device scratch (no runtime allocation) ----------------
// 24 x 9216 K-chunk hi-images | h1 image 17408 | embed B image [upw|ipw] 33792
#define CH_SZ    9216
#define WOFF_H1  (24 * CH_SZ)
#define WOFF_EMB (WOFF_H1 + 17408)
__device__ __align__(16) unsigned char  g_wbuf[WOFF_EMB + 33792];

// ---------------- common helpers ----------------
static __device__ __forceinline__ uint32_t smem_u32(const void* p) {
    uint32_t a;
    asm("{ .reg .u64 t; cvta.to.shared.u64 t, %1; cvt.u32.u64 %0, t; }" : "=r"(a) : "l"(p));
    return a;
}
static __device__ __forceinline__ void ldmA(uint32_t a[4], uint32_t addr) {
    asm volatile("ldmatrix.sync.aligned.m8n8.x4.shared.b16 {%0,%1,%2,%3}, [%4];"
                 : "=r"(a[0]), "=r"(a[1]), "=r"(a[2]), "=r"(a[3]) : "r"(addr));
}
static __device__ __forceinline__ void ldmB4(uint32_t b[4], uint32_t addr) {
    asm volatile("ldmatrix.sync.aligned.m8n8.x4.shared.b16 {%0,%1,%2,%3}, [%4];"
                 : "=r"(b[0]), "=r"(b[1]), "=r"(b[2]), "=r"(b[3]) : "r"(addr));
}
static __device__ __forceinline__ void mma16816(float d[4], const uint32_t a[4], const uint32_t b[2]) {
    asm volatile("mma.sync.aligned.m16n8k16.row.col.f32.f16.f16.f32 "
                 "{%0,%1,%2,%3}, {%4,%5,%6,%7}, {%8,%9}, {%0,%1,%2,%3};"
                 : "+f"(d[0]), "+f"(d[1]), "+f"(d[2]), "+f"(d[3])
                 : "r"(a[0]), "r"(a[1]), "r"(a[2]), "r"(a[3]), "r"(b[0]), "r"(b[1]));
}

// fp32 pair -> packed fp16
static __device__ __forceinline__ uint32_t cvt_hi(float v0, float v1) {
    __half2 hb = __floats2half2_rn(v0, v1);
    return *reinterpret_cast<uint32_t*>(&hb);
}

// 1-term fp16 gemm, register A, B hi tile [64 rows][BSTR bytes].
// Software-pipelined B loads: next k-chunk's 4 LDSMs issue before current chunk's MMAs.
template<int NKC, int BSTR>
static __device__ __forceinline__ void gemm1r4(float (*acc)[4],
        const uint32_t (*fh)[4], uint32_t bBase) {
    const int lane = threadIdx.x & 31;
    uint32_t bAddr = bBase + (lane & 7) * BSTR + (((lane >> 3) & 1) << 4)
                   + ((lane >> 4) & 1) * 8 * BSTR;
    uint32_t bh[2][4][4];
    #pragma unroll
    for (int jp = 0; jp < 4; ++jp)
        ldmB4(bh[0][jp], bAddr + jp * 16 * BSTR);
    #pragma unroll
    for (int kc = 0; kc < NKC; ++kc) {
        if (kc + 1 < NKC) {
            #pragma unroll
            for (int jp = 0; jp < 4; ++jp)
                ldmB4(bh[(kc + 1) & 1][jp], bAddr + jp * 16 * BSTR + (kc + 1) * 32);
        }
        #pragma unroll
        for (int jp = 0; jp < 4; ++jp) {
            mma16816(acc[2 * jp],     fh[kc], &bh[kc & 1][jp][0]);
            mma16816(acc[2 * jp + 1], fh[kc], &bh[kc & 1][jp][2]);
        }
    }
}

// 1-term gemm, tile A (hi only, [rows][ASTR bytes]) x B hi ([64][BSTR]) — head.
// Same double-buffered B pipeline.
template<int NKC, int ASTR, int BSTR>
static __device__ void gemm1t(float (*acc)[4], uint32_t aBase, uint32_t bBase) {
    const int lane = threadIdx.x & 31;
    uint32_t aAddr = aBase + (lane & 15) * ASTR + ((lane >> 4) << 4);
    uint32_t bAddr = bBase + (lane & 7) * BSTR + (((lane >> 3) & 1) << 4)
                   + ((lane >> 4) & 1) * 8 * BSTR;
    uint32_t bh[2][4][4];
    #pragma unroll
    for (int jp = 0; jp < 4; ++jp)
        ldmB4(bh[0][jp], bAddr + jp * 16 * BSTR);
    #pragma unroll
    for (int kc = 0; kc < NKC; ++kc) {
        uint32_t ah[4];
        ldmA(ah, aAddr + kc * 32);
        if (kc + 1 < NKC) {
            #pragma unroll
            for (int jp = 0; jp < 4; ++jp)
                ldmB4(bh[(kc + 1) & 1][jp], bAddr + jp * 16 * BSTR + (kc + 1) * 32);
        }
        #pragma unroll
        for (int jp = 0; jp < 4; ++jp) {
            mma16816(acc[2 * jp],     ah, &bh[kc & 1][jp][0]);
            mma16816(acc[2 * jp + 1], ah, &bh[kc & 1][jp][2]);
        }
    }
}

// build m16n8k16 A fragments (hi only) from register values v[rowhalf][j][2]
static __device__ __forceinline__ void build_fr(const float v[2][8][2], uint32_t fh[4][4]) {
    #pragma unroll
    for (int kc = 0; kc < 4; ++kc)
        #pragma unroll
        for (int m = 0; m < 4; ++m) {
            int h = m & 1, j = 2 * kc + (m >> 1);
            fh[kc][m] = cvt_hi(v[h][j][0], v[h][j][1]);
        }
}

// fp16 pair store into tile [r][strideElems]
static __device__ __forceinline__ void st_hi(char* sm, uint32_t off, int strideElems,
                                             int r, int c, float f0, float f1) {
    __half* row = (__half*)(sm + off) + (size_t)r * strideElems;
    *reinterpret_cast<uint32_t*>(row + c) = cvt_hi(f0, f1);
}

// embed gemm: A rows 0-7 = user feats (K cols 0:128), rows 8-15 = item feats (128:256).
// B hi image [64][528B]. 1-term; fragments built on the fly, B pipelined.
static __device__ void gemm1_emb(float (*acc)[4], const float* __restrict__ fpU,
                                 const float* __restrict__ fpI, uint32_t bBase, int qc) {
    const int lane = threadIdx.x & 31;
    uint32_t bAddr = bBase + (lane & 7) * 528 + (((lane >> 3) & 1) << 4)
                   + ((lane >> 4) & 1) * 8 * 528;
    uint32_t bh[2][4][4];
    #pragma unroll
    for (int jp = 0; jp < 4; ++jp)
        ldmB4(bh[0][jp], bAddr + jp * 16 * 528);
    #pragma unroll
    for (int kc = 0; kc < 16; ++kc) {
        uint32_t ah[4] = {0u, 0u, 0u, 0u};
        if (kc < 8) {
            int col = 16 * kc + 2 * qc;
            float2 f0 = __ldg(reinterpret_cast<const float2*>(fpU + col));
            float2 f1 = __ldg(reinterpret_cast<const float2*>(fpU + col + 8));
            ah[0] = cvt_hi(f0.x, f0.y);
            ah[2] = cvt_hi(f1.x, f1.y);
        } else {
            int col = 16 * (kc - 8) + 2 * qc;
            float2 f0 = __ldg(reinterpret_cast<const float2*>(fpI + col));
            float2 f1 = __ldg(reinterpret_cast<const float2*>(fpI + col + 8));
            ah[1] = cvt_hi(f0.x, f0.y);
            ah[3] = cvt_hi(f1.x, f1.y);
        }
        if (kc + 1 < 16) {
            #pragma unroll
            for (int jp = 0; jp < 4; ++jp)
                ldmB4(bh[(kc + 1) & 1][jp], bAddr + jp * 16 * 528 + (kc + 1) * 32);
        }
        #pragma unroll
        for (int jp = 0; jp < 4; ++jp) {
            mma16816(acc[2 * jp],     ah, &bh[kc & 1][jp][0]);
            mma16816(acc[2 * jp + 1], ah, &bh[kc & 1][jp][2]);
        }
    }
}

// ---------------- cp.async ----------------
#define CP16(dst, src) asm volatile("cp.async.cg.shared.global [%0], [%1], 16;" \
                                    :: "r"(dst), "l"(src) : "memory")
#define CP_COMMIT() asm volatile("cp.async.commit_group;" ::: "memory")
#define CP_WAIT0()  asm volatile("cp.async.wait_group 0;" ::: "memory")

// =====================================================================================
// Kernel 1: convert all weights to fp16 HI-ONLY tile images (26 blocks)
// =====================================================================================
__global__ void conv_w_kernel(const float* __restrict__ in_w, const float* __restrict__ out_w,
                              const float* __restrict__ ff1_w, const float* __restrict__ ff2_w,
                              const float* __restrict__ h1_w, const float* __restrict__ upw,
                              const float* __restrict__ ipw)
{
    int b = blockIdx.x;
    if (b < 24) {
        int l = b / 12, c = b % 12;
        const float* src; int rs;
        if (c < 3)       { src = in_w  + ((size_t)l * 192 + 64 * c) * 64; rs = 64; }
        else if (c == 3) { src = out_w + (size_t)l * 4096;                rs = 64; }
        else {
            int cc = (c - 4) >> 1;
            if (((c - 4) & 1) == 0) { src = ff1_w + ((size_t)l * 256 + 64 * cc) * 64; rs = 64;  }
            else                    { src = ff2_w + (size_t)l * 16384 + 64 * cc;      rs = 256; }
        }
        unsigned char* dst = g_wbuf + (size_t)b * CH_SZ;
        for (int idx = threadIdx.x; idx < 64 * 32; idx += 256) {
            int n = idx >> 5, k2 = (idx & 31) << 1;
            float2 f = *reinterpret_cast<const float2*>(src + (size_t)n * rs + k2);
            *reinterpret_cast<uint32_t*>(dst + n * 144 + k2 * 2) = cvt_hi(f.x, f.y);
        }
    } else if (b == 24) {
        unsigned char* dst = g_wbuf + WOFF_H1;
        for (int idx = threadIdx.x; idx < 64 * 64; idx += 256) {
            int n = idx >> 6, k2 = (idx & 63) << 1;
            float2 f = *reinterpret_cast<const float2*>(h1_w + (size_t)n * 128 + k2);
            *reinterpret_cast<uint32_t*>(dst + n * 272 + k2 * 2) = cvt_hi(f.x, f.y);
        }
    } else {
        unsigned char* dst = g_wbuf + WOFF_EMB;
        for (int idx = threadIdx.x; idx < 64 * 128; idx += 256) {
            int n = idx >> 7, k2 = (idx & 127) << 1;
            float2 f = (k2 < 128)
                     ? *reinterpret_cast<const float2*>(upw + (size_t)n * 128 + k2)
                     : *reinterpret_cast<const float2*>(ipw + (size_t)n * 128 + (k2 - 128));
            *reinterpret_cast<uint32_t*>(dst + n * 528 + k2 * 2) = cvt_hi(f.x, f.y);
        }
    }
}

// =====================================================================================
// Kernel 2 (main): 128 threads / 32 samples / 4 warps; 2 CTAs per SM.
// warp w (0..3), thread qr owns SAMPLE sl=8w+qr; both tokens in-thread.
// smem: XT head tile [32][272B] @0 | WB ring 2x33792 @8704  total 76288
// phases: p0 embed, p1..p12 transformer, p13 head.
// =====================================================================================
#define XT_OFF 0u
#define WB_OFF 8704u
#define SLOT_SZ 33792u
#define MAIN_SMEM (8704u + 2u * SLOT_SZ)
#define MT 128

static __device__ __forceinline__ void stage_cp(uint32_t dst, const unsigned char* src,
                                                int bytes, int tid) {
    for (int o = tid * 16; o < bytes; o += MT * 16)
        CP16(dst + o, src + o);
}

static __device__ __forceinline__ void phase_src(int p, int& off, int& bytes) {
    if (p == 0)  { off = WOFF_EMB; bytes = 33792; return; }
    if (p == 13) { off = WOFF_H1;  bytes = 17408; return; }
    int l = (p - 1) / 6, k = (p - 1) % 6;
    int ch = l * 12 + (k == 0 ? 0 : (k == 1 ? 3 : 4 + 2 * (k - 2)));
    off = ch * CH_SZ;
    bytes = (k == 0 ? 3 * CH_SZ : (k == 1 ? CH_SZ : 2 * CH_SZ));
}

// register-only LayerNorm over one 64-wide row spread across 4 qc lanes
static __device__ __forceinline__ void ln_reg(float v[8][2], const float* g, const float* b, int qc) {
    float s = 0.f;
    #pragma unroll
    for (int j = 0; j < 8; ++j) s += v[j][0] + v[j][1];
    s += __shfl_xor_sync(0xffffffffu, s, 1);
    s += __shfl_xor_sync(0xffffffffu, s, 2);
    float m = s * (1.f / 64.f);
    float var = 0.f;
    #pragma unroll
    for (int j = 0; j < 8; ++j) {
        float d0 = v[j][0] - m, d1 = v[j][1] - m;
        var += d0 * d0 + d1 * d1;
    }
    var += __shfl_xor_sync(0xffffffffu, var, 1);
    var += __shfl_xor_sync(0xffffffffu, var, 2);
    float inv = rsqrtf(var * (1.f / 64.f) + 1e-5f);
    #pragma unroll
    for (int j = 0; j < 8; ++j) {
        int cc = 8 * j + 2 * qc;
        v[j][0] = (v[j][0] - m) * inv * __ldg(g + cc)     + __ldg(b + cc);
        v[j][1] = (v[j][1] - m) * inv * __ldg(g + cc + 1) + __ldg(b + cc + 1);
    }
}

__global__ void __launch_bounds__(MT, 2)
main_kernel(const int* __restrict__ user_idx, const int* __restrict__ item_idx,
            const float* __restrict__ user_features, const float* __restrict__ item_features,
            const float* __restrict__ user_table, const float* __restrict__ item_table,
            const float* __restrict__ upb, const float* __restrict__ ipb,
            const float* __restrict__ pe,
            const float* __restrict__ in_b, const float* __restrict__ out_b,
            const float* __restrict__ ln1_g, const float* __restrict__ ln1_b,
            const float* __restrict__ ff1_b, const float* __restrict__ ff2_b,
            const float* __restrict__ ln2_g, const float* __restrict__ ln2_b,
            const float* __restrict__ h1_b, const float* __restrict__ h2_w,
            const float* __restrict__ h2_b, float* __restrict__ out)
{
    extern __shared__ char sm[];
    const int tid = threadIdx.x, lane = tid & 31, w = tid >> 5;   // w: 0..3
    const int qr = lane >> 2, qc = lane & 3;
    const int sl = 8 * w + qr;                 // sample owned by this thread (0..31)
    const int s0m = blockIdx.x << 5;           // 32 samples per block
    const uint32_t xt_u = smem_u32(sm + XT_OFF);
    const uint32_t wb_u = smem_u32(sm + WB_OFF);
    const uint32_t slot[2] = { wb_u, wb_u + SLOT_SZ };

    // prefetch phase 0 (embed B image)
    stage_cp(slot[0], g_wbuf + WOFF_EMB, 33792, tid);
    CP_COMMIT();

    float x_[2][8][2];                 // [0]=user token, [1]=item token
    uint32_t fxh[4][4];
    float accF[8][4];
    uint32_t fch[4][4];

    for (int p = 0; p <= 13; ++p) {
        CP_WAIT0();
        __syncthreads();
        if (p < 13) {
            int off, by; phase_src(p + 1, off, by);
            stage_cp(slot[(p + 1) & 1], g_wbuf + off, by, tid);
            CP_COMMIT();
        }
        const uint32_t bb = slot[p & 1];

        if (p == 0) {
            // ======== embed ========
            float acc[8][4];
            #pragma unroll
            for (int j = 0; j < 8; ++j) { acc[j][0] = acc[j][1] = acc[j][2] = acc[j][3] = 0.f; }
            gemm1_emb(acc, user_features + (size_t)(s0m + sl) * 128,
                           item_features + (size_t)(s0m + sl) * 128, bb, qc);
            int uidx = __ldg(user_idx + s0m + sl);
            int iidx = __ldg(item_idx + s0m + sl);
            const float* ut = user_table + (size_t)uidx * 64;
            const float* it = item_table + (size_t)iidx * 64;
            #pragma unroll
            for (int j = 0; j < 8; ++j) {
                int c = 8 * j + 2 * qc;
                x_[0][j][0] = acc[j][0] + __ldg(upb + c)     + __ldg(ut + c)     + __ldg(pe + c);
                x_[0][j][1] = acc[j][1] + __ldg(upb + c + 1) + __ldg(ut + c + 1) + __ldg(pe + c + 1);
                x_[1][j][0] = acc[j][2] + __ldg(ipb + c)     + __ldg(it + c)     + __ldg(pe + 64 + c);
                x_[1][j][1] = acc[j][3] + __ldg(ipb + c + 1) + __ldg(it + c + 1) + __ldg(pe + 64 + c + 1);
            }
            build_fr(x_, fxh);
        } else if (p == 13) {
            // ======== head: 32 samples -> warps 0,1 (16 rows each) ========
            if (w < 2) {
                float acc[8][4];
                #pragma unroll
                for (int j = 0; j < 8; ++j) { acc[j][0] = acc[j][1] = acc[j][2] = acc[j][3] = 0.f; }
                gemm1t<8, 272, 272>(acc, xt_u + (uint32_t)(16 * w) * 272u, bb);
                float pA = 0.f, pB = 0.f;
                #pragma unroll
                for (int j = 0; j < 8; ++j) {
                    int c = 8 * j + 2 * qc;
                    float b0 = __ldg(h1_b + c), b1 = __ldg(h1_b + c + 1);
                    float w0 = __ldg(h2_w + c), w1 = __ldg(h2_w + c + 1);
                    pA += fmaxf(acc[j][0] + b0, 0.f) * w0 + fmaxf(acc[j][1] + b1, 0.f) * w1;
                    pB += fmaxf(acc[j][2] + b0, 0.f) * w0 + fmaxf(acc[j][3] + b1, 0.f) * w1;
                }
                pA += __shfl_xor_sync(0xffffffffu, pA, 1);
                pA += __shfl_xor_sync(0xffffffffu, pA, 2);
                pB += __shfl_xor_sync(0xffffffffu, pB, 1);
                pB += __shfl_xor_sync(0xffffffffu, pB, 2);
                if (qc == 0) {
                    float hb = __ldg(h2_b);
                    out[s0m + 16 * w + qr]     = pA + hb;
                    out[s0m + 16 * w + qr + 8] = pB + hb;
                }
            }
        } else {
            const int l = (p - 1) / 6, k = (p - 1) % 6;
            if (k == 0) {
                // ======== qkv + attention (partner token in-thread) ========
                float q_[8][4];
                #pragma unroll
                for (int j = 0; j < 8; ++j) { q_[j][0] = q_[j][1] = q_[j][2] = q_[j][3] = 0.f; }
                gemm1r4<4, 144>(q_, fxh, bb);
                const float* bq = in_b + l * 192;
                #pragma unroll
                for (int j = 0; j < 8; ++j) {
                    int c = 8 * j + 2 * qc;
                    float b0 = __ldg(bq + c), b1 = __ldg(bq + c + 1);
                    q_[j][0] += b0; q_[j][1] += b1; q_[j][2] += b0; q_[j][3] += b1;
                }
                float t_[8][4];
                #pragma unroll
                for (int j = 0; j < 8; ++j) { t_[j][0] = t_[j][1] = t_[j][2] = t_[j][3] = 0.f; }
                gemm1r4<4, 144>(t_, fxh, bb + (uint32_t)CH_SZ);
                const float* bk = in_b + l * 192 + 64;
                #pragma unroll
                for (int j = 0; j < 8; ++j) {
                    int c = 8 * j + 2 * qc;
                    float b0 = __ldg(bk + c), b1 = __ldg(bk + c + 1);
                    t_[j][0] += b0; t_[j][1] += b1; t_[j][2] += b0; t_[j][3] += b1;
                }
                float wUU[4], wUI[4], wIU[4], wII[4];
                {
                    float sUU[4], sUI[4], sIU[4], sII[4];
                    #pragma unroll
                    for (int h = 0; h < 4; ++h) {
                        int j0 = 2 * h, j1 = 2 * h + 1;
                        sUU[h] = q_[j0][0] * t_[j0][0] + q_[j0][1] * t_[j0][1]
                               + q_[j1][0] * t_[j1][0] + q_[j1][1] * t_[j1][1];
                        sUI[h] = q_[j0][0] * t_[j0][2] + q_[j0][1] * t_[j0][3]
                               + q_[j1][0] * t_[j1][2] + q_[j1][1] * t_[j1][3];
                        sIU[h] = q_[j0][2] * t_[j0][0] + q_[j0][3] * t_[j0][1]
                               + q_[j1][2] * t_[j1][0] + q_[j1][3] * t_[j1][1];
                        sII[h] = q_[j0][2] * t_[j0][2] + q_[j0][3] * t_[j0][3]
                               + q_[j1][2] * t_[j1][2] + q_[j1][3] * t_[j1][3];
                    }
                    #pragma unroll
                    for (int h = 0; h < 4; ++h) {
                        sUU[h] += __shfl_xor_sync(0xffffffffu, sUU[h], 1);
                        sUU[h] += __shfl_xor_sync(0xffffffffu, sUU[h], 2);
                        sUI[h] += __shfl_xor_sync(0xffffffffu, sUI[h], 1);
                        sUI[h] += __shfl_xor_sync(0xffffffffu, sUI[h], 2);
                        sIU[h] += __shfl_xor_sync(0xffffffffu, sIU[h], 1);
                        sIU[h] += __shfl_xor_sync(0xffffffffu, sIU[h], 2);
                        sII[h] += __shfl_xor_sync(0xffffffffu, sII[h], 1);
                        sII[h] += __shfl_xor_sync(0xffffffffu, sII[h], 2);
                        float a = sUU[h] * 0.25f, o = sUI[h] * 0.25f;
                        float m = fmaxf(a, o);
                        float ea = __expf(a - m), eo = __expf(o - m);
                        float inv = __fdividef(1.f, ea + eo);
                        wUU[h] = ea * inv; wUI[h] = eo * inv;
                        a = sIU[h] * 0.25f; o = sII[h] * 0.25f;
                        m = fmaxf(a, o);
                        ea = __expf(a - m); eo = __expf(o - m);
                        inv = __fdividef(1.f, ea + eo);
                        wIU[h] = ea * inv; wII[h] = eo * inv;
                    }
                }
                // v (reuse t_)
                #pragma unroll
                for (int j = 0; j < 8; ++j) { t_[j][0] = t_[j][1] = t_[j][2] = t_[j][3] = 0.f; }
                gemm1r4<4, 144>(t_, fxh, bb + 2u * CH_SZ);
                const float* bv = in_b + l * 192 + 128;
                #pragma unroll
                for (int j = 0; j < 8; ++j) {
                    int c = 8 * j + 2 * qc;
                    float b0 = __ldg(bv + c), b1 = __ldg(bv + c + 1);
                    t_[j][0] += b0; t_[j][1] += b1; t_[j][2] += b0; t_[j][3] += b1;
                }
                #pragma unroll
                for (int j = 0; j < 8; ++j) {
                    int h = j >> 1;
                    float c00 = wUU[h] * t_[j][0] + wUI[h] * t_[j][2];
                    float c01 = wUU[h] * t_[j][1] + wUI[h] * t_[j][3];
                    float c10 = wIU[h] * t_[j][0] + wII[h] * t_[j][2];
                    float c11 = wIU[h] * t_[j][1] + wII[h] * t_[j][3];
                    int kc = j >> 1, jh = j & 1;
                    fch[kc][(jh << 1) | 0] = cvt_hi(c00, c01);
                    fch[kc][(jh << 1) | 1] = cvt_hi(c10, c11);
                }
            } else if (k == 1) {
                // ======== out-proj + residual + LN1 ========
                float acc[8][4];
                #pragma unroll
                for (int j = 0; j < 8; ++j) { acc[j][0] = acc[j][1] = acc[j][2] = acc[j][3] = 0.f; }
                gemm1r4<4, 144>(acc, fch, bb);
                const float* bo = out_b + l * 64;
                #pragma unroll
                for (int j = 0; j < 8; ++j) {
                    int c = 8 * j + 2 * qc;
                    float b0 = __ldg(bo + c), b1 = __ldg(bo + c + 1);
                    x_[0][j][0] += acc[j][0] + b0; x_[0][j][1] += acc[j][1] + b1;
                    x_[1][j][0] += acc[j][2] + b0; x_[1][j][1] += acc[j][3] + b1;
                }
                ln_reg(x_[0], ln1_g + l * 64, ln1_b + l * 64, qc);
                ln_reg(x_[1], ln1_g + l * 64, ln1_b + l * 64, qc);
                build_fr(x_, fxh);
            } else {
                // ======== ff pair ========
                int c4 = k - 2;
                float acc[8][4];
                #pragma unroll
                for (int j = 0; j < 8; ++j) { acc[j][0] = acc[j][1] = acc[j][2] = acc[j][3] = 0.f; }
                gemm1r4<4, 144>(acc, fxh, bb);
                const float* b1p = ff1_b + l * 256 + 64 * c4;
                #pragma unroll
                for (int j = 0; j < 8; ++j) {
                    int c = 8 * j + 2 * qc;
                    float b0 = __ldg(b1p + c), b1 = __ldg(b1p + c + 1);
                    float h00 = fmaxf(acc[j][0] + b0, 0.f), h01 = fmaxf(acc[j][1] + b1, 0.f);
                    float h10 = fmaxf(acc[j][2] + b0, 0.f), h11 = fmaxf(acc[j][3] + b1, 0.f);
                    int kc = j >> 1, jh = j & 1;
                    fch[kc][(jh << 1) | 0] = cvt_hi(h00, h01);
                    fch[kc][(jh << 1) | 1] = cvt_hi(h10, h11);
                }
                if (c4 == 0) {
                    #pragma unroll
                    for (int j = 0; j < 8; ++j) { accF[j][0] = accF[j][1] = accF[j][2] = accF[j][3] = 0.f; }
                }
                gemm1r4<4, 144>(accF, fch, bb + (uint32_t)CH_SZ);
                if (c4 == 3) {
                    const float* b2 = ff2_b + l * 64;
                    #pragma unroll
                    for (int j = 0; j < 8; ++j) {
                        int c = 8 * j + 2 * qc;
                        float b0 = __ldg(b2 + c), b1 = __ldg(b2 + c + 1);
                        x_[0][j][0] += accF[j][0] + b0; x_[0][j][1] += accF[j][1] + b1;
                        x_[1][j][0] += accF[j][2] + b0; x_[1][j][1] += accF[j][3] + b1;
                    }
                    ln_reg(x_[0], ln2_g + l * 64, ln2_b + l * 64, qc);
                    ln_reg(x_[1], ln2_g + l * 64, ln2_b + l * 64, qc);
                    if (l == 0) {
                        build_fr(x_, fxh);
                    } else {
                        // head A tile: row = sample; user cols 0:64, item cols 64:128
                        #pragma unroll
                        for (int j = 0; j < 8; ++j) {
                            int c = 8 * j + 2 * qc;
                            st_hi(sm, XT_OFF, 136, sl, c,      x_[0][j][0], x_[0][j][1]);
                            st_hi(sm, XT_OFF, 136, sl, 64 + c, x_[1][j][0], x_[1][j][1]);
                        }
                    }
                }
            }
        }
    }
}

// =====================================================================================
extern "C" void kernel_launch(void* const* d_in, const int* in_sizes, int n_in,
                              void* d_out, int out_size)
{
    const int*   user_idx      = (const int*)  d_in[0];
    const int*   item_idx      = (const int*)  d_in[1];
    const float* user_features = (const float*)d_in[2];
    const float* item_features = (const float*)d_in[3];
    const float* user_table    = (const float*)d_in[4];
    const float* item_table    = (const float*)d_in[5];
    const float* upw           = (const float*)d_in[6];
    const float* upb           = (const float*)d_in[7];
    const float* ipw           = (const float*)d_in[8];
    const float* ipb           = (const float*)d_in[9];
    const float* pe            = (const float*)d_in[10];
    const float* in_w          = (const float*)d_in[11];
    const float* in_b          = (const float*)d_in[12];
    const float* out_w         = (const float*)d_in[13];
    const float* out_b         = (const float*)d_in[14];
    const float* ln1_g         = (const float*)d_in[15];
    const float* ln1_b         = (const float*)d_in[16];
    const float* ff1_w         = (const float*)d_in[17];
    const float* ff1_b         = (const float*)d_in[18];
    const float* ff2_w         = (const float*)d_in[19];
    const float* ff2_b         = (const float*)d_in[20];
    const float* ln2_g         = (const float*)d_in[21];
    const float* ln2_b         = (const float*)d_in[22];
    const float* h1_w          = (const float*)d_in[23];
    const float* h1_b          = (const float*)d_in[24];
    const float* h2_w          = (const float*)d_in[25];
    const float* h2_b          = (const float*)d_in[26];
    float* out = (float*)d_out;

    const int B = in_sizes[0];

    static bool attr_set = false;
    if (!attr_set) {
        cudaFuncSetAttribute(main_kernel, cudaFuncAttributeMaxDynamicSharedMemorySize, MAIN_SMEM);
        attr_set = true;
    }

    conv_w_kernel<<<26, 256>>>(in_w, out_w, ff1_w, ff2_w, h1_w, upw, ipw);
    main_kernel<<<B / 32, MT, MAIN_SMEM>>>(user_idx, item_idx, user_features, item_features,
                                           user_table, item_table, upb, ipb, pe,
                                           in_b, out_b, ln1_g, ln1_b, ff1_b, ff2_b,
                                           ln2_g, ln2_b, h1_b, h2_w, h2_b, out);
}

// round 17
// speedup vs baseline: 2.2404x; 1.1643x over previous
#include <cuda_runtime.h>
#include <cuda_fp16.h>
#include <cstdint>

// ---------------- persistent device scratch (no runtime allocation) ----------------
// 24 x 9216 K-chunk hi-images | h1 image 17408 | embed B image [upw|ipw] 33792
#define CH_SZ    9216
#define WOFF_H1  (24 * CH_SZ)
#define WOFF_EMB (WOFF_H1 + 17408)
__device__ __align__(16) unsigned char  g_wbuf[WOFF_EMB + 33792];

// ---------------- common helpers ----------------
static __device__ __forceinline__ uint32_t smem_u32(const void* p) {
    uint32_t a;
    asm("{ .reg .u64 t; cvta.to.shared.u64 t, %1; cvt.u32.u64 %0, t; }" : "=r"(a) : "l"(p));
    return a;
}
static __device__ __forceinline__ void ldmA(uint32_t a[4], uint32_t addr) {
    asm volatile("ldmatrix.sync.aligned.m8n8.x4.shared.b16 {%0,%1,%2,%3}, [%4];"
                 : "=r"(a[0]), "=r"(a[1]), "=r"(a[2]), "=r"(a[3]) : "r"(addr));
}
static __device__ __forceinline__ void ldmB4(uint32_t b[4], uint32_t addr) {
    asm volatile("ldmatrix.sync.aligned.m8n8.x4.shared.b16 {%0,%1,%2,%3}, [%4];"
                 : "=r"(b[0]), "=r"(b[1]), "=r"(b[2]), "=r"(b[3]) : "r"(addr));
}
static __device__ __forceinline__ void mma16816(float d[4], const uint32_t a[4], const uint32_t b[2]) {
    asm volatile("mma.sync.aligned.m16n8k16.row.col.f32.f16.f16.f32 "
                 "{%0,%1,%2,%3}, {%4,%5,%6,%7}, {%8,%9}, {%0,%1,%2,%3};"
                 : "+f"(d[0]), "+f"(d[1]), "+f"(d[2]), "+f"(d[3])
                 : "r"(a[0]), "r"(a[1]), "r"(a[2]), "r"(a[3]), "r"(b[0]), "r"(b[1]));
}

// fp32 pair -> packed fp16
static __device__ __forceinline__ uint32_t cvt_hi(float v0, float v1) {
    __half2 hb = __floats2half2_rn(v0, v1);
    return *reinterpret_cast<uint32_t*>(&hb);
}

// 1-term fp16 gemm, register A (hi only), B hi tile [64 rows][BSTR bytes]
template<int NKC, int BSTR>
static __device__ __forceinline__ void gemm1r4(float (*acc)[4],
        const uint32_t (*fh)[4], uint32_t bBase) {
    const int lane = threadIdx.x & 31;
    uint32_t bAddr = bBase + (lane & 7) * BSTR + (((lane >> 3) & 1) << 4)
                   + ((lane >> 4) & 1) * 8 * BSTR;
    #pragma unroll
    for (int kc = 0; kc < NKC; ++kc) {
        uint32_t bh[4][4];
        #pragma unroll
        for (int jp = 0; jp < 4; ++jp)
            ldmB4(bh[jp], bAddr + jp * 16 * BSTR + kc * 32);
        #pragma unroll
        for (int jp = 0; jp < 4; ++jp) {
            mma16816(acc[2 * jp],     fh[kc], &bh[jp][0]);
            mma16816(acc[2 * jp + 1], fh[kc], &bh[jp][2]);
        }
    }
}

// 1-term gemm, tile A (hi only, [rows][ASTR bytes]) x B hi ([64][BSTR]) — head
template<int NKC, int ASTR, int BSTR>
static __device__ void gemm1t(float (*acc)[4], uint32_t aBase, uint32_t bBase) {
    const int lane = threadIdx.x & 31;
    uint32_t aAddr = aBase + (lane & 15) * ASTR + ((lane >> 4) << 4);
    uint32_t bAddr = bBase + (lane & 7) * BSTR + (((lane >> 3) & 1) << 4)
                   + ((lane >> 4) & 1) * 8 * BSTR;
    #pragma unroll
    for (int kc = 0; kc < NKC; ++kc) {
        uint32_t ah[4];
        ldmA(ah, aAddr + kc * 32);
        uint32_t bh[4][4];
        #pragma unroll
        for (int jp = 0; jp < 4; ++jp)
            ldmB4(bh[jp], bAddr + jp * 16 * BSTR + kc * 32);
        #pragma unroll
        for (int jp = 0; jp < 4; ++jp) {
            mma16816(acc[2 * jp],     ah, &bh[jp][0]);
            mma16816(acc[2 * jp + 1], ah, &bh[jp][2]);
        }
    }
}

// build m16n8k16 A fragments (hi only) from register values v[rowhalf][j][2]
static __device__ __forceinline__ void build_fr(const float v[2][8][2], uint32_t fh[4][4]) {
    #pragma unroll
    for (int kc = 0; kc < 4; ++kc)
        #pragma unroll
        for (int m = 0; m < 4; ++m) {
            int h = m & 1, j = 2 * kc + (m >> 1);
            fh[kc][m] = cvt_hi(v[h][j][0], v[h][j][1]);
        }
}

// fp16 pair store into tile [r][strideElems]
static __device__ __forceinline__ void st_hi(char* sm, uint32_t off, int strideElems,
                                             int r, int c, float f0, float f1) {
    __half* row = (__half*)(sm + off) + (size_t)r * strideElems;
    *reinterpret_cast<uint32_t*>(row + c) = cvt_hi(f0, f1);
}

// embed gemm: A rows 0-7 = user feats (K cols 0:128), rows 8-15 = item feats (128:256).
// B hi image [64][528B]. 1-term; fragments built on the fly.
static __device__ void gemm1_emb(float (*acc)[4], const float* __restrict__ fpU,
                                 const float* __restrict__ fpI, uint32_t bBase, int qc) {
    const int lane = threadIdx.x & 31;
    uint32_t bAddr = bBase + (lane & 7) * 528 + (((lane >> 3) & 1) << 4)
                   + ((lane >> 4) & 1) * 8 * 528;
    #pragma unroll
    for (int kc = 0; kc < 16; ++kc) {
        uint32_t ah[4] = {0u, 0u, 0u, 0u};
        if (kc < 8) {
            int col = 16 * kc + 2 * qc;
            float2 f0 = __ldg(reinterpret_cast<const float2*>(fpU + col));
            float2 f1 = __ldg(reinterpret_cast<const float2*>(fpU + col + 8));
            ah[0] = cvt_hi(f0.x, f0.y);
            ah[2] = cvt_hi(f1.x, f1.y);
        } else {
            int col = 16 * (kc - 8) + 2 * qc;
            float2 f0 = __ldg(reinterpret_cast<const float2*>(fpI + col));
            float2 f1 = __ldg(reinterpret_cast<const float2*>(fpI + col + 8));
            ah[1] = cvt_hi(f0.x, f0.y);
            ah[3] = cvt_hi(f1.x, f1.y);
        }
        uint32_t bh[4][4];
        #pragma unroll
        for (int jp = 0; jp < 4; ++jp)
            ldmB4(bh[jp], bAddr + jp * 16 * 528 + kc * 32);
        #pragma unroll
        for (int jp = 0; jp < 4; ++jp) {
            mma16816(acc[2 * jp],     ah, &bh[jp][0]);
            mma16816(acc[2 * jp + 1], ah, &bh[jp][2]);
        }
    }
}

// ---------------- cp.async ----------------
#define CP16(dst, src) asm volatile("cp.async.cg.shared.global [%0], [%1], 16;" \
                                    :: "r"(dst), "l"(src) : "memory")
#define CP_COMMIT() asm volatile("cp.async.commit_group;" ::: "memory")
#define CP_WAIT0()  asm volatile("cp.async.wait_group 0;" ::: "memory")

// =====================================================================================
// Kernel 1: convert all weights to fp16 HI-ONLY tile images (26 blocks)
// =====================================================================================
__global__ void conv_w_kernel(const float* __restrict__ in_w, const float* __restrict__ out_w,
                              const float* __restrict__ ff1_w, const float* __restrict__ ff2_w,
                              const float* __restrict__ h1_w, const float* __restrict__ upw,
                              const float* __restrict__ ipw)
{
    int b = blockIdx.x;
    if (b < 24) {
        int l = b / 12, c = b % 12;
        const float* src; int rs;
        if (c < 3)       { src = in_w  + ((size_t)l * 192 + 64 * c) * 64; rs = 64; }
        else if (c == 3) { src = out_w + (size_t)l * 4096;                rs = 64; }
        else {
            int cc = (c - 4) >> 1;
            if (((c - 4) & 1) == 0) { src = ff1_w + ((size_t)l * 256 + 64 * cc) * 64; rs = 64;  }
            else                    { src = ff2_w + (size_t)l * 16384 + 64 * cc;      rs = 256; }
        }
        unsigned char* dst = g_wbuf + (size_t)b * CH_SZ;
        for (int idx = threadIdx.x; idx < 64 * 32; idx += 256) {
            int n = idx >> 5, k2 = (idx & 31) << 1;
            float2 f = *reinterpret_cast<const float2*>(src + (size_t)n * rs + k2);
            *reinterpret_cast<uint32_t*>(dst + n * 144 + k2 * 2) = cvt_hi(f.x, f.y);
        }
    } else if (b == 24) {
        unsigned char* dst = g_wbuf + WOFF_H1;
        for (int idx = threadIdx.x; idx < 64 * 64; idx += 256) {
            int n = idx >> 6, k2 = (idx & 63) << 1;
            float2 f = *reinterpret_cast<const float2*>(h1_w + (size_t)n * 128 + k2);
            *reinterpret_cast<uint32_t*>(dst + n * 272 + k2 * 2) = cvt_hi(f.x, f.y);
        }
    } else {
        unsigned char* dst = g_wbuf + WOFF_EMB;
        for (int idx = threadIdx.x; idx < 64 * 128; idx += 256) {
            int n = idx >> 7, k2 = (idx & 127) << 1;
            float2 f = (k2 < 128)
                     ? *reinterpret_cast<const float2*>(upw + (size_t)n * 128 + k2)
                     : *reinterpret_cast<const float2*>(ipw + (size_t)n * 128 + (k2 - 128));
            *reinterpret_cast<uint32_t*>(dst + n * 528 + k2 * 2) = cvt_hi(f.x, f.y);
        }
    }
}

// =====================================================================================
// Kernel 2 (main): 128 threads / 32 samples / 4 warps; 3 CTAs per SM (12 warps/SM).
// warp w (0..3), thread qr owns SAMPLE sl=8w+qr; both tokens in-thread.
// smem: XT head tile [32][272B] @0 | WB ring 2x33792 @8704  total 76288 (x3 = 228.9KB)
// phases: p0 embed, p1..p12 transformer, p13 head. ff2 accumulates directly into x_.
// =====================================================================================
#define XT_OFF 0u
#define WB_OFF 8704u
#define SLOT_SZ 33792u
#define MAIN_SMEM (8704u + 2u * SLOT_SZ)
#define MT 128

static __device__ __forceinline__ void stage_cp(uint32_t dst, const unsigned char* src,
                                                int bytes, int tid) {
    for (int o = tid * 16; o < bytes; o += MT * 16)
        CP16(dst + o, src + o);
}

static __device__ __forceinline__ void phase_src(int p, int& off, int& bytes) {
    if (p == 0)  { off = WOFF_EMB; bytes = 33792; return; }
    if (p == 13) { off = WOFF_H1;  bytes = 17408; return; }
    int l = (p - 1) / 6, k = (p - 1) % 6;
    int ch = l * 12 + (k == 0 ? 0 : (k == 1 ? 3 : 4 + 2 * (k - 2)));
    off = ch * CH_SZ;
    bytes = (k == 0 ? 3 * CH_SZ : (k == 1 ? CH_SZ : 2 * CH_SZ));
}

// register-only LayerNorm over one 64-wide row spread across 4 qc lanes
static __device__ __forceinline__ void ln_reg(float v[8][2], const float* g, const float* b, int qc) {
    float s = 0.f;
    #pragma unroll
    for (int j = 0; j < 8; ++j) s += v[j][0] + v[j][1];
    s += __shfl_xor_sync(0xffffffffu, s, 1);
    s += __shfl_xor_sync(0xffffffffu, s, 2);
    float m = s * (1.f / 64.f);
    float var = 0.f;
    #pragma unroll
    for (int j = 0; j < 8; ++j) {
        float d0 = v[j][0] - m, d1 = v[j][1] - m;
        var += d0 * d0 + d1 * d1;
    }
    var += __shfl_xor_sync(0xffffffffu, var, 1);
    var += __shfl_xor_sync(0xffffffffu, var, 2);
    float inv = rsqrtf(var * (1.f / 64.f) + 1e-5f);
    #pragma unroll
    for (int j = 0; j < 8; ++j) {
        int cc = 8 * j + 2 * qc;
        v[j][0] = (v[j][0] - m) * inv * __ldg(g + cc)     + __ldg(b + cc);
        v[j][1] = (v[j][1] - m) * inv * __ldg(g + cc + 1) + __ldg(b + cc + 1);
    }
}

__global__ void __launch_bounds__(MT, 3)
main_kernel(const int* __restrict__ user_idx, const int* __restrict__ item_idx,
            const float* __restrict__ user_features, const float* __restrict__ item_features,
            const float* __restrict__ user_table, const float* __restrict__ item_table,
            const float* __restrict__ upb, const float* __restrict__ ipb,
            const float* __restrict__ pe,
            const float* __restrict__ in_b, const float* __restrict__ out_b,
            const float* __restrict__ ln1_g, const float* __restrict__ ln1_b,
            const float* __restrict__ ff1_b, const float* __restrict__ ff2_b,
            const float* __restrict__ ln2_g, const float* __restrict__ ln2_b,
            const float* __restrict__ h1_b, const float* __restrict__ h2_w,
            const float* __restrict__ h2_b, float* __restrict__ out)
{
    extern __shared__ char sm[];
    const int tid = threadIdx.x, lane = tid & 31, w = tid >> 5;   // w: 0..3
    const int qr = lane >> 2, qc = lane & 3;
    const int sl = 8 * w + qr;                 // sample owned by this thread (0..31)
    const int s0m = blockIdx.x << 5;           // 32 samples per block
    const uint32_t xt_u = smem_u32(sm + XT_OFF);
    const uint32_t wb_u = smem_u32(sm + WB_OFF);
    const uint32_t slot[2] = { wb_u, wb_u + SLOT_SZ };

    // prefetch phase 0 (embed B image)
    stage_cp(slot[0], g_wbuf + WOFF_EMB, 33792, tid);
    CP_COMMIT();

    float x_[2][8][2];                 // [0]=user token, [1]=item token
    uint32_t fxh[4][4];
    uint32_t fch[4][4];

    for (int p = 0; p <= 13; ++p) {
        CP_WAIT0();
        __syncthreads();
        if (p < 13) {
            int off, by; phase_src(p + 1, off, by);
            stage_cp(slot[(p + 1) & 1], g_wbuf + off, by, tid);
            CP_COMMIT();
        }
        const uint32_t bb = slot[p & 1];

        if (p == 0) {
            // ======== embed ========
            float acc[8][4];
            #pragma unroll
            for (int j = 0; j < 8; ++j) { acc[j][0] = acc[j][1] = acc[j][2] = acc[j][3] = 0.f; }
            gemm1_emb(acc, user_features + (size_t)(s0m + sl) * 128,
                           item_features + (size_t)(s0m + sl) * 128, bb, qc);
            int uidx = __ldg(user_idx + s0m + sl);
            int iidx = __ldg(item_idx + s0m + sl);
            const float* ut = user_table + (size_t)uidx * 64;
            const float* it = item_table + (size_t)iidx * 64;
            #pragma unroll
            for (int j = 0; j < 8; ++j) {
                int c = 8 * j + 2 * qc;
                x_[0][j][0] = acc[j][0] + __ldg(upb + c)     + __ldg(ut + c)     + __ldg(pe + c);
                x_[0][j][1] = acc[j][1] + __ldg(upb + c + 1) + __ldg(ut + c + 1) + __ldg(pe + c + 1);
                x_[1][j][0] = acc[j][2] + __ldg(ipb + c)     + __ldg(it + c)     + __ldg(pe + 64 + c);
                x_[1][j][1] = acc[j][3] + __ldg(ipb + c + 1) + __ldg(it + c + 1) + __ldg(pe + 64 + c + 1);
            }
            build_fr(x_, fxh);
        } else if (p == 13) {
            // ======== head: 32 samples -> warps 0,1 (16 rows each) ========
            if (w < 2) {
                float acc[8][4];
                #pragma unroll
                for (int j = 0; j < 8; ++j) { acc[j][0] = acc[j][1] = acc[j][2] = acc[j][3] = 0.f; }
                gemm1t<8, 272, 272>(acc, xt_u + (uint32_t)(16 * w) * 272u, bb);
                float pA = 0.f, pB = 0.f;
                #pragma unroll
                for (int j = 0; j < 8; ++j) {
                    int c = 8 * j + 2 * qc;
                    float b0 = __ldg(h1_b + c), b1 = __ldg(h1_b + c + 1);
                    float w0 = __ldg(h2_w + c), w1 = __ldg(h2_w + c + 1);
                    pA += fmaxf(acc[j][0] + b0, 0.f) * w0 + fmaxf(acc[j][1] + b1, 0.f) * w1;
                    pB += fmaxf(acc[j][2] + b0, 0.f) * w0 + fmaxf(acc[j][3] + b1, 0.f) * w1;
                }
                pA += __shfl_xor_sync(0xffffffffu, pA, 1);
                pA += __shfl_xor_sync(0xffffffffu, pA, 2);
                pB += __shfl_xor_sync(0xffffffffu, pB, 1);
                pB += __shfl_xor_sync(0xffffffffu, pB, 2);
                if (qc == 0) {
                    float hb = __ldg(h2_b);
                    out[s0m + 16 * w + qr]     = pA + hb;
                    out[s0m + 16 * w + qr + 8] = pB + hb;
                }
            }
        } else {
            const int l = (p - 1) / 6, k = (p - 1) % 6;
            if (k == 0) {
                // ======== qkv + attention (partner token in-thread) ========
                float q_[8][4];
                #pragma unroll
                for (int j = 0; j < 8; ++j) { q_[j][0] = q_[j][1] = q_[j][2] = q_[j][3] = 0.f; }
                gemm1r4<4, 144>(q_, fxh, bb);
                const float* bq = in_b + l * 192;
                #pragma unroll
                for (int j = 0; j < 8; ++j) {
                    int c = 8 * j + 2 * qc;
                    float b0 = __ldg(bq + c), b1 = __ldg(bq + c + 1);
                    q_[j][0] += b0; q_[j][1] += b1; q_[j][2] += b0; q_[j][3] += b1;
                }
                float t_[8][4];
                #pragma unroll
                for (int j = 0; j < 8; ++j) { t_[j][0] = t_[j][1] = t_[j][2] = t_[j][3] = 0.f; }
                gemm1r4<4, 144>(t_, fxh, bb + (uint32_t)CH_SZ);
                const float* bk = in_b + l * 192 + 64;
                #pragma unroll
                for (int j = 0; j < 8; ++j) {
                    int c = 8 * j + 2 * qc;
                    float b0 = __ldg(bk + c), b1 = __ldg(bk + c + 1);
                    t_[j][0] += b0; t_[j][1] += b1; t_[j][2] += b0; t_[j][3] += b1;
                }
                float wUU[4], wUI[4], wIU[4], wII[4];
                {
                    float sUU[4], sUI[4], sIU[4], sII[4];
                    #pragma unroll
                    for (int h = 0; h < 4; ++h) {
                        int j0 = 2 * h, j1 = 2 * h + 1;
                        sUU[h] = q_[j0][0] * t_[j0][0] + q_[j0][1] * t_[j0][1]
                               + q_[j1][0] * t_[j1][0] + q_[j1][1] * t_[j1][1];
                        sUI[h] = q_[j0][0] * t_[j0][2] + q_[j0][1] * t_[j0][3]
                               + q_[j1][0] * t_[j1][2] + q_[j1][1] * t_[j1][3];
                        sIU[h] = q_[j0][2] * t_[j0][0] + q_[j0][3] * t_[j0][1]
                               + q_[j1][2] * t_[j1][0] + q_[j1][3] * t_[j1][1];
                        sII[h] = q_[j0][2] * t_[j0][2] + q_[j0][3] * t_[j0][3]
                               + q_[j1][2] * t_[j1][2] + q_[j1][3] * t_[j1][3];
                    }
                    #pragma unroll
                    for (int h = 0; h < 4; ++h) {
                        sUU[h] += __shfl_xor_sync(0xffffffffu, sUU[h], 1);
                        sUU[h] += __shfl_xor_sync(0xffffffffu, sUU[h], 2);
                        sUI[h] += __shfl_xor_sync(0xffffffffu, sUI[h], 1);
                        sUI[h] += __shfl_xor_sync(0xffffffffu, sUI[h], 2);
                        sIU[h] += __shfl_xor_sync(0xffffffffu, sIU[h], 1);
                        sIU[h] += __shfl_xor_sync(0xffffffffu, sIU[h], 2);
                        sII[h] += __shfl_xor_sync(0xffffffffu, sII[h], 1);
                        sII[h] += __shfl_xor_sync(0xffffffffu, sII[h], 2);
                        float a = sUU[h] * 0.25f, o = sUI[h] * 0.25f;
                        float m = fmaxf(a, o);
                        float ea = __expf(a - m), eo = __expf(o - m);
                        float inv = __fdividef(1.f, ea + eo);
                        wUU[h] = ea * inv; wUI[h] = eo * inv;
                        a = sIU[h] * 0.25f; o = sII[h] * 0.25f;
                        m = fmaxf(a, o);
                        ea = __expf(a - m); eo = __expf(o - m);
                        inv = __fdividef(1.f, ea + eo);
                        wIU[h] = ea * inv; wII[h] = eo * inv;
                    }
                }
                // v (reuse t_)
                #pragma unroll
                for (int j = 0; j < 8; ++j) { t_[j][0] = t_[j][1] = t_[j][2] = t_[j][3] = 0.f; }
                gemm1r4<4, 144>(t_, fxh, bb + 2u * CH_SZ);
                const float* bv = in_b + l * 192 + 128;
                #pragma unroll
                for (int j = 0; j < 8; ++j) {
                    int c = 8 * j + 2 * qc;
                    float b0 = __ldg(bv + c), b1 = __ldg(bv + c + 1);
                    t_[j][0] += b0; t_[j][1] += b1; t_[j][2] += b0; t_[j][3] += b1;
                }
                #pragma unroll
                for (int j = 0; j < 8; ++j) {
                    int h = j >> 1;
                    float c00 = wUU[h] * t_[j][0] + wUI[h] * t_[j][2];
                    float c01 = wUU[h] * t_[j][1] + wUI[h] * t_[j][3];
                    float c10 = wIU[h] * t_[j][0] + wII[h] * t_[j][2];
                    float c11 = wIU[h] * t_[j][1] + wII[h] * t_[j][3];
                    int kc = j >> 1, jh = j & 1;
                    fch[kc][(jh << 1) | 0] = cvt_hi(c00, c01);
                    fch[kc][(jh << 1) | 1] = cvt_hi(c10, c11);
                }
            } else if (k == 1) {
                // ======== out-proj + residual + LN1 ========
                float acc[8][4];
                #pragma unroll
                for (int j = 0; j < 8; ++j) { acc[j][0] = acc[j][1] = acc[j][2] = acc[j][3] = 0.f; }
                gemm1r4<4, 144>(acc, fch, bb);
                const float* bo = out_b + l * 64;
                #pragma unroll
                for (int j = 0; j < 8; ++j) {
                    int c = 8 * j + 2 * qc;
                    float b0 = __ldg(bo + c), b1 = __ldg(bo + c + 1);
                    x_[0][j][0] += acc[j][0] + b0; x_[0][j][1] += acc[j][1] + b1;
                    x_[1][j][0] += acc[j][2] + b0; x_[1][j][1] += acc[j][3] + b1;
                }
                ln_reg(x_[0], ln1_g + l * 64, ln1_b + l * 64, qc);
                ln_reg(x_[1], ln1_g + l * 64, ln1_b + l * 64, qc);
                build_fr(x_, fxh);
            } else {
                // ======== ff pair: ff1 -> relu -> fch; ff2 accumulates into x_ ========
                int c4 = k - 2;
                float acc[8][4];
                #pragma unroll
                for (int j = 0; j < 8; ++j) { acc[j][0] = acc[j][1] = acc[j][2] = acc[j][3] = 0.f; }
                gemm1r4<4, 144>(acc, fxh, bb);
                const float* b1p = ff1_b + l * 256 + 64 * c4;
                #pragma unroll
                for (int j = 0; j < 8; ++j) {
                    int c = 8 * j + 2 * qc;
                    float b0 = __ldg(b1p + c), b1 = __ldg(b1p + c + 1);
                    float h00 = fmaxf(acc[j][0] + b0, 0.f), h01 = fmaxf(acc[j][1] + b1, 0.f);
                    float h10 = fmaxf(acc[j][2] + b0, 0.f), h11 = fmaxf(acc[j][3] + b1, 0.f);
                    int kc = j >> 1, jh = j & 1;
                    fch[kc][(jh << 1) | 0] = cvt_hi(h00, h01);
                    fch[kc][(jh << 1) | 1] = cvt_hi(h10, h11);
                }
                // ff2 chunk: reuse acc, accumulate straight into x_
                #pragma unroll
                for (int j = 0; j < 8; ++j) { acc[j][0] = acc[j][1] = acc[j][2] = acc[j][3] = 0.f; }
                gemm1r4<4, 144>(acc, fch, bb + (uint32_t)CH_SZ);
                #pragma unroll
                for (int j = 0; j < 8; ++j) {
                    x_[0][j][0] += acc[j][0]; x_[0][j][1] += acc[j][1];
                    x_[1][j][0] += acc[j][2]; x_[1][j][1] += acc[j][3];
                }
                if (c4 == 3) {
                    const float* b2 = ff2_b + l * 64;
                    #pragma unroll
                    for (int j = 0; j < 8; ++j) {
                        int c = 8 * j + 2 * qc;
                        float b0 = __ldg(b2 + c), b1 = __ldg(b2 + c + 1);
                        x_[0][j][0] += b0; x_[0][j][1] += b1;
                        x_[1][j][0] += b0; x_[1][j][1] += b1;
                    }
                    ln_reg(x_[0], ln2_g + l * 64, ln2_b + l * 64, qc);
                    ln_reg(x_[1], ln2_g + l * 64, ln2_b + l * 64, qc);
                    if (l == 0) {
                        build_fr(x_, fxh);
                    } else {
                        // head A tile: row = sample; user cols 0:64, item cols 64:128
                        #pragma unroll
                        for (int j = 0; j < 8; ++j) {
                            int c = 8 * j + 2 * qc;
                            st_hi(sm, XT_OFF, 136, sl, c,      x_[0][j][0], x_[0][j][1]);
                            st_hi(sm, XT_OFF, 136, sl, 64 + c, x_[1][j][0], x_[1][j][1]);
                        }
                    }
                }
            }
        }
    }
}

// =====================================================================================
extern "C" void kernel_launch(void* const* d_in, const int* in_sizes, int n_in,
                              void* d_out, int out_size)
{
    const int*   user_idx      = (const int*)  d_in[0];
    const int*   item_idx      = (const int*)  d_in[1];
    const float* user_features = (const float*)d_in[2];
    const float* item_features = (const float*)d_in[3];
    const float* user_table    = (const float*)d_in[4];
    const float* item_table    = (const float*)d_in[5];
    const float* upw           = (const float*)d_in[6];
    const float* upb           = (const float*)d_in[7];
    const float* ipw           = (const float*)d_in[8];
    const float* ipb           = (const float*)d_in[9];
    const float* pe            = (const float*)d_in[10];
    const float* in_w          = (const float*)d_in[11];
    const float* in_b          = (const float*)d_in[12];
    const float* out_w         = (const float*)d_in[13];
    const float* out_b         = (const float*)d_in[14];
    const float* ln1_g         = (const float*)d_in[15];
    const float* ln1_b         = (const float*)d_in[16];
    const float* ff1_w         = (const float*)d_in[17];
    const float* ff1_b         = (const float*)d_in[18];
    const float* ff2_w         = (const float*)d_in[19];
    const float* ff2_b         = (const float*)d_in[20];
    const float* ln2_g         = (const float*)d_in[21];
    const float* ln2_b         = (const float*)d_in[22];
    const float* h1_w          = (const float*)d_in[23];
    const float* h1_b          = (const float*)d_in[24];
    const float* h2_w          = (const float*)d_in[25];
    const float* h2_b          = (const float*)d_in[26];
    float* out = (float*)d_out;

    const int B = in_sizes[0];

    static bool attr_set = false;
    if (!attr_set) {
        cudaFuncSetAttribute(main_kernel, cudaFuncAttributeMaxDynamicSharedMemorySize, MAIN_SMEM);
        attr_set = true;
    }

    conv_w_kernel<<<26, 256>>>(in_w, out_w, ff1_w, ff2_w, h1_w, upw, ipw);
    main_kernel<<<B / 32, MT, MAIN_SMEM>>>(user_idx, item_idx, user_features, item_features,
                                           user_table, item_table, upb, ipb, pe,
                                           in_b, out_b, ln1_g, ln1_b, ff1_b, ff2_b,
                                           ln2_g, ln2_b, h1_b, h2_w, h2_b, out);
}